// round 1
// baseline (speedup 1.0000x reference)
#include <cuda_runtime.h>
#include <cuda_bf16.h>
#include <cstdint>

// ---------------- problem constants ----------------
#define B_SZ   2
#define L_SZ   2048
#define DM     1024      // d_model
#define DI     2048      // d_inner
#define DS     128       // d_state
#define DCONV  4
#define NH     32        // nheads
#define HD     64        // headdim
#define DTIME  64
#define CD     (DI + 2*DS)            // 2304 conv dim
#define DIP    (2*DI + 2*DS + NH)     // 4384 in-proj dim
#define ROWS   (B_SZ*L_SZ)            // 4096
#define NC     16                     // scan chunks
#define CL     (L_SZ/NC)              // 128 chunk len
#define EPSV   1e-5f

// ---------------- scratch (device globals; no allocs allowed) ----------------
__device__ float g_u[ROWS*DM];
__device__ float g_zx[ROWS*DIP];
__device__ float g_xBCa[ROWS*CD];
__device__ float g_dt[ROWS*NH];
__device__ float g_dA[ROWS*NH];
__device__ float g_cumdec[B_SZ*NH*L_SZ];
__device__ float g_Sfinal[B_SZ*NH*NC*HD*DS];
__device__ float g_Hinit [B_SZ*NH*NC*HD*DS];
__device__ float g_y[ROWS*DI];

// ---------------- fp32 SGEMM: C[M,N] = A[M,K] @ B[K,N] (+bias) ----------------
// BM=BN=128, BK=8, 256 threads, 8x8 micro-tile. M%128==0, K%8==0, N%4==0 assumed.
template<bool HAS_BIAS>
__global__ void __launch_bounds__(256) sgemm128(
    const float* __restrict__ A, const float* __restrict__ Bm,
    const float* __restrict__ bias, float* __restrict__ C,
    int M, int N, int K)
{
    __shared__ float As[8][132];
    __shared__ float Bs[8][128];

    const int tid  = threadIdx.x;
    const int row0 = blockIdx.y * 128;
    const int col0 = blockIdx.x * 128;

    const int arow = tid >> 1;            // 0..127
    const int ak   = (tid & 1) * 4;       // 0 or 4
    const int bk   = tid >> 5;            // 0..7
    const int bn   = (tid & 31) * 4;      // 0..124

    const int tr = tid >> 4;              // 0..15
    const int tc = tid & 15;              // 0..15

    float acc[8][8];
    #pragma unroll
    for (int i = 0; i < 8; i++)
        #pragma unroll
        for (int j = 0; j < 8; j++) acc[i][j] = 0.f;

    for (int k0 = 0; k0 < K; k0 += 8) {
        // A tile load (always in-bounds: M%128==0, K%8==0)
        float4 a4 = *(const float4*)&A[(size_t)(row0 + arow) * K + k0 + ak];
        As[ak+0][arow] = a4.x; As[ak+1][arow] = a4.y;
        As[ak+2][arow] = a4.z; As[ak+3][arow] = a4.w;

        // B tile load (guard N; N%4==0 so float4 either fully in or out)
        int gcol = col0 + bn;
        float4 b4 = make_float4(0.f, 0.f, 0.f, 0.f);
        if (gcol < N) b4 = *(const float4*)&Bm[(size_t)(k0 + bk) * N + gcol];
        *(float4*)&Bs[bk][bn] = b4;

        __syncthreads();

        #pragma unroll
        for (int kk = 0; kk < 8; kk++) {
            float a[8], b[8];
            #pragma unroll
            for (int i = 0; i < 8; i++) a[i] = As[kk][tr*8 + i];
            float4 b0 = *(float4*)&Bs[kk][tc*8];
            float4 b1 = *(float4*)&Bs[kk][tc*8 + 4];
            b[0]=b0.x; b[1]=b0.y; b[2]=b0.z; b[3]=b0.w;
            b[4]=b1.x; b[5]=b1.y; b[6]=b1.z; b[7]=b1.w;
            #pragma unroll
            for (int i = 0; i < 8; i++)
                #pragma unroll
                for (int j = 0; j < 8; j++)
                    acc[i][j] = fmaf(a[i], b[j], acc[i][j]);
        }
        __syncthreads();
    }

    // store (float4; col%4==0 and N%4==0 -> guard on col<N only)
    #pragma unroll
    for (int i = 0; i < 8; i++) {
        int r = row0 + tr*8 + i;
        #pragma unroll
        for (int jj = 0; jj < 8; jj += 4) {
            int col = col0 + tc*8 + jj;
            if (col < N) {
                float4 v;
                v.x = acc[i][jj+0]; v.y = acc[i][jj+1];
                v.z = acc[i][jj+2]; v.w = acc[i][jj+3];
                if (HAS_BIAS) {
                    v.x += bias[col+0]; v.y += bias[col+1];
                    v.z += bias[col+2]; v.w += bias[col+3];
                }
                *(float4*)&C[(size_t)r * N + col] = v;
            }
        }
    }
}

// ---------------- dtmod + dt/softplus + dA ----------------
__global__ void dt_kernel(const float* __restrict__ dte,
                          const float* __restrict__ Wd,
                          const float* __restrict__ bd,
                          const float* __restrict__ zx,
                          const float* __restrict__ dt_bias,
                          const float* __restrict__ A_log)
{
    int idx = blockIdx.x * blockDim.x + threadIdx.x;   // ROWS*NH
    if (idx >= ROWS * NH) return;
    int h   = idx & (NH - 1);
    int row = idx >> 5;
    const float* d = dte + (size_t)row * DTIME;
    float s = bd[h];
    #pragma unroll 8
    for (int j = 0; j < DTIME; j++) s = fmaf(d[j], Wd[j*NH + h], s);
    float x  = zx[(size_t)row * DIP + (DI + CD) + h] + dt_bias[h] + s;
    float dt = (x > 20.f) ? x : log1pf(expf(x));
    float A  = -expf(A_log[h]);
    g_dt[idx] = dt;
    g_dA[idx] = expf(dt * A);
}

// ---------------- causal conv (taps=4) + bias + silu ----------------
__global__ void conv_kernel(const float* __restrict__ zx,
                            const float* __restrict__ conv_w,
                            const float* __restrict__ conv_b)
{
    int idx = blockIdx.x * blockDim.x + threadIdx.x;   // ROWS*CD
    if (idx >= ROWS * CD) return;
    int c   = idx % CD;
    int row = idx / CD;
    int l   = row & (L_SZ - 1);
    int b   = row / L_SZ;
    float acc = conv_b[c];
    #pragma unroll
    for (int k = 0; k < DCONV; k++) {
        int ll = l - (DCONV - 1) + k;
        if (ll >= 0)
            acc = fmaf(zx[(size_t)(b*L_SZ + ll) * DIP + DI + c], conv_w[k*CD + c], acc);
    }
    g_xBCa[idx] = acc / (1.f + expf(-acc));   // silu
}

// ---------------- scan phase A: per-chunk local scan from zero state ----------------
__global__ void __launch_bounds__(256) scanA_kernel(const float* __restrict__ Dvec)
{
    const int c = blockIdx.x, h = blockIdx.y, b = blockIdx.z;
    const int t = threadIdx.x;
    __shared__ float xs[2][64], Bs[2][128], Cs[2][128], red[2][256];

    const int p = t & 63, g = t >> 6, n0 = g * 32;
    float s[32];
    #pragma unroll
    for (int j = 0; j < 32; j++) s[j] = 0.f;
    float cum = 1.f;
    const float Dh = Dvec[h];
    const int l0 = c * CL;
    const int bh = b * NH + h;

    for (int li = 0; li < CL; li++) {
        const int l = l0 + li, par = li & 1;
        const float* base = g_xBCa + (size_t)(b*L_SZ + l) * CD;
        for (int i = t; i < 320; i += 256) {
            if (i < 64)        xs[par][i]       = base[h*HD + i];
            else if (i < 192)  Bs[par][i - 64]  = base[DI + (i - 64)];
            else               Cs[par][i - 192] = base[DI + DS + (i - 192)];
        }
        float dtv = g_dt[(b*L_SZ + l)*NH + h];
        float dAv = g_dA[(b*L_SZ + l)*NH + h];
        __syncthreads();

        float coef = dtv * xs[par][p];
        float acc = 0.f;
        #pragma unroll
        for (int j = 0; j < 32; j++) {
            s[j] = fmaf(dAv, s[j], coef * Bs[par][n0 + j]);
            acc  = fmaf(s[j], Cs[par][n0 + j], acc);
        }
        red[par][t] = acc;
        cum *= dAv;
        __syncthreads();

        if (t < 64) {
            float y = red[par][t] + red[par][t+64] + red[par][t+128] + red[par][t+192]
                    + Dh * xs[par][t];
            g_y[(size_t)(b*L_SZ + l)*DI + h*HD + t] = y;
        }
        if (t == 0) g_cumdec[bh*L_SZ + l] = cum;
        // double buffering makes an end-of-loop barrier unnecessary
    }

    const size_t sbase = ((size_t)bh * NC + c) * (HD * DS);
    #pragma unroll
    for (int j = 0; j < 32; j++) g_Sfinal[sbase + p*DS + n0 + j] = s[j];
}

// ---------------- scan phase B: sequential chunk-state combine (tiny) ----------------
__global__ void phaseB_kernel()
{
    const int bh = blockIdx.x;
    const int t  = threadIdx.x;
    for (int e = t; e < HD * DS; e += 256) {
        float hv = 0.f;
        for (int c = 0; c < NC; c++) {
            const size_t o = ((size_t)bh * NC + c) * (HD * DS) + e;
            g_Hinit[o] = hv;
            float P = g_cumdec[bh*L_SZ + c*CL + CL - 1];
            hv = fmaf(P, hv, g_Sfinal[o]);
        }
    }
}

// ---------------- scan phase C: rank-correction y += cumdec * C^T h_init ----------------
__global__ void __launch_bounds__(256) phaseC_kernel()
{
    const int c = blockIdx.x;
    if (c == 0) return;               // zero initial state
    const int h = blockIdx.y, b = blockIdx.z;
    const int t = threadIdx.x;
    __shared__ float Hs[64 * 129];
    __shared__ float Cs[2][128], red[2][256];

    const int bh = b * NH + h;
    const size_t hbase = ((size_t)bh * NC + c) * (HD * DS);
    for (int i = t; i < HD * DS; i += 256)
        Hs[(i >> 7) * 129 + (i & 127)] = g_Hinit[hbase + i];

    const int p = t & 63, g = t >> 6, n0 = g * 32;
    const int l0 = c * CL;
    __syncthreads();

    for (int li = 0; li < CL; li++) {
        const int l = l0 + li, par = li & 1;
        const float* base = g_xBCa + (size_t)(b*L_SZ + l) * CD + DI + DS;
        if (t < 128) Cs[par][t] = base[t];
        float cd = g_cumdec[bh*L_SZ + l];
        __syncthreads();

        float acc = 0.f;
        #pragma unroll
        for (int j = 0; j < 32; j++)
            acc = fmaf(Hs[p*129 + n0 + j], Cs[par][n0 + j], acc);
        red[par][t] = acc;
        __syncthreads();

        if (t < 64)
            g_y[(size_t)(b*L_SZ + l)*DI + h*HD + t] +=
                cd * (red[par][t] + red[par][t+64] + red[par][t+128] + red[par][t+192]);
    }
}

// ---------------- gating (silu(z)) + RMS norm ----------------
__global__ void __launch_bounds__(256) epilogue_kernel(const float* __restrict__ norm_w)
{
    const int row = blockIdx.x;       // b*L + l
    const int t   = threadIdx.x;
    float gv[8];
    float ss = 0.f;
    #pragma unroll
    for (int i = 0; i < 8; i++) {
        int cidx = t + i * 256;
        float yv = g_y[(size_t)row * DI + cidx];
        float zv = g_zx[(size_t)row * DIP + cidx];
        float sil = zv / (1.f + expf(-zv));
        float v = yv * sil;
        gv[i] = v;
        ss += v * v;
    }
    __shared__ float rs[32];
    #pragma unroll
    for (int o = 16; o; o >>= 1) ss += __shfl_xor_sync(~0u, ss, o);
    if ((t & 31) == 0) rs[t >> 5] = ss;
    __syncthreads();
    if (t < 32) {
        float v = (t < 8) ? rs[t] : 0.f;
        #pragma unroll
        for (int o = 4; o; o >>= 1) v += __shfl_xor_sync(~0u, v, o);
        if (t == 0) rs[0] = v;
    }
    __syncthreads();
    float scale = rsqrtf(rs[0] / (float)DI + EPSV);
    #pragma unroll
    for (int i = 0; i < 8; i++) {
        int cidx = t + i * 256;
        g_y[(size_t)row * DI + cidx] = gv[i] * scale * norm_w[cidx];
    }
}

// ---------------- launch ----------------
extern "C" void kernel_launch(void* const* d_in, const int* in_sizes, int n_in,
                              void* d_out, int out_size)
{
    const float* hidden  = (const float*)d_in[0];
    const float* dte     = (const float*)d_in[1];
    const float* W_proj  = (const float*)d_in[2];
    const float* b_proj  = (const float*)d_in[3];
    const float* W_dtmod = (const float*)d_in[4];
    const float* b_dtmod = (const float*)d_in[5];
    const float* W_in    = (const float*)d_in[6];
    const float* conv_w  = (const float*)d_in[7];
    const float* conv_b  = (const float*)d_in[8];
    const float* dt_bias = (const float*)d_in[9];
    const float* A_log   = (const float*)d_in[10];
    const float* Dvec    = (const float*)d_in[11];
    const float* norm_w  = (const float*)d_in[12];
    const float* W_out   = (const float*)d_in[13];
    float* out = (float*)d_out;

    float *p_u, *p_zx, *p_y;
    cudaGetSymbolAddress((void**)&p_u,  g_u);
    cudaGetSymbolAddress((void**)&p_zx, g_zx);
    cudaGetSymbolAddress((void**)&p_y,  g_y);

    // 1) u = hidden @ W_proj + b_proj        [4096,1024] x [1024,1024]
    sgemm128<true><<<dim3(DM/128, ROWS/128), 256>>>(hidden, W_proj, b_proj, p_u, ROWS, DM, DM);

    // 2) zxbcdt = u @ W_in                   [4096,4384] x K=1024
    sgemm128<false><<<dim3((DIP + 127)/128, ROWS/128), 256>>>(p_u, W_in, nullptr, p_zx, ROWS, DIP, DM);

    // 3) dt = softplus(dt_raw + dt_bias + dte@W_dtmod + b_dtmod); dA = exp(dt*A)
    dt_kernel<<<(ROWS*NH + 255)/256, 256>>>(dte, W_dtmod, b_dtmod, p_zx, dt_bias, A_log);

    // 4) xBC = silu(causal_conv(xBC) + conv_b)
    conv_kernel<<<(ROWS*CD + 255)/256, 256>>>(p_zx, conv_w, conv_b);

    // 5) chunked selective scan
    scanA_kernel<<<dim3(NC, NH, B_SZ), 256>>>(Dvec);
    phaseB_kernel<<<B_SZ*NH, 256>>>();
    phaseC_kernel<<<dim3(NC, NH, B_SZ), 256>>>();

    // 6) gating + RMS norm (in place on g_y)
    epilogue_kernel<<<ROWS, 256>>>(norm_w);

    // 7) out = yn @ W_out                    [4096,1024] x K=2048
    sgemm128<false><<<dim3(DM/128, ROWS/128), 256>>>(p_y, W_out, nullptr, out, ROWS, DM, DI);
}

// round 3
// speedup vs baseline: 1.2225x; 1.2225x over previous
#include <cuda_runtime.h>
#include <cuda_bf16.h>
#include <cstdint>

// ---------------- problem constants ----------------
#define B_SZ   2
#define L_SZ   2048
#define DM     1024      // d_model
#define DI     2048      // d_inner
#define DS     128       // d_state
#define DCONV  4
#define NH     32        // nheads
#define HD     64        // headdim
#define DTIME  64
#define CD     (DI + 2*DS)            // 2304 conv dim
#define DIP    (2*DI + 2*DS + NH)     // 4384 in-proj dim
#define DIPPAD 4480                   // 35*128
#define ROWS   (B_SZ*L_SZ)            // 4096
#define NC     16                     // scan chunks
#define CL     (L_SZ/NC)              // 128 chunk len
#define EPSV   1e-5f

// ---------------- scratch (device globals; no allocs allowed) ----------------
__device__ float g_uhi[ROWS*DM], g_ulo[ROWS*DM];
__device__ float g_zx[ROWS*DIP];
__device__ float g_xBCa[ROWS*CD];
__device__ float g_dt[ROWS*NH];
__device__ float g_dA[ROWS*NH];
__device__ float g_cumdec[B_SZ*NH*L_SZ];
__device__ float g_Sfinal[B_SZ*NH*NC*HD*DS];
__device__ float g_Hinit [B_SZ*NH*NC*HD*DS];
__device__ float g_y[ROWS*DI];
__device__ float g_yhi[ROWS*DI], g_ylo[ROWS*DI];
__device__ float g_hhi[ROWS*DM], g_hlo[ROWS*DM];
__device__ float g_wpt_hi[DM*DM],     g_wpt_lo[DM*DM];      // W_proj^T  [1024][1024]
__device__ float g_wit_hi[DIPPAD*DM], g_wit_lo[DIPPAD*DM];  // W_in^T    [4480][1024]
__device__ float g_wot_hi[DM*DI],     g_wot_lo[DM*DI];      // W_out^T   [1024][2048]

// ---------------- helpers ----------------
__device__ __forceinline__ float tf32_hi(float x) {
    uint32_t u;
    asm("cvt.rna.tf32.f32 %0, %1;" : "=r"(u) : "f"(x));
    return __uint_as_float(u);
}

__device__ __forceinline__ void mma8(float& d0, float& d1, float& d2, float& d3,
                                     uint32_t a0, uint32_t a1, uint32_t a2, uint32_t a3,
                                     uint32_t b0, uint32_t b1)
{
    asm volatile("mma.sync.aligned.m16n8k8.row.col.f32.tf32.tf32.f32 "
        "{%0,%1,%2,%3},{%4,%5,%6,%7},{%8,%9},{%0,%1,%2,%3};"
        : "+f"(d0), "+f"(d1), "+f"(d2), "+f"(d3)
        : "r"(a0), "r"(a1), "r"(a2), "r"(a3), "r"(b0), "r"(b1));
}

// smem geometry: rows of 32 floats padded to 36 (conflict-free frag loads)
#define ROWF   36
#define TBYTES (128 * ROWF * 4)           // 18432 bytes per tensor per stage
#define STAGEB (4 * TBYTES)               // Ahi,Alo,Bhi,Blo
#define GEMM_SMEM_BYTES (2 * STAGEB)      // 147456

// ---------------- split-TF32 GEMM via mma.sync (fallback HMMA tensor path) ----
// C[M,Nreal] = (Ahi+Alo)[M,K] @ (Bhi+Blo)^T, Bt stored [Npad,K] K-major.
// grid = (Npad/128, M/128), 256 threads = 8 warps (2 x 4), warp tile 64x32.
template<bool HAS_BIAS, bool SPLIT_OUT>
__global__ void __launch_bounds__(256, 1) gemm_mma(
    const float* __restrict__ Ahi, const float* __restrict__ Alo,
    const float* __restrict__ Bhi, const float* __restrict__ Blo,
    const float* __restrict__ bias,
    float* __restrict__ Cout, float* __restrict__ Cout2,
    int M, int Nreal, int K)
{
    extern __shared__ __align__(16) char smem[];
    const int tid = threadIdx.x;
    const int wid = tid >> 5;
    const int lane = tid & 31;
    const int wm = wid & 1;           // warp row (2)
    const int wn = wid >> 1;          // warp col (4)
    const int r = lane >> 2;          // 0..7
    const int c = lane & 3;           // 0..3
    const int m0 = blockIdx.y << 7;
    const int n0 = blockIdx.x << 7;
    const int nsteps = K >> 5;

    // loader role: 64 threads per tensor {Ahi,Alo,Bhi,Blo}
    const int t4  = tid >> 6;
    const int l64 = tid & 63;
    const float* gsel = (t4 == 0) ? Ahi : (t4 == 1) ? Alo : (t4 == 2) ? Bhi : Blo;
    const int rb = (t4 < 2) ? m0 : n0;

    auto load_stage = [&](int kstep, int s) {
        const int k0 = kstep << 5;
        const float* gb = gsel + (size_t)rb * K + k0;
        char* tb = smem + s * STAGEB + t4 * TBYTES;
        #pragma unroll
        for (int j = 0; j < 16; j++) {
            int q = j * 64 + l64;
            int row = q >> 3, col = q & 7;
            const float* gp = gb + (size_t)row * K + (col << 2);
            char* sp = tb + row * (ROWF * 4) + (col << 4);
            uint32_t sa = (uint32_t)__cvta_generic_to_shared(sp);
            asm volatile("cp.async.cg.shared.global [%0], [%1], 16;" :: "r"(sa), "l"(gp) : "memory");
        }
        asm volatile("cp.async.commit_group;" ::: "memory");
    };

    float acc[4][4][4];
    #pragma unroll
    for (int i = 0; i < 4; i++)
        #pragma unroll
        for (int j = 0; j < 4; j++)
            #pragma unroll
            for (int q = 0; q < 4; q++) acc[i][j][q] = 0.f;

    load_stage(0, 0);

    for (int i = 0; i < nsteps; i++) {
        if (i + 1 < nsteps) {
            load_stage(i + 1, (i + 1) & 1);
            asm volatile("cp.async.wait_group 1;" ::: "memory");
        } else {
            asm volatile("cp.async.wait_group 0;" ::: "memory");
        }
        __syncthreads();

        const int s = i & 1;
        const float* sAhi = (const float*)(smem + s * STAGEB);
        const float* sAlo = (const float*)(smem + s * STAGEB + TBYTES);
        const float* sBhi = (const float*)(smem + s * STAGEB + 2 * TBYTES);
        const float* sBlo = (const float*)(smem + s * STAGEB + 3 * TBYTES);

        #pragma unroll
        for (int kb = 0; kb < 4; kb++) {
            const int kc = kb * 8 + c;
            uint32_t ah[4][4], al[4][4], bh[4][2], bl[4][2];
            #pragma unroll
            for (int mt = 0; mt < 4; mt++) {
                const int row = wm * 64 + mt * 16 + r;
                ah[mt][0] = __float_as_uint(sAhi[row * ROWF + kc]);
                ah[mt][1] = __float_as_uint(sAhi[(row + 8) * ROWF + kc]);
                ah[mt][2] = __float_as_uint(sAhi[row * ROWF + kc + 4]);
                ah[mt][3] = __float_as_uint(sAhi[(row + 8) * ROWF + kc + 4]);
                al[mt][0] = __float_as_uint(sAlo[row * ROWF + kc]);
                al[mt][1] = __float_as_uint(sAlo[(row + 8) * ROWF + kc]);
                al[mt][2] = __float_as_uint(sAlo[row * ROWF + kc + 4]);
                al[mt][3] = __float_as_uint(sAlo[(row + 8) * ROWF + kc + 4]);
            }
            #pragma unroll
            for (int nt = 0; nt < 4; nt++) {
                const int n = wn * 32 + nt * 8 + r;
                bh[nt][0] = __float_as_uint(sBhi[n * ROWF + kc]);
                bh[nt][1] = __float_as_uint(sBhi[n * ROWF + kc + 4]);
                bl[nt][0] = __float_as_uint(sBlo[n * ROWF + kc]);
                bl[nt][1] = __float_as_uint(sBlo[n * ROWF + kc + 4]);
            }
            #pragma unroll
            for (int mt = 0; mt < 4; mt++)
                #pragma unroll
                for (int nt = 0; nt < 4; nt++) {
                    float* d = acc[mt][nt];
                    mma8(d[0], d[1], d[2], d[3],
                         ah[mt][0], ah[mt][1], ah[mt][2], ah[mt][3], bh[nt][0], bh[nt][1]);
                    mma8(d[0], d[1], d[2], d[3],
                         ah[mt][0], ah[mt][1], ah[mt][2], ah[mt][3], bl[nt][0], bl[nt][1]);
                    mma8(d[0], d[1], d[2], d[3],
                         al[mt][0], al[mt][1], al[mt][2], al[mt][3], bh[nt][0], bh[nt][1]);
                }
        }
        __syncthreads();
    }

    // epilogue
    #pragma unroll
    for (int mt = 0; mt < 4; mt++) {
        const int row = m0 + wm * 64 + mt * 16 + r;
        #pragma unroll
        for (int nt = 0; nt < 4; nt++) {
            const int col = n0 + wn * 32 + nt * 8 + 2 * c;
            if (col < Nreal) {
                float v0 = acc[mt][nt][0], v1 = acc[mt][nt][1];
                float v2 = acc[mt][nt][2], v3 = acc[mt][nt][3];
                if (HAS_BIAS) {
                    float b0 = bias[col], b1 = bias[col + 1];
                    v0 += b0; v1 += b1; v2 += b0; v3 += b1;
                }
                if (SPLIT_OUT) {
                    float h0 = tf32_hi(v0), h1 = tf32_hi(v1), h2 = tf32_hi(v2), h3 = tf32_hi(v3);
                    *(float2*)&Cout [(size_t)row * Nreal + col]       = make_float2(h0, h1);
                    *(float2*)&Cout [(size_t)(row + 8) * Nreal + col] = make_float2(h2, h3);
                    *(float2*)&Cout2[(size_t)row * Nreal + col]       = make_float2(tf32_hi(v0 - h0), tf32_hi(v1 - h1));
                    *(float2*)&Cout2[(size_t)(row + 8) * Nreal + col] = make_float2(tf32_hi(v2 - h2), tf32_hi(v3 - h3));
                } else {
                    *(float2*)&Cout[(size_t)row * Nreal + col]       = make_float2(v0, v1);
                    *(float2*)&Cout[(size_t)(row + 8) * Nreal + col] = make_float2(v2, v3);
                }
            }
        }
    }
}

// ---------------- elementwise split: x -> (hi, lo) tf32 pair ----------------
__global__ void split4_kernel(const float* __restrict__ x,
                              float* __restrict__ hi, float* __restrict__ lo, int n4)
{
    int i = blockIdx.x * blockDim.x + threadIdx.x;
    if (i >= n4) return;
    float4 v = ((const float4*)x)[i];
    float4 h, l;
    h.x = tf32_hi(v.x); l.x = tf32_hi(v.x - h.x);
    h.y = tf32_hi(v.y); l.y = tf32_hi(v.y - h.y);
    h.z = tf32_hi(v.z); l.z = tf32_hi(v.z - h.z);
    h.w = tf32_hi(v.w); l.w = tf32_hi(v.w - h.w);
    ((float4*)hi)[i] = h;
    ((float4*)lo)[i] = l;
}

// ---------------- transpose + split: W[K,N] -> Wt_hi/lo[Npad,K] (zero-padded) --
__global__ void tsplit_kernel(const float* __restrict__ W,
                              float* __restrict__ Thi, float* __restrict__ Tlo,
                              int K, int N)
{
    __shared__ float t[32][33];
    const int n0 = blockIdx.x * 32, k0 = blockIdx.y * 32;
    const int tx = threadIdx.x, ty = threadIdx.y;   // 32 x 8
    #pragma unroll
    for (int r = 0; r < 4; r++) {
        int k = k0 + ty + r * 8, n = n0 + tx;
        t[ty + r * 8][tx] = (n < N) ? W[(size_t)k * N + n] : 0.f;
    }
    __syncthreads();
    #pragma unroll
    for (int r = 0; r < 4; r++) {
        int n = n0 + ty + r * 8, k = k0 + tx;
        float v = t[tx][ty + r * 8];
        float h = tf32_hi(v);
        Thi[(size_t)n * K + k] = h;
        Tlo[(size_t)n * K + k] = tf32_hi(v - h);
    }
}

// ---------------- dtmod + dt/softplus + dA ----------------
__global__ void dt_kernel(const float* __restrict__ dte,
                          const float* __restrict__ Wd,
                          const float* __restrict__ bd,
                          const float* __restrict__ zx,
                          const float* __restrict__ dt_bias,
                          const float* __restrict__ A_log)
{
    int idx = blockIdx.x * blockDim.x + threadIdx.x;   // ROWS*NH
    if (idx >= ROWS * NH) return;
    int h   = idx & (NH - 1);
    int row = idx >> 5;
    const float* d = dte + (size_t)row * DTIME;
    float s = bd[h];
    #pragma unroll 8
    for (int j = 0; j < DTIME; j++) s = fmaf(d[j], Wd[j*NH + h], s);
    float x  = zx[(size_t)row * DIP + (DI + CD) + h] + dt_bias[h] + s;
    float dt = (x > 20.f) ? x : log1pf(expf(x));
    float A  = -expf(A_log[h]);
    g_dt[idx] = dt;
    g_dA[idx] = expf(dt * A);
}

// ---------------- causal conv (taps=4) + bias + silu ----------------
__global__ void conv_kernel(const float* __restrict__ zx,
                            const float* __restrict__ conv_w,
                            const float* __restrict__ conv_b)
{
    int idx = blockIdx.x * blockDim.x + threadIdx.x;   // ROWS*CD
    if (idx >= ROWS * CD) return;
    int c   = idx % CD;
    int row = idx / CD;
    int l   = row & (L_SZ - 1);
    int b   = row / L_SZ;
    float acc = conv_b[c];
    #pragma unroll
    for (int k = 0; k < DCONV; k++) {
        int ll = l - (DCONV - 1) + k;
        if (ll >= 0)
            acc = fmaf(zx[(size_t)(b*L_SZ + ll) * DIP + DI + c], conv_w[k*CD + c], acc);
    }
    g_xBCa[idx] = acc / (1.f + expf(-acc));   // silu
}

// ---------------- scan phase A: per-chunk local scan from zero state ----------
__global__ void __launch_bounds__(256) scanA_kernel(const float* __restrict__ Dvec)
{
    const int c = blockIdx.x, h = blockIdx.y, b = blockIdx.z;
    const int t = threadIdx.x;
    __shared__ float xs[2][64], Bs[2][128], Cs[2][128], red[2][256];

    const int p = t & 63, g = t >> 6, n0 = g * 32;
    float s[32];
    #pragma unroll
    for (int j = 0; j < 32; j++) s[j] = 0.f;
    float cum = 1.f;
    const float Dh = Dvec[h];
    const int l0 = c * CL;
    const int bh = b * NH + h;

    for (int li = 0; li < CL; li++) {
        const int l = l0 + li, par = li & 1;
        const float* base = g_xBCa + (size_t)(b*L_SZ + l) * CD;
        for (int i = t; i < 320; i += 256) {
            if (i < 64)        xs[par][i]       = base[h*HD + i];
            else if (i < 192)  Bs[par][i - 64]  = base[DI + (i - 64)];
            else               Cs[par][i - 192] = base[DI + DS + (i - 192)];
        }
        float dtv = g_dt[(b*L_SZ + l)*NH + h];
        float dAv = g_dA[(b*L_SZ + l)*NH + h];
        __syncthreads();

        float coef = dtv * xs[par][p];
        float acc = 0.f;
        #pragma unroll
        for (int j = 0; j < 32; j++) {
            s[j] = fmaf(dAv, s[j], coef * Bs[par][n0 + j]);
            acc  = fmaf(s[j], Cs[par][n0 + j], acc);
        }
        red[par][t] = acc;
        cum *= dAv;
        __syncthreads();

        if (t < 64) {
            float y = red[par][t] + red[par][t+64] + red[par][t+128] + red[par][t+192]
                    + Dh * xs[par][t];
            g_y[(size_t)(b*L_SZ + l)*DI + h*HD + t] = y;
        }
        if (t == 0) g_cumdec[bh*L_SZ + l] = cum;
    }

    const size_t sbase = ((size_t)bh * NC + c) * (HD * DS);
    #pragma unroll
    for (int j = 0; j < 32; j++) g_Sfinal[sbase + p*DS + n0 + j] = s[j];
}

// ---------------- scan phase B: sequential chunk-state combine (tiny) --------
__global__ void phaseB_kernel()
{
    const int bh = blockIdx.x;
    const int t  = threadIdx.x;
    for (int e = t; e < HD * DS; e += 256) {
        float hv = 0.f;
        for (int c = 0; c < NC; c++) {
            const size_t o = ((size_t)bh * NC + c) * (HD * DS) + e;
            g_Hinit[o] = hv;
            float P = g_cumdec[bh*L_SZ + c*CL + CL - 1];
            hv = fmaf(P, hv, g_Sfinal[o]);
        }
    }
}

// ---------------- scan phase C: rank-correction y += cumdec * C^T h_init -----
__global__ void __launch_bounds__(256) phaseC_kernel()
{
    const int c = blockIdx.x;
    if (c == 0) return;               // zero initial state
    const int h = blockIdx.y, b = blockIdx.z;
    const int t = threadIdx.x;
    __shared__ float Hs[64 * 129];
    __shared__ float Cs[2][128], red[2][256];

    const int bh = b * NH + h;
    const size_t hbase = ((size_t)bh * NC + c) * (HD * DS);
    for (int i = t; i < HD * DS; i += 256)
        Hs[(i >> 7) * 129 + (i & 127)] = g_Hinit[hbase + i];

    const int p = t & 63, g = t >> 6, n0 = g * 32;
    const int l0 = c * CL;
    __syncthreads();

    for (int li = 0; li < CL; li++) {
        const int l = l0 + li, par = li & 1;
        const float* base = g_xBCa + (size_t)(b*L_SZ + l) * CD + DI + DS;
        if (t < 128) Cs[par][t] = base[t];
        float cd = g_cumdec[bh*L_SZ + l];
        __syncthreads();

        float acc = 0.f;
        #pragma unroll
        for (int j = 0; j < 32; j++)
            acc = fmaf(Hs[p*129 + n0 + j], Cs[par][n0 + j], acc);
        red[par][t] = acc;
        __syncthreads();

        if (t < 64)
            g_y[(size_t)(b*L_SZ + l)*DI + h*HD + t] +=
                cd * (red[par][t] + red[par][t+64] + red[par][t+128] + red[par][t+192]);
    }
}

// ---------------- gating (silu(z)) + RMS norm -> split tf32 pair -------------
__global__ void __launch_bounds__(256) epilogue_kernel(const float* __restrict__ norm_w)
{
    const int row = blockIdx.x;       // b*L + l
    const int t   = threadIdx.x;
    float gv[8];
    float ss = 0.f;
    #pragma unroll
    for (int i = 0; i < 8; i++) {
        int cidx = t + i * 256;
        float yv = g_y[(size_t)row * DI + cidx];
        float zv = g_zx[(size_t)row * DIP + cidx];
        float sil = zv / (1.f + expf(-zv));
        float v = yv * sil;
        gv[i] = v;
        ss += v * v;
    }
    __shared__ float rs[32];
    #pragma unroll
    for (int o = 16; o; o >>= 1) ss += __shfl_xor_sync(~0u, ss, o);
    if ((t & 31) == 0) rs[t >> 5] = ss;
    __syncthreads();
    if (t < 32) {
        float v = (t < 8) ? rs[t] : 0.f;
        #pragma unroll
        for (int o = 4; o; o >>= 1) v += __shfl_xor_sync(~0u, v, o);
        if (t == 0) rs[0] = v;
    }
    __syncthreads();
    float scale = rsqrtf(rs[0] / (float)DI + EPSV);
    #pragma unroll
    for (int i = 0; i < 8; i++) {
        int cidx = t + i * 256;
        float v = gv[i] * scale * norm_w[cidx];
        float h = tf32_hi(v);
        const size_t off = (size_t)row * DI + cidx;
        g_yhi[off] = h;
        g_ylo[off] = tf32_hi(v - h);
    }
}

// ---------------- launch ----------------
extern "C" void kernel_launch(void* const* d_in, const int* in_sizes, int n_in,
                              void* d_out, int out_size)
{
    const float* hidden  = (const float*)d_in[0];
    const float* dte     = (const float*)d_in[1];
    const float* W_proj  = (const float*)d_in[2];
    const float* b_proj  = (const float*)d_in[3];
    const float* W_dtmod = (const float*)d_in[4];
    const float* b_dtmod = (const float*)d_in[5];
    const float* W_in    = (const float*)d_in[6];
    const float* conv_w  = (const float*)d_in[7];
    const float* conv_b  = (const float*)d_in[8];
    const float* dt_bias = (const float*)d_in[9];
    const float* A_log   = (const float*)d_in[10];
    const float* Dvec    = (const float*)d_in[11];
    const float* norm_w  = (const float*)d_in[12];
    const float* W_out   = (const float*)d_in[13];
    float* out = (float*)d_out;

    float *p_uhi, *p_ulo, *p_zx, *p_yhi, *p_ylo, *p_hhi, *p_hlo;
    float *p_wpt_hi, *p_wpt_lo, *p_wit_hi, *p_wit_lo, *p_wot_hi, *p_wot_lo;
    cudaGetSymbolAddress((void**)&p_uhi, g_uhi);
    cudaGetSymbolAddress((void**)&p_ulo, g_ulo);
    cudaGetSymbolAddress((void**)&p_zx,  g_zx);
    cudaGetSymbolAddress((void**)&p_yhi, g_yhi);
    cudaGetSymbolAddress((void**)&p_ylo, g_ylo);
    cudaGetSymbolAddress((void**)&p_hhi, g_hhi);
    cudaGetSymbolAddress((void**)&p_hlo, g_hlo);
    cudaGetSymbolAddress((void**)&p_wpt_hi, g_wpt_hi);
    cudaGetSymbolAddress((void**)&p_wpt_lo, g_wpt_lo);
    cudaGetSymbolAddress((void**)&p_wit_hi, g_wit_hi);
    cudaGetSymbolAddress((void**)&p_wit_lo, g_wit_lo);
    cudaGetSymbolAddress((void**)&p_wot_hi, g_wot_hi);
    cudaGetSymbolAddress((void**)&p_wot_lo, g_wot_lo);

    cudaFuncSetAttribute(gemm_mma<true,  true >, cudaFuncAttributeMaxDynamicSharedMemorySize, GEMM_SMEM_BYTES);
    cudaFuncSetAttribute(gemm_mma<false, false>, cudaFuncAttributeMaxDynamicSharedMemorySize, GEMM_SMEM_BYTES);

    // 0) operand prep: split hidden; transpose+split weights (padded where needed)
    split4_kernel<<<(ROWS*DM/4 + 255)/256, 256>>>(hidden, p_hhi, p_hlo, ROWS*DM/4);
    tsplit_kernel<<<dim3(DM/32,  DM/32), dim3(32,8)>>>(W_proj, p_wpt_hi, p_wpt_lo, DM, DM);
    tsplit_kernel<<<dim3(DIPPAD/32, DM/32), dim3(32,8)>>>(W_in,  p_wit_hi, p_wit_lo, DM, DIP);
    tsplit_kernel<<<dim3(DM/32,  DI/32), dim3(32,8)>>>(W_out, p_wot_hi, p_wot_lo, DI, DM);

    // 1) u = hidden @ W_proj + b_proj   (outputs split u directly)
    gemm_mma<true, true><<<dim3(DM/128, ROWS/128), 256, GEMM_SMEM_BYTES>>>(
        p_hhi, p_hlo, p_wpt_hi, p_wpt_lo, b_proj, p_uhi, p_ulo, ROWS, DM, DM);

    // 2) zxbcdt = u @ W_in
    gemm_mma<false, false><<<dim3(DIPPAD/128, ROWS/128), 256, GEMM_SMEM_BYTES>>>(
        p_uhi, p_ulo, p_wit_hi, p_wit_lo, nullptr, p_zx, nullptr, ROWS, DIP, DM);

    // 3) dt = softplus(dt_raw + dt_bias + dte@W_dtmod + b_dtmod); dA = exp(dt*A)
    dt_kernel<<<(ROWS*NH + 255)/256, 256>>>(dte, W_dtmod, b_dtmod, p_zx, dt_bias, A_log);

    // 4) xBC = silu(causal_conv(xBC) + conv_b)
    conv_kernel<<<(ROWS*CD + 255)/256, 256>>>(p_zx, conv_w, conv_b);

    // 5) chunked selective scan
    scanA_kernel<<<dim3(NC, NH, B_SZ), 256>>>(Dvec);
    phaseB_kernel<<<B_SZ*NH, 256>>>();
    phaseC_kernel<<<dim3(NC, NH, B_SZ), 256>>>();

    // 6) gating + RMS norm (writes split y)
    epilogue_kernel<<<ROWS, 256>>>(norm_w);

    // 7) out = yn @ W_out
    gemm_mma<false, false><<<dim3(DM/128, ROWS/128), 256, GEMM_SMEM_BYTES>>>(
        p_yhi, p_ylo, p_wot_hi, p_wot_lo, nullptr, out, nullptr, ROWS, DM, DI);
}

// round 4
// speedup vs baseline: 1.5922x; 1.3024x over previous
#include <cuda_runtime.h>
#include <cuda_fp16.h>
#include <cuda_bf16.h>
#include <cstdint>

// ---------------- problem constants ----------------
#define B_SZ   2
#define L_SZ   2048
#define DM     1024      // d_model
#define DI     2048      // d_inner
#define DS     128       // d_state
#define DCONV  4
#define NH     32        // nheads
#define HD     64        // headdim
#define DTIME  64
#define CD     (DI + 2*DS)            // 2304 conv dim
#define DIP    (2*DI + 2*DS + NH)     // 4384 in-proj dim
#define DIPPAD 4480                   // 35*128
#define ROWS   (B_SZ*L_SZ)            // 4096
#define NC     16                     // scan chunks
#define CL     (L_SZ/NC)              // 128 chunk len
#define EPSV   1e-5f

// ---------------- scratch (device globals; no allocs allowed) ----------------
__device__ __half g_uhi[ROWS*DM], g_ulo[ROWS*DM];
__device__ float  g_zx[ROWS*DIP];
__device__ float  g_xBCa[ROWS*CD];
__device__ float  g_dt[ROWS*NH];
__device__ float  g_dA[ROWS*NH];
__device__ float  g_cumdec[B_SZ*NH*L_SZ];
__device__ float  g_Sfinal[B_SZ*NH*NC*HD*DS];
__device__ float  g_Hinit [B_SZ*NH*NC*HD*DS];
__device__ float  g_y[ROWS*DI];
__device__ __half g_yhi[ROWS*DI], g_ylo[ROWS*DI];
__device__ __half g_hhi[ROWS*DM], g_hlo[ROWS*DM];
__device__ __half g_wpt_hi[DM*DM],     g_wpt_lo[DM*DM];      // W_proj^T  [1024][1024]
__device__ __half g_wit_hi[DIPPAD*DM], g_wit_lo[DIPPAD*DM];  // W_in^T    [4480][1024]
__device__ __half g_wot_hi[DM*DI],     g_wot_lo[DM*DI];      // W_out^T   [1024][2048]

// ---------------- mma / ldmatrix helpers ----------------
__device__ __forceinline__ void mma16(float& d0, float& d1, float& d2, float& d3,
                                      uint32_t a0, uint32_t a1, uint32_t a2, uint32_t a3,
                                      uint32_t b0, uint32_t b1)
{
    asm volatile("mma.sync.aligned.m16n8k16.row.col.f32.f16.f16.f32 "
        "{%0,%1,%2,%3},{%4,%5,%6,%7},{%8,%9},{%0,%1,%2,%3};"
        : "+f"(d0), "+f"(d1), "+f"(d2), "+f"(d3)
        : "r"(a0), "r"(a1), "r"(a2), "r"(a3), "r"(b0), "r"(b1));
}
#define LDSM4(r0,r1,r2,r3, addr) \
    asm volatile("ldmatrix.sync.aligned.m8n8.x4.shared.b16 {%0,%1,%2,%3}, [%4];" \
        : "=r"(r0), "=r"(r1), "=r"(r2), "=r"(r3) : "r"(addr))

// smem geometry: rows of 64 halfs padded to 72 (144B stride; 8-row groups bank-disjoint)
#define HSTRIDE 72
#define TBYTES  (128 * HSTRIDE * 2)       // 18432 bytes per tensor per stage
#define STAGEB  (4 * TBYTES)              // Ahi,Alo,Bhi,Blo = 73728
#define GEMM_SMEM_BYTES (2 * STAGEB)      // 147456

// ---------------- split-FP16 GEMM via mma.sync m16n8k16 ----------------------
// C = (Ahi+Alo)[M,K] @ (Bhi+Blo)^T, Bt stored [Npad,K] K-major halves.
// 3 passes: AhiBhi + AhiBlo + AloBhi.  grid=(Npad/128, M/128), 8 warps (2x4),
// warp tile 64x32, K-step 64.
template<bool HAS_BIAS, bool SPLIT_OUT>
__global__ void __launch_bounds__(256, 1) gemm_h(
    const __half* __restrict__ Ahi, const __half* __restrict__ Alo,
    const __half* __restrict__ Bhi, const __half* __restrict__ Blo,
    const float* __restrict__ bias,
    float* __restrict__ Cout, __half* __restrict__ Hout, __half* __restrict__ Lout,
    int M, int Nreal, int K)
{
    extern __shared__ __align__(16) char smem[];
    const uint32_t sb = (uint32_t)__cvta_generic_to_shared(smem);
    const int tid = threadIdx.x;
    const int wid = tid >> 5;
    const int lane = tid & 31;
    const int wm = wid & 1;           // warp row (2)
    const int wn = wid >> 1;          // warp col (4)
    const int r = lane >> 2;          // 0..7
    const int c = lane & 3;           // 0..3
    const int m0 = blockIdx.y << 7;
    const int n0 = blockIdx.x << 7;
    const int nsteps = K >> 6;

    // loader role: 64 threads per tensor {Ahi,Alo,Bhi,Blo}
    const int t4  = tid >> 6;
    const int l64 = tid & 63;
    const __half* gsel = (t4 == 0) ? Ahi : (t4 == 1) ? Alo : (t4 == 2) ? Bhi : Blo;
    const int rb = (t4 < 2) ? m0 : n0;

    auto load_stage = [&](int kstep, int s) {
        const int k0 = kstep << 6;
        const __half* gb = gsel + (size_t)rb * K + k0;
        const uint32_t tb = sb + (uint32_t)(s * STAGEB + t4 * TBYTES);
        #pragma unroll
        for (int j = 0; j < 16; j++) {
            int q = j * 64 + l64;             // 1024 chunks of 16B
            int row = q >> 3, col = q & 7;
            const __half* gp = gb + (size_t)row * K + (col << 3);
            uint32_t sa = tb + (uint32_t)(row * (HSTRIDE * 2) + (col << 4));
            asm volatile("cp.async.cg.shared.global [%0], [%1], 16;" :: "r"(sa), "l"(gp) : "memory");
        }
        asm volatile("cp.async.commit_group;" ::: "memory");
    };

    float acc[4][4][4];
    #pragma unroll
    for (int i = 0; i < 4; i++)
        #pragma unroll
        for (int j = 0; j < 4; j++)
            #pragma unroll
            for (int q = 0; q < 4; q++) acc[i][j][q] = 0.f;

    // ldmatrix per-thread row offsets
    const int lrow = lane & 15;
    const int lk16 = (lane >> 4) << 4;  // 0 or 16 bytes (8 halves)
    uint32_t arow_off[4], brow_off[2];
    #pragma unroll
    for (int mt = 0; mt < 4; mt++)
        arow_off[mt] = (uint32_t)((wm * 64 + mt * 16 + lrow) * (HSTRIDE * 2)) + (uint32_t)lk16;
    #pragma unroll
    for (int g = 0; g < 2; g++)
        brow_off[g] = (uint32_t)((wn * 32 + g * 16 + lrow) * (HSTRIDE * 2)) + (uint32_t)lk16;

    load_stage(0, 0);

    for (int i = 0; i < nsteps; i++) {
        if (i + 1 < nsteps) {
            load_stage(i + 1, (i + 1) & 1);
            asm volatile("cp.async.wait_group 1;" ::: "memory");
        } else {
            asm volatile("cp.async.wait_group 0;" ::: "memory");
        }
        __syncthreads();

        const int s = i & 1;
        const uint32_t stA_hi = sb + (uint32_t)(s * STAGEB);
        const uint32_t stA_lo = stA_hi + TBYTES;
        const uint32_t stB_hi = stA_hi + 2 * TBYTES;
        const uint32_t stB_lo = stA_hi + 3 * TBYTES;

        #pragma unroll
        for (int kb = 0; kb < 4; kb++) {
            const uint32_t koff = (uint32_t)(kb << 5);   // kb*16 halves = 32 bytes
            uint32_t ah[4][4], al[4][4], bh[4][2], bl[4][2];
            #pragma unroll
            for (int mt = 0; mt < 4; mt++) {
                LDSM4(ah[mt][0], ah[mt][1], ah[mt][2], ah[mt][3], stA_hi + arow_off[mt] + koff);
                LDSM4(al[mt][0], al[mt][1], al[mt][2], al[mt][3], stA_lo + arow_off[mt] + koff);
            }
            #pragma unroll
            for (int g = 0; g < 2; g++) {
                uint32_t r0, r1, r2, r3;
                LDSM4(r0, r1, r2, r3, stB_hi + brow_off[g] + koff);
                bh[2*g][0] = r0; bh[2*g+1][0] = r1; bh[2*g][1] = r2; bh[2*g+1][1] = r3;
                LDSM4(r0, r1, r2, r3, stB_lo + brow_off[g] + koff);
                bl[2*g][0] = r0; bl[2*g+1][0] = r1; bl[2*g][1] = r2; bl[2*g+1][1] = r3;
            }
            #pragma unroll
            for (int mt = 0; mt < 4; mt++)
                #pragma unroll
                for (int nt = 0; nt < 4; nt++) {
                    float* d = acc[mt][nt];
                    mma16(d[0], d[1], d[2], d[3],
                          ah[mt][0], ah[mt][1], ah[mt][2], ah[mt][3], bh[nt][0], bh[nt][1]);
                    mma16(d[0], d[1], d[2], d[3],
                          ah[mt][0], ah[mt][1], ah[mt][2], ah[mt][3], bl[nt][0], bl[nt][1]);
                    mma16(d[0], d[1], d[2], d[3],
                          al[mt][0], al[mt][1], al[mt][2], al[mt][3], bh[nt][0], bh[nt][1]);
                }
        }
        __syncthreads();
    }

    // epilogue: thread (r,c) owns rows {row, row+8}, cols {2c, 2c+1} per tile
    #pragma unroll
    for (int mt = 0; mt < 4; mt++) {
        const int row = m0 + wm * 64 + mt * 16 + r;
        #pragma unroll
        for (int nt = 0; nt < 4; nt++) {
            const int col = n0 + wn * 32 + nt * 8 + 2 * c;
            if (col < Nreal) {
                float v0 = acc[mt][nt][0], v1 = acc[mt][nt][1];
                float v2 = acc[mt][nt][2], v3 = acc[mt][nt][3];
                if (HAS_BIAS) {
                    float b0 = bias[col], b1 = bias[col + 1];
                    v0 += b0; v1 += b1; v2 += b0; v3 += b1;
                }
                if (SPLIT_OUT) {
                    __half h0 = __float2half_rn(v0), h1 = __float2half_rn(v1);
                    __half h2 = __float2half_rn(v2), h3 = __float2half_rn(v3);
                    *(half2*)&Hout[(size_t)row * Nreal + col]       = __halves2half2(h0, h1);
                    *(half2*)&Hout[(size_t)(row + 8) * Nreal + col] = __halves2half2(h2, h3);
                    *(half2*)&Lout[(size_t)row * Nreal + col] =
                        __halves2half2(__float2half_rn(v0 - __half2float(h0)),
                                       __float2half_rn(v1 - __half2float(h1)));
                    *(half2*)&Lout[(size_t)(row + 8) * Nreal + col] =
                        __halves2half2(__float2half_rn(v2 - __half2float(h2)),
                                       __float2half_rn(v3 - __half2float(h3)));
                } else {
                    *(float2*)&Cout[(size_t)row * Nreal + col]       = make_float2(v0, v1);
                    *(float2*)&Cout[(size_t)(row + 8) * Nreal + col] = make_float2(v2, v3);
                }
            }
        }
    }
}

// ---------------- elementwise split: float -> (hi, lo) fp16 pair -------------
__global__ void split4h_kernel(const float* __restrict__ x,
                               __half* __restrict__ hi, __half* __restrict__ lo, int n4)
{
    int i = blockIdx.x * blockDim.x + threadIdx.x;
    if (i >= n4) return;
    float4 v = ((const float4*)x)[i];
    __half h0 = __float2half_rn(v.x), h1 = __float2half_rn(v.y);
    __half h2 = __float2half_rn(v.z), h3 = __float2half_rn(v.w);
    half2 hA = __halves2half2(h0, h1), hB = __halves2half2(h2, h3);
    half2 lA = __halves2half2(__float2half_rn(v.x - __half2float(h0)),
                              __float2half_rn(v.y - __half2float(h1)));
    half2 lB = __halves2half2(__float2half_rn(v.z - __half2float(h2)),
                              __float2half_rn(v.w - __half2float(h3)));
    ((half2*)hi)[2*i]   = hA; ((half2*)hi)[2*i+1] = hB;
    ((half2*)lo)[2*i]   = lA; ((half2*)lo)[2*i+1] = lB;
}

// ---------------- transpose + split: W[K,N] -> Wt_hi/lo[Npad,K] fp16 ---------
__global__ void tsplit_kernel(const float* __restrict__ W,
                              __half* __restrict__ Thi, __half* __restrict__ Tlo,
                              int K, int N)
{
    __shared__ float t[32][33];
    const int n0 = blockIdx.x * 32, k0 = blockIdx.y * 32;
    const int tx = threadIdx.x, ty = threadIdx.y;   // 32 x 8
    #pragma unroll
    for (int r = 0; r < 4; r++) {
        int k = k0 + ty + r * 8, n = n0 + tx;
        t[ty + r * 8][tx] = (n < N) ? W[(size_t)k * N + n] : 0.f;
    }
    __syncthreads();
    #pragma unroll
    for (int r = 0; r < 4; r++) {
        int n = n0 + ty + r * 8, k = k0 + tx;
        float v = t[tx][ty + r * 8];
        __half h = __float2half_rn(v);
        Thi[(size_t)n * K + k] = h;
        Tlo[(size_t)n * K + k] = __float2half_rn(v - __half2float(h));
    }
}

// ---------------- dtmod + dt/softplus + dA ----------------
__global__ void dt_kernel(const float* __restrict__ dte,
                          const float* __restrict__ Wd,
                          const float* __restrict__ bd,
                          const float* __restrict__ zx,
                          const float* __restrict__ dt_bias,
                          const float* __restrict__ A_log)
{
    int idx = blockIdx.x * blockDim.x + threadIdx.x;   // ROWS*NH
    if (idx >= ROWS * NH) return;
    int h   = idx & (NH - 1);
    int row = idx >> 5;
    const float* d = dte + (size_t)row * DTIME;
    float s = bd[h];
    #pragma unroll 8
    for (int j = 0; j < DTIME; j++) s = fmaf(d[j], Wd[j*NH + h], s);
    float x  = zx[(size_t)row * DIP + (DI + CD) + h] + dt_bias[h] + s;
    float dt = (x > 20.f) ? x : log1pf(expf(x));
    float A  = -expf(A_log[h]);
    g_dt[idx] = dt;
    g_dA[idx] = expf(dt * A);
}

// ---------------- causal conv (taps=4) + bias + silu ----------------
__global__ void conv_kernel(const float* __restrict__ zx,
                            const float* __restrict__ conv_w,
                            const float* __restrict__ conv_b)
{
    int idx = blockIdx.x * blockDim.x + threadIdx.x;   // ROWS*CD
    if (idx >= ROWS * CD) return;
    int c   = idx % CD;
    int row = idx / CD;
    int l   = row & (L_SZ - 1);
    int b   = row / L_SZ;
    float acc = conv_b[c];
    #pragma unroll
    for (int k = 0; k < DCONV; k++) {
        int ll = l - (DCONV - 1) + k;
        if (ll >= 0)
            acc = fmaf(zx[(size_t)(b*L_SZ + ll) * DIP + DI + c], conv_w[k*CD + c], acc);
    }
    g_xBCa[idx] = acc / (1.f + expf(-acc));   // silu
}

// ---------------- scan phase A: per-chunk local scan from zero state ----------
__global__ void __launch_bounds__(256) scanA_kernel(const float* __restrict__ Dvec)
{
    const int c = blockIdx.x, h = blockIdx.y, b = blockIdx.z;
    const int t = threadIdx.x;
    __shared__ float xs[2][64], Bs[2][128], Cs[2][128], red[2][256];

    const int p = t & 63, g = t >> 6, n0 = g * 32;
    float s[32];
    #pragma unroll
    for (int j = 0; j < 32; j++) s[j] = 0.f;
    float cum = 1.f;
    const float Dh = Dvec[h];
    const int l0 = c * CL;
    const int bh = b * NH + h;

    for (int li = 0; li < CL; li++) {
        const int l = l0 + li, par = li & 1;
        const float* base = g_xBCa + (size_t)(b*L_SZ + l) * CD;
        for (int i = t; i < 320; i += 256) {
            if (i < 64)        xs[par][i]       = base[h*HD + i];
            else if (i < 192)  Bs[par][i - 64]  = base[DI + (i - 64)];
            else               Cs[par][i - 192] = base[DI + DS + (i - 192)];
        }
        float dtv = g_dt[(b*L_SZ + l)*NH + h];
        float dAv = g_dA[(b*L_SZ + l)*NH + h];
        __syncthreads();

        float coef = dtv * xs[par][p];
        float acc = 0.f;
        #pragma unroll
        for (int j = 0; j < 32; j++) {
            s[j] = fmaf(dAv, s[j], coef * Bs[par][n0 + j]);
            acc  = fmaf(s[j], Cs[par][n0 + j], acc);
        }
        red[par][t] = acc;
        cum *= dAv;
        __syncthreads();

        if (t < 64) {
            float y = red[par][t] + red[par][t+64] + red[par][t+128] + red[par][t+192]
                    + Dh * xs[par][t];
            g_y[(size_t)(b*L_SZ + l)*DI + h*HD + t] = y;
        }
        if (t == 0) g_cumdec[bh*L_SZ + l] = cum;
    }

    const size_t sbase = ((size_t)bh * NC + c) * (HD * DS);
    #pragma unroll
    for (int j = 0; j < 32; j++) g_Sfinal[sbase + p*DS + n0 + j] = s[j];
}

// ---------------- scan phase B: sequential chunk-state combine (tiny) --------
__global__ void phaseB_kernel()
{
    const int bh = blockIdx.x;
    const int t  = threadIdx.x;
    for (int e = t; e < HD * DS; e += 256) {
        float hv = 0.f;
        for (int c = 0; c < NC; c++) {
            const size_t o = ((size_t)bh * NC + c) * (HD * DS) + e;
            g_Hinit[o] = hv;
            float P = g_cumdec[bh*L_SZ + c*CL + CL - 1];
            hv = fmaf(P, hv, g_Sfinal[o]);
        }
    }
}

// ---------------- scan phase C: rank-correction y += cumdec * C^T h_init -----
__global__ void __launch_bounds__(256) phaseC_kernel()
{
    const int c = blockIdx.x;
    if (c == 0) return;               // zero initial state
    const int h = blockIdx.y, b = blockIdx.z;
    const int t = threadIdx.x;
    __shared__ float Hs[64 * 129];
    __shared__ float Cs[2][128], red[2][256];

    const int bh = b * NH + h;
    const size_t hbase = ((size_t)bh * NC + c) * (HD * DS);
    for (int i = t; i < HD * DS; i += 256)
        Hs[(i >> 7) * 129 + (i & 127)] = g_Hinit[hbase + i];

    const int p = t & 63, g = t >> 6, n0 = g * 32;
    const int l0 = c * CL;
    __syncthreads();

    for (int li = 0; li < CL; li++) {
        const int l = l0 + li, par = li & 1;
        const float* base = g_xBCa + (size_t)(b*L_SZ + l) * CD + DI + DS;
        if (t < 128) Cs[par][t] = base[t];
        float cd = g_cumdec[bh*L_SZ + l];
        __syncthreads();

        float acc = 0.f;
        #pragma unroll
        for (int j = 0; j < 32; j++)
            acc = fmaf(Hs[p*129 + n0 + j], Cs[par][n0 + j], acc);
        red[par][t] = acc;
        __syncthreads();

        if (t < 64)
            g_y[(size_t)(b*L_SZ + l)*DI + h*HD + t] +=
                cd * (red[par][t] + red[par][t+64] + red[par][t+128] + red[par][t+192]);
    }
}

// ---------------- gating (silu(z)) + RMS norm -> split fp16 pair -------------
__global__ void __launch_bounds__(256) epilogue_kernel(const float* __restrict__ norm_w)
{
    const int row = blockIdx.x;       // b*L + l
    const int t   = threadIdx.x;
    float gv[8];
    float ss = 0.f;
    #pragma unroll
    for (int i = 0; i < 8; i++) {
        int cidx = t + i * 256;
        float yv = g_y[(size_t)row * DI + cidx];
        float zv = g_zx[(size_t)row * DIP + cidx];
        float sil = zv / (1.f + expf(-zv));
        float v = yv * sil;
        gv[i] = v;
        ss += v * v;
    }
    __shared__ float rs[32];
    #pragma unroll
    for (int o = 16; o; o >>= 1) ss += __shfl_xor_sync(~0u, ss, o);
    if ((t & 31) == 0) rs[t >> 5] = ss;
    __syncthreads();
    if (t < 32) {
        float v = (t < 8) ? rs[t] : 0.f;
        #pragma unroll
        for (int o = 4; o; o >>= 1) v += __shfl_xor_sync(~0u, v, o);
        if (t == 0) rs[0] = v;
    }
    __syncthreads();
    float scale = rsqrtf(rs[0] / (float)DI + EPSV);
    #pragma unroll
    for (int i = 0; i < 8; i++) {
        int cidx = t + i * 256;
        float v = gv[i] * scale * norm_w[cidx];
        __half h = __float2half_rn(v);
        const size_t off = (size_t)row * DI + cidx;
        g_yhi[off] = h;
        g_ylo[off] = __float2half_rn(v - __half2float(h));
    }
}

// ---------------- launch ----------------
extern "C" void kernel_launch(void* const* d_in, const int* in_sizes, int n_in,
                              void* d_out, int out_size)
{
    const float* hidden  = (const float*)d_in[0];
    const float* dte     = (const float*)d_in[1];
    const float* W_proj  = (const float*)d_in[2];
    const float* b_proj  = (const float*)d_in[3];
    const float* W_dtmod = (const float*)d_in[4];
    const float* b_dtmod = (const float*)d_in[5];
    const float* W_in    = (const float*)d_in[6];
    const float* conv_w  = (const float*)d_in[7];
    const float* conv_b  = (const float*)d_in[8];
    const float* dt_bias = (const float*)d_in[9];
    const float* A_log   = (const float*)d_in[10];
    const float* Dvec    = (const float*)d_in[11];
    const float* norm_w  = (const float*)d_in[12];
    const float* W_out   = (const float*)d_in[13];
    float* out = (float*)d_out;

    float *p_zx;
    __half *p_uhi, *p_ulo, *p_yhi, *p_ylo, *p_hhi, *p_hlo;
    __half *p_wpt_hi, *p_wpt_lo, *p_wit_hi, *p_wit_lo, *p_wot_hi, *p_wot_lo;
    cudaGetSymbolAddress((void**)&p_uhi, g_uhi);
    cudaGetSymbolAddress((void**)&p_ulo, g_ulo);
    cudaGetSymbolAddress((void**)&p_zx,  g_zx);
    cudaGetSymbolAddress((void**)&p_yhi, g_yhi);
    cudaGetSymbolAddress((void**)&p_ylo, g_ylo);
    cudaGetSymbolAddress((void**)&p_hhi, g_hhi);
    cudaGetSymbolAddress((void**)&p_hlo, g_hlo);
    cudaGetSymbolAddress((void**)&p_wpt_hi, g_wpt_hi);
    cudaGetSymbolAddress((void**)&p_wpt_lo, g_wpt_lo);
    cudaGetSymbolAddress((void**)&p_wit_hi, g_wit_hi);
    cudaGetSymbolAddress((void**)&p_wit_lo, g_wit_lo);
    cudaGetSymbolAddress((void**)&p_wot_hi, g_wot_hi);
    cudaGetSymbolAddress((void**)&p_wot_lo, g_wot_lo);

    cudaFuncSetAttribute(gemm_h<true,  true >, cudaFuncAttributeMaxDynamicSharedMemorySize, GEMM_SMEM_BYTES);
    cudaFuncSetAttribute(gemm_h<false, false>, cudaFuncAttributeMaxDynamicSharedMemorySize, GEMM_SMEM_BYTES);

    // 0) operand prep: split hidden; transpose+split weights (fp16 hi/lo)
    split4h_kernel<<<(ROWS*DM/4 + 255)/256, 256>>>(hidden, p_hhi, p_hlo, ROWS*DM/4);
    tsplit_kernel<<<dim3(DM/32,  DM/32), dim3(32,8)>>>(W_proj, p_wpt_hi, p_wpt_lo, DM, DM);
    tsplit_kernel<<<dim3(DIPPAD/32, DM/32), dim3(32,8)>>>(W_in,  p_wit_hi, p_wit_lo, DM, DIP);
    tsplit_kernel<<<dim3(DM/32,  DI/32), dim3(32,8)>>>(W_out, p_wot_hi, p_wot_lo, DI, DM);

    // 1) u = hidden @ W_proj + b_proj   (outputs split u directly)
    gemm_h<true, true><<<dim3(DM/128, ROWS/128), 256, GEMM_SMEM_BYTES>>>(
        p_hhi, p_hlo, p_wpt_hi, p_wpt_lo, b_proj, nullptr, p_uhi, p_ulo, ROWS, DM, DM);

    // 2) zxbcdt = u @ W_in
    gemm_h<false, false><<<dim3(DIPPAD/128, ROWS/128), 256, GEMM_SMEM_BYTES>>>(
        p_uhi, p_ulo, p_wit_hi, p_wit_lo, nullptr, p_zx, nullptr, nullptr, ROWS, DIP, DM);

    // 3) dt = softplus(dt_raw + dt_bias + dte@W_dtmod + b_dtmod); dA = exp(dt*A)
    dt_kernel<<<(ROWS*NH + 255)/256, 256>>>(dte, W_dtmod, b_dtmod, p_zx, dt_bias, A_log);

    // 4) xBC = silu(causal_conv(xBC) + conv_b)
    conv_kernel<<<(ROWS*CD + 255)/256, 256>>>(p_zx, conv_w, conv_b);

    // 5) chunked selective scan
    scanA_kernel<<<dim3(NC, NH, B_SZ), 256>>>(Dvec);
    phaseB_kernel<<<B_SZ*NH, 256>>>();
    phaseC_kernel<<<dim3(NC, NH, B_SZ), 256>>>();

    // 6) gating + RMS norm (writes split y)
    epilogue_kernel<<<ROWS, 256>>>(norm_w);

    // 7) out = yn @ W_out
    gemm_h<false, false><<<dim3(DM/128, ROWS/128), 256, GEMM_SMEM_BYTES>>>(
        p_yhi, p_ylo, p_wot_hi, p_wot_lo, nullptr, out, nullptr, nullptr, ROWS, DM, DI);
}

// round 5
// speedup vs baseline: 1.6069x; 1.0092x over previous
#include <cuda_runtime.h>
#include <cuda_fp16.h>
#include <cuda_bf16.h>
#include <cstdint>

// ---------------- problem constants ----------------
#define B_SZ   2
#define L_SZ   2048
#define DM     1024      // d_model
#define DI     2048      // d_inner
#define DS     128       // d_state
#define DCONV  4
#define NH     32        // nheads
#define HD     64        // headdim
#define DTIME  64
#define CD     (DI + 2*DS)            // 2304 conv dim
#define DIP    (2*DI + 2*DS + NH)     // 4384 in-proj dim
#define DIPPAD 4480                   // 35*128
#define ROWS   (B_SZ*L_SZ)            // 4096
#define NC     16                     // scan chunks
#define CL     (L_SZ/NC)              // 128 chunk len
#define EPSV   1e-5f

// ---------------- scratch (device globals; no allocs allowed) ----------------
__device__ __half g_uhi[ROWS*DM], g_ulo[ROWS*DM];
__device__ float  g_zx[ROWS*DIP];
__device__ float  g_xBCa[ROWS*CD];
__device__ float  g_dt[ROWS*NH];
__device__ float  g_dA[ROWS*NH];
__device__ float  g_cumdec[B_SZ*NH*L_SZ];
__device__ float  g_Sfinal[B_SZ*NH*NC*HD*DS];
__device__ float  g_Hinit [B_SZ*NH*NC*HD*DS];
__device__ float  g_y[ROWS*DI];
__device__ __half g_yhi[ROWS*DI], g_ylo[ROWS*DI];
__device__ __half g_hhi[ROWS*DM], g_hlo[ROWS*DM];
__device__ __half g_wpt_hi[DM*DM],     g_wpt_lo[DM*DM];      // W_proj^T  [1024][1024]
__device__ __half g_wit_hi[DIPPAD*DM], g_wit_lo[DIPPAD*DM];  // W_in^T    [4480][1024]
__device__ __half g_wot_hi[DM*DI],     g_wot_lo[DM*DI];      // W_out^T   [1024][2048]

// ---------------- mma / ldmatrix helpers ----------------
__device__ __forceinline__ void mma16(float& d0, float& d1, float& d2, float& d3,
                                      uint32_t a0, uint32_t a1, uint32_t a2, uint32_t a3,
                                      uint32_t b0, uint32_t b1)
{
    asm volatile("mma.sync.aligned.m16n8k16.row.col.f32.f16.f16.f32 "
        "{%0,%1,%2,%3},{%4,%5,%6,%7},{%8,%9},{%0,%1,%2,%3};"
        : "+f"(d0), "+f"(d1), "+f"(d2), "+f"(d3)
        : "r"(a0), "r"(a1), "r"(a2), "r"(a3), "r"(b0), "r"(b1));
}
#define LDSM4(r0,r1,r2,r3, addr) \
    asm volatile("ldmatrix.sync.aligned.m8n8.x4.shared.b16 {%0,%1,%2,%3}, [%4];" \
        : "=r"(r0), "=r"(r1), "=r"(r2), "=r"(r3) : "r"(addr))

// smem geometry: rows of 64 halfs padded to 72 (144B stride; 8-row groups bank-disjoint)
#define HSTRIDE 72
#define TBYTES  (128 * HSTRIDE * 2)       // 18432 bytes per tensor per stage
#define STAGEB  (4 * TBYTES)              // Ahi,Alo,Bhi,Blo = 73728
#define GEMM_SMEM_BYTES (2 * STAGEB)      // 147456

// ---------------- split-FP16 GEMM via mma.sync m16n8k16 ----------------------
// C = (Ahi+Alo)[M,K] @ (Bhi+Blo)^T, Bt stored [Npad,K] K-major halves.
// 3 passes: AhiBhi + AhiBlo + AloBhi.  grid=(Npad/128, M/128), 512 threads =
// 16 warps (4x4), warp tile 32x32, K-step 64.
template<bool HAS_BIAS, bool SPLIT_OUT>
__global__ void __launch_bounds__(512, 1) gemm_h(
    const __half* __restrict__ Ahi, const __half* __restrict__ Alo,
    const __half* __restrict__ Bhi, const __half* __restrict__ Blo,
    const float* __restrict__ bias,
    float* __restrict__ Cout, __half* __restrict__ Hout, __half* __restrict__ Lout,
    int M, int Nreal, int K)
{
    extern __shared__ __align__(16) char smem[];
    const uint32_t sb = (uint32_t)__cvta_generic_to_shared(smem);
    const int tid = threadIdx.x;
    const int wid = tid >> 5;
    const int lane = tid & 31;
    const int wm = wid & 3;           // warp row (4)
    const int wn = wid >> 2;          // warp col (4)
    const int r = lane >> 2;          // 0..7
    const int c = lane & 3;           // 0..3
    const int m0 = blockIdx.y << 7;
    const int n0 = blockIdx.x << 7;
    const int nsteps = K >> 6;

    // loader role: 128 threads per tensor {Ahi,Alo,Bhi,Blo}
    const int t4   = tid >> 7;
    const int l128 = tid & 127;
    const __half* gsel = (t4 == 0) ? Ahi : (t4 == 1) ? Alo : (t4 == 2) ? Bhi : Blo;
    const int rb = (t4 < 2) ? m0 : n0;

    auto load_stage = [&](int kstep, int s) {
        const int k0 = kstep << 6;
        const __half* gb = gsel + (size_t)rb * K + k0;
        const uint32_t tb = sb + (uint32_t)(s * STAGEB + t4 * TBYTES);
        #pragma unroll
        for (int j = 0; j < 8; j++) {
            int q = j * 128 + l128;           // 1024 chunks of 16B
            int row = q >> 3, col = q & 7;
            const __half* gp = gb + (size_t)row * K + (col << 3);
            uint32_t sa = tb + (uint32_t)(row * (HSTRIDE * 2) + (col << 4));
            asm volatile("cp.async.cg.shared.global [%0], [%1], 16;" :: "r"(sa), "l"(gp) : "memory");
        }
        asm volatile("cp.async.commit_group;" ::: "memory");
    };

    float acc[2][4][4];
    #pragma unroll
    for (int i = 0; i < 2; i++)
        #pragma unroll
        for (int j = 0; j < 4; j++)
            #pragma unroll
            for (int q = 0; q < 4; q++) acc[i][j][q] = 0.f;

    // ldmatrix per-thread row offsets
    const int lrow = lane & 15;
    const int lk16 = (lane >> 4) << 4;  // 0 or 16 bytes (8 halves)
    uint32_t arow_off[2], brow_off[2];
    #pragma unroll
    for (int mt = 0; mt < 2; mt++)
        arow_off[mt] = (uint32_t)((wm * 32 + mt * 16 + lrow) * (HSTRIDE * 2)) + (uint32_t)lk16;
    #pragma unroll
    for (int g = 0; g < 2; g++)
        brow_off[g] = (uint32_t)((wn * 32 + g * 16 + lrow) * (HSTRIDE * 2)) + (uint32_t)lk16;

    load_stage(0, 0);

    for (int i = 0; i < nsteps; i++) {
        if (i + 1 < nsteps) {
            load_stage(i + 1, (i + 1) & 1);
            asm volatile("cp.async.wait_group 1;" ::: "memory");
        } else {
            asm volatile("cp.async.wait_group 0;" ::: "memory");
        }
        __syncthreads();

        const int s = i & 1;
        const uint32_t stA_hi = sb + (uint32_t)(s * STAGEB);
        const uint32_t stA_lo = stA_hi + TBYTES;
        const uint32_t stB_hi = stA_hi + 2 * TBYTES;
        const uint32_t stB_lo = stA_hi + 3 * TBYTES;

        #pragma unroll
        for (int kb = 0; kb < 4; kb++) {
            const uint32_t koff = (uint32_t)(kb << 5);   // kb*16 halves = 32 bytes
            uint32_t ah[2][4], al[2][4], bh[4][2], bl[4][2];
            #pragma unroll
            for (int mt = 0; mt < 2; mt++) {
                LDSM4(ah[mt][0], ah[mt][1], ah[mt][2], ah[mt][3], stA_hi + arow_off[mt] + koff);
                LDSM4(al[mt][0], al[mt][1], al[mt][2], al[mt][3], stA_lo + arow_off[mt] + koff);
            }
            #pragma unroll
            for (int g = 0; g < 2; g++) {
                uint32_t r0, r1, r2, r3;
                LDSM4(r0, r1, r2, r3, stB_hi + brow_off[g] + koff);
                bh[2*g][0] = r0; bh[2*g+1][0] = r1; bh[2*g][1] = r2; bh[2*g+1][1] = r3;
                LDSM4(r0, r1, r2, r3, stB_lo + brow_off[g] + koff);
                bl[2*g][0] = r0; bl[2*g+1][0] = r1; bl[2*g][1] = r2; bl[2*g+1][1] = r3;
            }
            #pragma unroll
            for (int mt = 0; mt < 2; mt++)
                #pragma unroll
                for (int nt = 0; nt < 4; nt++) {
                    float* d = acc[mt][nt];
                    mma16(d[0], d[1], d[2], d[3],
                          ah[mt][0], ah[mt][1], ah[mt][2], ah[mt][3], bh[nt][0], bh[nt][1]);
                    mma16(d[0], d[1], d[2], d[3],
                          ah[mt][0], ah[mt][1], ah[mt][2], ah[mt][3], bl[nt][0], bl[nt][1]);
                    mma16(d[0], d[1], d[2], d[3],
                          al[mt][0], al[mt][1], al[mt][2], al[mt][3], bh[nt][0], bh[nt][1]);
                }
        }
        __syncthreads();
    }

    // epilogue: thread (r,c) owns rows {row, row+8}, cols {2c, 2c+1} per tile
    #pragma unroll
    for (int mt = 0; mt < 2; mt++) {
        const int row = m0 + wm * 32 + mt * 16 + r;
        #pragma unroll
        for (int nt = 0; nt < 4; nt++) {
            const int col = n0 + wn * 32 + nt * 8 + 2 * c;
            if (col < Nreal) {
                float v0 = acc[mt][nt][0], v1 = acc[mt][nt][1];
                float v2 = acc[mt][nt][2], v3 = acc[mt][nt][3];
                if (HAS_BIAS) {
                    float b0 = bias[col], b1 = bias[col + 1];
                    v0 += b0; v1 += b1; v2 += b0; v3 += b1;
                }
                if (SPLIT_OUT) {
                    __half h0 = __float2half_rn(v0), h1 = __float2half_rn(v1);
                    __half h2 = __float2half_rn(v2), h3 = __float2half_rn(v3);
                    *(half2*)&Hout[(size_t)row * Nreal + col]       = __halves2half2(h0, h1);
                    *(half2*)&Hout[(size_t)(row + 8) * Nreal + col] = __halves2half2(h2, h3);
                    *(half2*)&Lout[(size_t)row * Nreal + col] =
                        __halves2half2(__float2half_rn(v0 - __half2float(h0)),
                                       __float2half_rn(v1 - __half2float(h1)));
                    *(half2*)&Lout[(size_t)(row + 8) * Nreal + col] =
                        __halves2half2(__float2half_rn(v2 - __half2float(h2)),
                                       __float2half_rn(v3 - __half2float(h3)));
                } else {
                    *(float2*)&Cout[(size_t)row * Nreal + col]       = make_float2(v0, v1);
                    *(float2*)&Cout[(size_t)(row + 8) * Nreal + col] = make_float2(v2, v3);
                }
            }
        }
    }
}

// ---------------- elementwise split: float -> (hi, lo) fp16 pair -------------
__global__ void split4h_kernel(const float* __restrict__ x,
                               __half* __restrict__ hi, __half* __restrict__ lo, int n4)
{
    int i = blockIdx.x * blockDim.x + threadIdx.x;
    if (i >= n4) return;
    float4 v = ((const float4*)x)[i];
    __half h0 = __float2half_rn(v.x), h1 = __float2half_rn(v.y);
    __half h2 = __float2half_rn(v.z), h3 = __float2half_rn(v.w);
    half2 hA = __halves2half2(h0, h1), hB = __halves2half2(h2, h3);
    half2 lA = __halves2half2(__float2half_rn(v.x - __half2float(h0)),
                              __float2half_rn(v.y - __half2float(h1)));
    half2 lB = __halves2half2(__float2half_rn(v.z - __half2float(h2)),
                              __float2half_rn(v.w - __half2float(h3)));
    ((half2*)hi)[2*i]   = hA; ((half2*)hi)[2*i+1] = hB;
    ((half2*)lo)[2*i]   = lA; ((half2*)lo)[2*i+1] = lB;
}

// ---------------- transpose + split: W[K,N] -> Wt_hi/lo[Npad,K] fp16 ---------
__global__ void tsplit_kernel(const float* __restrict__ W,
                              __half* __restrict__ Thi, __half* __restrict__ Tlo,
                              int K, int N)
{
    __shared__ float t[32][33];
    const int n0 = blockIdx.x * 32, k0 = blockIdx.y * 32;
    const int tx = threadIdx.x, ty = threadIdx.y;   // 32 x 8
    #pragma unroll
    for (int r = 0; r < 4; r++) {
        int k = k0 + ty + r * 8, n = n0 + tx;
        t[ty + r * 8][tx] = (n < N) ? W[(size_t)k * N + n] : 0.f;
    }
    __syncthreads();
    #pragma unroll
    for (int r = 0; r < 4; r++) {
        int n = n0 + ty + r * 8, k = k0 + tx;
        float v = t[tx][ty + r * 8];
        __half h = __float2half_rn(v);
        Thi[(size_t)n * K + k] = h;
        Tlo[(size_t)n * K + k] = __float2half_rn(v - __half2float(h));
    }
}

// ---------------- dtmod + dt/softplus + dA ----------------
__global__ void dt_kernel(const float* __restrict__ dte,
                          const float* __restrict__ Wd,
                          const float* __restrict__ bd,
                          const float* __restrict__ zx,
                          const float* __restrict__ dt_bias,
                          const float* __restrict__ A_log)
{
    int idx = blockIdx.x * blockDim.x + threadIdx.x;   // ROWS*NH
    if (idx >= ROWS * NH) return;
    int h   = idx & (NH - 1);
    int row = idx >> 5;
    const float* d = dte + (size_t)row * DTIME;
    float s = bd[h];
    #pragma unroll 8
    for (int j = 0; j < DTIME; j++) s = fmaf(d[j], Wd[j*NH + h], s);
    float x  = zx[(size_t)row * DIP + (DI + CD) + h] + dt_bias[h] + s;
    float dt = (x > 20.f) ? x : log1pf(expf(x));
    float A  = -expf(A_log[h]);
    g_dt[idx] = dt;
    g_dA[idx] = expf(dt * A);
}

// ---------------- causal conv (taps=4) + bias + silu ----------------
__global__ void conv_kernel(const float* __restrict__ zx,
                            const float* __restrict__ conv_w,
                            const float* __restrict__ conv_b)
{
    int idx = blockIdx.x * blockDim.x + threadIdx.x;   // ROWS*CD
    if (idx >= ROWS * CD) return;
    int c   = idx % CD;
    int row = idx / CD;
    int l   = row & (L_SZ - 1);
    int b   = row / L_SZ;
    float acc = conv_b[c];
    #pragma unroll
    for (int k = 0; k < DCONV; k++) {
        int ll = l - (DCONV - 1) + k;
        if (ll >= 0)
            acc = fmaf(zx[(size_t)(b*L_SZ + ll) * DIP + DI + c], conv_w[k*CD + c], acc);
    }
    g_xBCa[idx] = acc / (1.f + expf(-acc));   // silu
}

// ---------------- scan phase A: per-chunk local scan from zero state ----------
__global__ void __launch_bounds__(256) scanA_kernel(const float* __restrict__ Dvec)
{
    const int c = blockIdx.x, h = blockIdx.y, b = blockIdx.z;
    const int t = threadIdx.x;
    __shared__ float xs[2][64], Bs[2][128], Cs[2][128], red[2][256];

    const int p = t & 63, g = t >> 6, n0 = g * 32;
    float s[32];
    #pragma unroll
    for (int j = 0; j < 32; j++) s[j] = 0.f;
    float cum = 1.f;
    const float Dh = Dvec[h];
    const int l0 = c * CL;
    const int bh = b * NH + h;

    for (int li = 0; li < CL; li++) {
        const int l = l0 + li, par = li & 1;
        const float* base = g_xBCa + (size_t)(b*L_SZ + l) * CD;
        for (int i = t; i < 320; i += 256) {
            if (i < 64)        xs[par][i]       = base[h*HD + i];
            else if (i < 192)  Bs[par][i - 64]  = base[DI + (i - 64)];
            else               Cs[par][i - 192] = base[DI + DS + (i - 192)];
        }
        float dtv = g_dt[(b*L_SZ + l)*NH + h];
        float dAv = g_dA[(b*L_SZ + l)*NH + h];
        __syncthreads();

        float coef = dtv * xs[par][p];
        float acc = 0.f;
        #pragma unroll
        for (int j = 0; j < 32; j++) {
            s[j] = fmaf(dAv, s[j], coef * Bs[par][n0 + j]);
            acc  = fmaf(s[j], Cs[par][n0 + j], acc);
        }
        red[par][t] = acc;
        cum *= dAv;
        __syncthreads();

        if (t < 64) {
            float y = red[par][t] + red[par][t+64] + red[par][t+128] + red[par][t+192]
                    + Dh * xs[par][t];
            g_y[(size_t)(b*L_SZ + l)*DI + h*HD + t] = y;
        }
        if (t == 0) g_cumdec[bh*L_SZ + l] = cum;
    }

    const size_t sbase = ((size_t)bh * NC + c) * (HD * DS);
    #pragma unroll
    for (int j = 0; j < 32; j++) g_Sfinal[sbase + p*DS + n0 + j] = s[j];
}

// ---------------- scan phase B: sequential chunk-state combine (tiny) --------
__global__ void phaseB_kernel()
{
    const int bh = blockIdx.x;
    const int t  = threadIdx.x;
    for (int e = t; e < HD * DS; e += 256) {
        float hv = 0.f;
        for (int c = 0; c < NC; c++) {
            const size_t o = ((size_t)bh * NC + c) * (HD * DS) + e;
            g_Hinit[o] = hv;
            float P = g_cumdec[bh*L_SZ + c*CL + CL - 1];
            hv = fmaf(P, hv, g_Sfinal[o]);
        }
    }
}

// ---------------- scan phase C: rank-correction y += cumdec * C^T h_init -----
__global__ void __launch_bounds__(256) phaseC_kernel()
{
    const int c = blockIdx.x;
    if (c == 0) return;               // zero initial state
    const int h = blockIdx.y, b = blockIdx.z;
    const int t = threadIdx.x;
    __shared__ float Hs[64 * 129];
    __shared__ float Cs[2][128], red[2][256];

    const int bh = b * NH + h;
    const size_t hbase = ((size_t)bh * NC + c) * (HD * DS);
    for (int i = t; i < HD * DS; i += 256)
        Hs[(i >> 7) * 129 + (i & 127)] = g_Hinit[hbase + i];

    const int p = t & 63, g = t >> 6, n0 = g * 32;
    const int l0 = c * CL;
    __syncthreads();

    for (int li = 0; li < CL; li++) {
        const int l = l0 + li, par = li & 1;
        const float* base = g_xBCa + (size_t)(b*L_SZ + l) * CD + DI + DS;
        if (t < 128) Cs[par][t] = base[t];
        float cd = g_cumdec[bh*L_SZ + l];
        __syncthreads();

        float acc = 0.f;
        #pragma unroll
        for (int j = 0; j < 32; j++)
            acc = fmaf(Hs[p*129 + n0 + j], Cs[par][n0 + j], acc);
        red[par][t] = acc;
        __syncthreads();

        if (t < 64)
            g_y[(size_t)(b*L_SZ + l)*DI + h*HD + t] +=
                cd * (red[par][t] + red[par][t+64] + red[par][t+128] + red[par][t+192]);
    }
}

// ---------------- gating (silu(z)) + RMS norm -> split fp16 pair -------------
__global__ void __launch_bounds__(256) epilogue_kernel(const float* __restrict__ norm_w)
{
    const int row = blockIdx.x;       // b*L + l
    const int t   = threadIdx.x;
    float gv[8];
    float ss = 0.f;
    #pragma unroll
    for (int i = 0; i < 8; i++) {
        int cidx = t + i * 256;
        float yv = g_y[(size_t)row * DI + cidx];
        float zv = g_zx[(size_t)row * DIP + cidx];
        float sil = zv / (1.f + expf(-zv));
        float v = yv * sil;
        gv[i] = v;
        ss += v * v;
    }
    __shared__ float rs[32];
    #pragma unroll
    for (int o = 16; o; o >>= 1) ss += __shfl_xor_sync(~0u, ss, o);
    if ((t & 31) == 0) rs[t >> 5] = ss;
    __syncthreads();
    if (t < 32) {
        float v = (t < 8) ? rs[t] : 0.f;
        #pragma unroll
        for (int o = 4; o; o >>= 1) v += __shfl_xor_sync(~0u, v, o);
        if (t == 0) rs[0] = v;
    }
    __syncthreads();
    float scale = rsqrtf(rs[0] / (float)DI + EPSV);
    #pragma unroll
    for (int i = 0; i < 8; i++) {
        int cidx = t + i * 256;
        float v = gv[i] * scale * norm_w[cidx];
        __half h = __float2half_rn(v);
        const size_t off = (size_t)row * DI + cidx;
        g_yhi[off] = h;
        g_ylo[off] = __float2half_rn(v - __half2float(h));
    }
}

// ---------------- launch ----------------
extern "C" void kernel_launch(void* const* d_in, const int* in_sizes, int n_in,
                              void* d_out, int out_size)
{
    const float* hidden  = (const float*)d_in[0];
    const float* dte     = (const float*)d_in[1];
    const float* W_proj  = (const float*)d_in[2];
    const float* b_proj  = (const float*)d_in[3];
    const float* W_dtmod = (const float*)d_in[4];
    const float* b_dtmod = (const float*)d_in[5];
    const float* W_in    = (const float*)d_in[6];
    const float* conv_w  = (const float*)d_in[7];
    const float* conv_b  = (const float*)d_in[8];
    const float* dt_bias = (const float*)d_in[9];
    const float* A_log   = (const float*)d_in[10];
    const float* Dvec    = (const float*)d_in[11];
    const float* norm_w  = (const float*)d_in[12];
    const float* W_out   = (const float*)d_in[13];
    float* out = (float*)d_out;

    float *p_zx;
    __half *p_uhi, *p_ulo, *p_yhi, *p_ylo, *p_hhi, *p_hlo;
    __half *p_wpt_hi, *p_wpt_lo, *p_wit_hi, *p_wit_lo, *p_wot_hi, *p_wot_lo;
    cudaGetSymbolAddress((void**)&p_uhi, g_uhi);
    cudaGetSymbolAddress((void**)&p_ulo, g_ulo);
    cudaGetSymbolAddress((void**)&p_zx,  g_zx);
    cudaGetSymbolAddress((void**)&p_yhi, g_yhi);
    cudaGetSymbolAddress((void**)&p_ylo, g_ylo);
    cudaGetSymbolAddress((void**)&p_hhi, g_hhi);
    cudaGetSymbolAddress((void**)&p_hlo, g_hlo);
    cudaGetSymbolAddress((void**)&p_wpt_hi, g_wpt_hi);
    cudaGetSymbolAddress((void**)&p_wpt_lo, g_wpt_lo);
    cudaGetSymbolAddress((void**)&p_wit_hi, g_wit_hi);
    cudaGetSymbolAddress((void**)&p_wit_lo, g_wit_lo);
    cudaGetSymbolAddress((void**)&p_wot_hi, g_wot_hi);
    cudaGetSymbolAddress((void**)&p_wot_lo, g_wot_lo);

    cudaFuncSetAttribute(gemm_h<true,  true >, cudaFuncAttributeMaxDynamicSharedMemorySize, GEMM_SMEM_BYTES);
    cudaFuncSetAttribute(gemm_h<false, false>, cudaFuncAttributeMaxDynamicSharedMemorySize, GEMM_SMEM_BYTES);

    // 0) operand prep: split hidden; transpose+split weights (fp16 hi/lo)
    split4h_kernel<<<(ROWS*DM/4 + 255)/256, 256>>>(hidden, p_hhi, p_hlo, ROWS*DM/4);
    tsplit_kernel<<<dim3(DM/32,  DM/32), dim3(32,8)>>>(W_proj, p_wpt_hi, p_wpt_lo, DM, DM);
    tsplit_kernel<<<dim3(DIPPAD/32, DM/32), dim3(32,8)>>>(W_in,  p_wit_hi, p_wit_lo, DM, DIP);
    tsplit_kernel<<<dim3(DM/32,  DI/32), dim3(32,8)>>>(W_out, p_wot_hi, p_wot_lo, DI, DM);

    // 1) u = hidden @ W_proj + b_proj   (outputs split u directly)
    gemm_h<true, true><<<dim3(DM/128, ROWS/128), 512, GEMM_SMEM_BYTES>>>(
        p_hhi, p_hlo, p_wpt_hi, p_wpt_lo, b_proj, nullptr, p_uhi, p_ulo, ROWS, DM, DM);

    // 2) zxbcdt = u @ W_in
    gemm_h<false, false><<<dim3(DIPPAD/128, ROWS/128), 512, GEMM_SMEM_BYTES>>>(
        p_uhi, p_ulo, p_wit_hi, p_wit_lo, nullptr, p_zx, nullptr, nullptr, ROWS, DIP, DM);

    // 3) dt = softplus(dt_raw + dt_bias + dte@W_dtmod + b_dtmod); dA = exp(dt*A)
    dt_kernel<<<(ROWS*NH + 255)/256, 256>>>(dte, W_dtmod, b_dtmod, p_zx, dt_bias, A_log);

    // 4) xBC = silu(causal_conv(xBC) + conv_b)
    conv_kernel<<<(ROWS*CD + 255)/256, 256>>>(p_zx, conv_w, conv_b);

    // 5) chunked selective scan
    scanA_kernel<<<dim3(NC, NH, B_SZ), 256>>>(Dvec);
    phaseB_kernel<<<B_SZ*NH, 256>>>();
    phaseC_kernel<<<dim3(NC, NH, B_SZ), 256>>>();

    // 6) gating + RMS norm (writes split y)
    epilogue_kernel<<<ROWS, 256>>>(norm_w);

    // 7) out = yn @ W_out
    gemm_h<false, false><<<dim3(DM/128, ROWS/128), 512, GEMM_SMEM_BYTES>>>(
        p_yhi, p_ylo, p_wot_hi, p_wot_lo, nullptr, out, nullptr, nullptr, ROWS, DM, DI);
}

// round 6
// speedup vs baseline: 1.9348x; 1.2041x over previous
#include <cuda_runtime.h>
#include <cuda_fp16.h>
#include <cuda_bf16.h>
#include <cstdint>

// ---------------- problem constants ----------------
#define B_SZ   2
#define L_SZ   2048
#define DM     1024      // d_model
#define DI     2048      // d_inner
#define DS     128       // d_state
#define DCONV  4
#define NH     32        // nheads
#define HD     64        // headdim
#define DTIME  64
#define CD     (DI + 2*DS)            // 2304 conv dim
#define DIP    (2*DI + 2*DS + NH)     // 4384 in-proj dim
#define DIPPAD 4480                   // 35*128
#define ROWS   (B_SZ*L_SZ)            // 4096
#define NC     16                     // scan chunks
#define CL     (L_SZ/NC)              // 128 chunk len
#define EPSV   1e-5f

// ---------------- scratch (device globals; no allocs allowed) ----------------
__device__ __half g_uhi[ROWS*DM], g_ulo[ROWS*DM];
__device__ float  g_zx[ROWS*DIP];
__device__ float  g_xBCa[ROWS*CD];
__device__ float  g_dt[ROWS*NH];
__device__ float  g_dA[ROWS*NH];
__device__ float  g_cumdec[B_SZ*NH*L_SZ];
__device__ float  g_Sfinal[B_SZ*NH*NC*HD*DS];
__device__ float  g_Hinit [B_SZ*NH*NC*HD*DS];
__device__ float  g_y[ROWS*DI];
__device__ __half g_yhi[ROWS*DI], g_ylo[ROWS*DI];
__device__ __half g_hhi[ROWS*DM], g_hlo[ROWS*DM];
__device__ __half g_wpt_hi[DM*DM],     g_wpt_lo[DM*DM];      // W_proj^T  [1024][1024]
__device__ __half g_wit_hi[DIPPAD*DM], g_wit_lo[DIPPAD*DM];  // W_in^T    [4480][1024]
__device__ __half g_wot_hi[DM*DI],     g_wot_lo[DM*DI];      // W_out^T   [1024][2048]

// ---------------- mma / ldmatrix helpers ----------------
__device__ __forceinline__ void mma16(float& d0, float& d1, float& d2, float& d3,
                                      uint32_t a0, uint32_t a1, uint32_t a2, uint32_t a3,
                                      uint32_t b0, uint32_t b1)
{
    asm volatile("mma.sync.aligned.m16n8k16.row.col.f32.f16.f16.f32 "
        "{%0,%1,%2,%3},{%4,%5,%6,%7},{%8,%9},{%0,%1,%2,%3};"
        : "+f"(d0), "+f"(d1), "+f"(d2), "+f"(d3)
        : "r"(a0), "r"(a1), "r"(a2), "r"(a3), "r"(b0), "r"(b1));
}
#define LDSM4(r0,r1,r2,r3, addr) \
    asm volatile("ldmatrix.sync.aligned.m8n8.x4.shared.b16 {%0,%1,%2,%3}, [%4];" \
        : "=r"(r0), "=r"(r1), "=r"(r2), "=r"(r3) : "r"(addr))

// smem geometry: rows of 64 halfs padded to 72 (144B stride; 8-row groups bank-disjoint)
#define HSTRIDE 72
#define TBYTES  (128 * HSTRIDE * 2)       // 18432 bytes per tensor per stage
#define STAGEB  (4 * TBYTES)              // Ahi,Alo,Bhi,Blo = 73728
#define GEMM_SMEM_BYTES (2 * STAGEB)      // 147456

// ---------------- split-FP16 GEMM via mma.sync m16n8k16 ----------------------
// C = (Ahi+Alo)[M,K] @ (Bhi[+Blo])^T, Bt stored [Npad,K] K-major halves.
// 2 passes: AhiBhi + AloBhi; tiles with n0 >= p3n0 also do AhiBlo (3-pass).
// grid=(Npad/128, M/128), 512 threads = 16 warps (4x4), warp tile 32x32, K-step 64.
template<bool HAS_BIAS, bool SPLIT_OUT>
__global__ void __launch_bounds__(512, 1) gemm_h(
    const __half* __restrict__ Ahi, const __half* __restrict__ Alo,
    const __half* __restrict__ Bhi, const __half* __restrict__ Blo,
    const float* __restrict__ bias,
    float* __restrict__ Cout, __half* __restrict__ Hout, __half* __restrict__ Lout,
    int M, int Nreal, int K, int p3n0)
{
    extern __shared__ __align__(16) char smem[];
    const uint32_t sb = (uint32_t)__cvta_generic_to_shared(smem);
    const int tid = threadIdx.x;
    const int wid = tid >> 5;
    const int lane = tid & 31;
    const int wm = wid & 3;           // warp row (4)
    const int wn = wid >> 2;          // warp col (4)
    const int r = lane >> 2;          // 0..7
    const int c = lane & 3;           // 0..3
    const int m0 = blockIdx.y << 7;
    const int n0 = blockIdx.x << 7;
    const int nsteps = K >> 6;
    const bool p3 = (n0 >= p3n0);     // third pass (AhiBlo) for sensitive tiles

    // loader role: 128 threads per tensor {Ahi,Alo,Bhi,Blo}
    const int t4   = tid >> 7;
    const int l128 = tid & 127;
    const __half* gsel = (t4 == 0) ? Ahi : (t4 == 1) ? Alo : (t4 == 2) ? Bhi : Blo;
    const int rb = (t4 < 2) ? m0 : n0;
    const bool do_load = (t4 < 3) || p3;   // skip Blo when 2-pass

    auto load_stage = [&](int kstep, int s) {
        if (do_load) {
            const int k0 = kstep << 6;
            const __half* gb = gsel + (size_t)rb * K + k0;
            const uint32_t tb = sb + (uint32_t)(s * STAGEB + t4 * TBYTES);
            #pragma unroll
            for (int j = 0; j < 8; j++) {
                int q = j * 128 + l128;           // 1024 chunks of 16B
                int row = q >> 3, col = q & 7;
                const __half* gp = gb + (size_t)row * K + (col << 3);
                uint32_t sa = tb + (uint32_t)(row * (HSTRIDE * 2) + (col << 4));
                asm volatile("cp.async.cg.shared.global [%0], [%1], 16;" :: "r"(sa), "l"(gp) : "memory");
            }
        }
        asm volatile("cp.async.commit_group;" ::: "memory");
    };

    float acc[2][4][4];
    #pragma unroll
    for (int i = 0; i < 2; i++)
        #pragma unroll
        for (int j = 0; j < 4; j++)
            #pragma unroll
            for (int q = 0; q < 4; q++) acc[i][j][q] = 0.f;

    // ldmatrix per-thread row offsets
    const int lrow = lane & 15;
    const int lk16 = (lane >> 4) << 4;  // 0 or 16 bytes (8 halves)
    uint32_t arow_off[2], brow_off[2];
    #pragma unroll
    for (int mt = 0; mt < 2; mt++)
        arow_off[mt] = (uint32_t)((wm * 32 + mt * 16 + lrow) * (HSTRIDE * 2)) + (uint32_t)lk16;
    #pragma unroll
    for (int g = 0; g < 2; g++)
        brow_off[g] = (uint32_t)((wn * 32 + g * 16 + lrow) * (HSTRIDE * 2)) + (uint32_t)lk16;

    load_stage(0, 0);

    for (int i = 0; i < nsteps; i++) {
        if (i + 1 < nsteps) {
            load_stage(i + 1, (i + 1) & 1);
            asm volatile("cp.async.wait_group 1;" ::: "memory");
        } else {
            asm volatile("cp.async.wait_group 0;" ::: "memory");
        }
        __syncthreads();

        const int s = i & 1;
        const uint32_t stA_hi = sb + (uint32_t)(s * STAGEB);
        const uint32_t stA_lo = stA_hi + TBYTES;
        const uint32_t stB_hi = stA_hi + 2 * TBYTES;
        const uint32_t stB_lo = stA_hi + 3 * TBYTES;

        #pragma unroll
        for (int kb = 0; kb < 4; kb++) {
            const uint32_t koff = (uint32_t)(kb << 5);   // kb*16 halves = 32 bytes
            uint32_t ah[2][4], al[2][4], bh[4][2];
            #pragma unroll
            for (int mt = 0; mt < 2; mt++) {
                LDSM4(ah[mt][0], ah[mt][1], ah[mt][2], ah[mt][3], stA_hi + arow_off[mt] + koff);
                LDSM4(al[mt][0], al[mt][1], al[mt][2], al[mt][3], stA_lo + arow_off[mt] + koff);
            }
            #pragma unroll
            for (int g = 0; g < 2; g++) {
                uint32_t r0, r1, r2, r3;
                LDSM4(r0, r1, r2, r3, stB_hi + brow_off[g] + koff);
                bh[2*g][0] = r0; bh[2*g+1][0] = r1; bh[2*g][1] = r2; bh[2*g+1][1] = r3;
            }
            #pragma unroll
            for (int mt = 0; mt < 2; mt++)
                #pragma unroll
                for (int nt = 0; nt < 4; nt++) {
                    float* d = acc[mt][nt];
                    mma16(d[0], d[1], d[2], d[3],
                          ah[mt][0], ah[mt][1], ah[mt][2], ah[mt][3], bh[nt][0], bh[nt][1]);
                    mma16(d[0], d[1], d[2], d[3],
                          al[mt][0], al[mt][1], al[mt][2], al[mt][3], bh[nt][0], bh[nt][1]);
                }
            if (p3) {
                uint32_t bl[4][2];
                #pragma unroll
                for (int g = 0; g < 2; g++) {
                    uint32_t r0, r1, r2, r3;
                    LDSM4(r0, r1, r2, r3, stB_lo + brow_off[g] + koff);
                    bl[2*g][0] = r0; bl[2*g+1][0] = r1; bl[2*g][1] = r2; bl[2*g+1][1] = r3;
                }
                #pragma unroll
                for (int mt = 0; mt < 2; mt++)
                    #pragma unroll
                    for (int nt = 0; nt < 4; nt++) {
                        float* d = acc[mt][nt];
                        mma16(d[0], d[1], d[2], d[3],
                              ah[mt][0], ah[mt][1], ah[mt][2], ah[mt][3], bl[nt][0], bl[nt][1]);
                    }
            }
        }
        __syncthreads();
    }

    // epilogue: thread (r,c) owns rows {row, row+8}, cols {2c, 2c+1} per tile
    #pragma unroll
    for (int mt = 0; mt < 2; mt++) {
        const int row = m0 + wm * 32 + mt * 16 + r;
        #pragma unroll
        for (int nt = 0; nt < 4; nt++) {
            const int col = n0 + wn * 32 + nt * 8 + 2 * c;
            if (col < Nreal) {
                float v0 = acc[mt][nt][0], v1 = acc[mt][nt][1];
                float v2 = acc[mt][nt][2], v3 = acc[mt][nt][3];
                if (HAS_BIAS) {
                    float b0 = bias[col], b1 = bias[col + 1];
                    v0 += b0; v1 += b1; v2 += b0; v3 += b1;
                }
                if (SPLIT_OUT) {
                    __half h0 = __float2half_rn(v0), h1 = __float2half_rn(v1);
                    __half h2 = __float2half_rn(v2), h3 = __float2half_rn(v3);
                    *(half2*)&Hout[(size_t)row * Nreal + col]       = __halves2half2(h0, h1);
                    *(half2*)&Hout[(size_t)(row + 8) * Nreal + col] = __halves2half2(h2, h3);
                    *(half2*)&Lout[(size_t)row * Nreal + col] =
                        __halves2half2(__float2half_rn(v0 - __half2float(h0)),
                                       __float2half_rn(v1 - __half2float(h1)));
                    *(half2*)&Lout[(size_t)(row + 8) * Nreal + col] =
                        __halves2half2(__float2half_rn(v2 - __half2float(h2)),
                                       __float2half_rn(v3 - __half2float(h3)));
                } else {
                    *(float2*)&Cout[(size_t)row * Nreal + col]       = make_float2(v0, v1);
                    *(float2*)&Cout[(size_t)(row + 8) * Nreal + col] = make_float2(v2, v3);
                }
            }
        }
    }
}

// ---------------- elementwise split: float -> (hi, lo) fp16 pair -------------
__global__ void split4h_kernel(const float* __restrict__ x,
                               __half* __restrict__ hi, __half* __restrict__ lo, int n4)
{
    int i = blockIdx.x * blockDim.x + threadIdx.x;
    if (i >= n4) return;
    float4 v = ((const float4*)x)[i];
    __half h0 = __float2half_rn(v.x), h1 = __float2half_rn(v.y);
    __half h2 = __float2half_rn(v.z), h3 = __float2half_rn(v.w);
    half2 hA = __halves2half2(h0, h1), hB = __halves2half2(h2, h3);
    half2 lA = __halves2half2(__float2half_rn(v.x - __half2float(h0)),
                              __float2half_rn(v.y - __half2float(h1)));
    half2 lB = __halves2half2(__float2half_rn(v.z - __half2float(h2)),
                              __float2half_rn(v.w - __half2float(h3)));
    ((half2*)hi)[2*i]   = hA; ((half2*)hi)[2*i+1] = hB;
    ((half2*)lo)[2*i]   = lA; ((half2*)lo)[2*i+1] = lB;
}

// ---------------- transpose + split: W[K,N] -> Wt_hi/lo[Npad,K] fp16 ---------
__global__ void tsplit_kernel(const float* __restrict__ W,
                              __half* __restrict__ Thi, __half* __restrict__ Tlo,
                              int K, int N)
{
    __shared__ float t[32][33];
    const int n0 = blockIdx.x * 32, k0 = blockIdx.y * 32;
    const int tx = threadIdx.x, ty = threadIdx.y;   // 32 x 8
    #pragma unroll
    for (int r = 0; r < 4; r++) {
        int k = k0 + ty + r * 8, n = n0 + tx;
        t[ty + r * 8][tx] = (n < N) ? W[(size_t)k * N + n] : 0.f;
    }
    __syncthreads();
    #pragma unroll
    for (int r = 0; r < 4; r++) {
        int n = n0 + ty + r * 8, k = k0 + tx;
        float v = t[tx][ty + r * 8];
        __half h = __float2half_rn(v);
        Thi[(size_t)n * K + k] = h;
        Tlo[(size_t)n * K + k] = __float2half_rn(v - __half2float(h));
    }
}

// ---------------- dtmod + dt/softplus + dA ----------------
__global__ void dt_kernel(const float* __restrict__ dte,
                          const float* __restrict__ Wd,
                          const float* __restrict__ bd,
                          const float* __restrict__ zx,
                          const float* __restrict__ dt_bias,
                          const float* __restrict__ A_log)
{
    int idx = blockIdx.x * blockDim.x + threadIdx.x;   // ROWS*NH
    if (idx >= ROWS * NH) return;
    int h   = idx & (NH - 1);
    int row = idx >> 5;
    const float* d = dte + (size_t)row * DTIME;
    float s = bd[h];
    #pragma unroll 8
    for (int j = 0; j < DTIME; j++) s = fmaf(d[j], Wd[j*NH + h], s);
    float x  = zx[(size_t)row * DIP + (DI + CD) + h] + dt_bias[h] + s;
    float dt = (x > 20.f) ? x : log1pf(expf(x));
    float A  = -expf(A_log[h]);
    g_dt[idx] = dt;
    g_dA[idx] = expf(dt * A);
}

// ---------------- causal conv (taps=4) + bias + silu ----------------
__global__ void conv_kernel(const float* __restrict__ zx,
                            const float* __restrict__ conv_w,
                            const float* __restrict__ conv_b)
{
    int idx = blockIdx.x * blockDim.x + threadIdx.x;   // ROWS*CD
    if (idx >= ROWS * CD) return;
    int c   = idx % CD;
    int row = idx / CD;
    int l   = row & (L_SZ - 1);
    int b   = row / L_SZ;
    float acc = conv_b[c];
    #pragma unroll
    for (int k = 0; k < DCONV; k++) {
        int ll = l - (DCONV - 1) + k;
        if (ll >= 0)
            acc = fmaf(zx[(size_t)(b*L_SZ + ll) * DIP + DI + c], conv_w[k*CD + c], acc);
    }
    g_xBCa[idx] = acc / (1.f + expf(-acc));   // silu
}

// ---------------- scan phase A: per-chunk local scan from zero state ----------
__global__ void __launch_bounds__(256) scanA_kernel(const float* __restrict__ Dvec)
{
    const int c = blockIdx.x, h = blockIdx.y, b = blockIdx.z;
    const int t = threadIdx.x;
    __shared__ float xs[2][64], Bs[2][128], Cs[2][128], red[2][256];

    const int p = t & 63, g = t >> 6, n0 = g * 32;
    float s[32];
    #pragma unroll
    for (int j = 0; j < 32; j++) s[j] = 0.f;
    float cum = 1.f;
    const float Dh = Dvec[h];
    const int l0 = c * CL;
    const int bh = b * NH + h;

    for (int li = 0; li < CL; li++) {
        const int l = l0 + li, par = li & 1;
        const float* base = g_xBCa + (size_t)(b*L_SZ + l) * CD;
        for (int i = t; i < 320; i += 256) {
            if (i < 64)        xs[par][i]       = base[h*HD + i];
            else if (i < 192)  Bs[par][i - 64]  = base[DI + (i - 64)];
            else               Cs[par][i - 192] = base[DI + DS + (i - 192)];
        }
        float dtv = g_dt[(b*L_SZ + l)*NH + h];
        float dAv = g_dA[(b*L_SZ + l)*NH + h];
        __syncthreads();

        float coef = dtv * xs[par][p];
        float acc = 0.f;
        #pragma unroll
        for (int j = 0; j < 32; j++) {
            s[j] = fmaf(dAv, s[j], coef * Bs[par][n0 + j]);
            acc  = fmaf(s[j], Cs[par][n0 + j], acc);
        }
        red[par][t] = acc;
        cum *= dAv;
        __syncthreads();

        if (t < 64) {
            float y = red[par][t] + red[par][t+64] + red[par][t+128] + red[par][t+192]
                    + Dh * xs[par][t];
            g_y[(size_t)(b*L_SZ + l)*DI + h*HD + t] = y;
        }
        if (t == 0) g_cumdec[bh*L_SZ + l] = cum;
    }

    const size_t sbase = ((size_t)bh * NC + c) * (HD * DS);
    #pragma unroll
    for (int j = 0; j < 32; j++) g_Sfinal[sbase + p*DS + n0 + j] = s[j];
}

// ---------------- scan phase B: sequential chunk-state combine ---------------
// grid = (B*NH, 8): each block handles 1024 of the 8192 state elements.
__global__ void phaseB_kernel()
{
    const int bh = blockIdx.x;
    const int e0 = blockIdx.y * 1024;
    const int t  = threadIdx.x;
    for (int e = e0 + t; e < e0 + 1024; e += 256) {
        float hv = 0.f;
        for (int c = 0; c < NC; c++) {
            const size_t o = ((size_t)bh * NC + c) * (HD * DS) + e;
            g_Hinit[o] = hv;
            float P = g_cumdec[bh*L_SZ + c*CL + CL - 1];
            hv = fmaf(P, hv, g_Sfinal[o]);
        }
    }
}

// ---------------- scan phase C: rank-correction y += cumdec * C^T h_init -----
__global__ void __launch_bounds__(256) phaseC_kernel()
{
    const int c = blockIdx.x;
    if (c == 0) return;               // zero initial state
    const int h = blockIdx.y, b = blockIdx.z;
    const int t = threadIdx.x;
    __shared__ float Hs[64 * 129];
    __shared__ float Cs[2][128], red[2][256];

    const int bh = b * NH + h;
    const size_t hbase = ((size_t)bh * NC + c) * (HD * DS);
    for (int i = t; i < HD * DS; i += 256)
        Hs[(i >> 7) * 129 + (i & 127)] = g_Hinit[hbase + i];

    const int p = t & 63, g = t >> 6, n0 = g * 32;
    const int l0 = c * CL;
    __syncthreads();

    for (int li = 0; li < CL; li++) {
        const int l = l0 + li, par = li & 1;
        const float* base = g_xBCa + (size_t)(b*L_SZ + l) * CD + DI + DS;
        if (t < 128) Cs[par][t] = base[t];
        float cd = g_cumdec[bh*L_SZ + l];
        __syncthreads();

        float acc = 0.f;
        #pragma unroll
        for (int j = 0; j < 32; j++)
            acc = fmaf(Hs[p*129 + n0 + j], Cs[par][n0 + j], acc);
        red[par][t] = acc;
        __syncthreads();

        if (t < 64)
            g_y[(size_t)(b*L_SZ + l)*DI + h*HD + t] +=
                cd * (red[par][t] + red[par][t+64] + red[par][t+128] + red[par][t+192]);
    }
}

// ---------------- gating (silu(z)) + RMS norm -> split fp16 pair -------------
__global__ void __launch_bounds__(256) epilogue_kernel(const float* __restrict__ norm_w)
{
    const int row = blockIdx.x;       // b*L + l
    const int t   = threadIdx.x;
    float gv[8];
    float ss = 0.f;
    #pragma unroll
    for (int i = 0; i < 8; i++) {
        int cidx = t + i * 256;
        float yv = g_y[(size_t)row * DI + cidx];
        float zv = g_zx[(size_t)row * DIP + cidx];
        float sil = zv / (1.f + expf(-zv));
        float v = yv * sil;
        gv[i] = v;
        ss += v * v;
    }
    __shared__ float rs[32];
    #pragma unroll
    for (int o = 16; o; o >>= 1) ss += __shfl_xor_sync(~0u, ss, o);
    if ((t & 31) == 0) rs[t >> 5] = ss;
    __syncthreads();
    if (t < 32) {
        float v = (t < 8) ? rs[t] : 0.f;
        #pragma unroll
        for (int o = 4; o; o >>= 1) v += __shfl_xor_sync(~0u, v, o);
        if (t == 0) rs[0] = v;
    }
    __syncthreads();
    float scale = rsqrtf(rs[0] / (float)DI + EPSV);
    #pragma unroll
    for (int i = 0; i < 8; i++) {
        int cidx = t + i * 256;
        float v = gv[i] * scale * norm_w[cidx];
        __half h = __float2half_rn(v);
        const size_t off = (size_t)row * DI + cidx;
        g_yhi[off] = h;
        g_ylo[off] = __float2half_rn(v - __half2float(h));
    }
}

// ---------------- launch ----------------
extern "C" void kernel_launch(void* const* d_in, const int* in_sizes, int n_in,
                              void* d_out, int out_size)
{
    const float* hidden  = (const float*)d_in[0];
    const float* dte     = (const float*)d_in[1];
    const float* W_proj  = (const float*)d_in[2];
    const float* b_proj  = (const float*)d_in[3];
    const float* W_dtmod = (const float*)d_in[4];
    const float* b_dtmod = (const float*)d_in[5];
    const float* W_in    = (const float*)d_in[6];
    const float* conv_w  = (const float*)d_in[7];
    const float* conv_b  = (const float*)d_in[8];
    const float* dt_bias = (const float*)d_in[9];
    const float* A_log   = (const float*)d_in[10];
    const float* Dvec    = (const float*)d_in[11];
    const float* norm_w  = (const float*)d_in[12];
    const float* W_out   = (const float*)d_in[13];
    float* out = (float*)d_out;

    float *p_zx;
    __half *p_uhi, *p_ulo, *p_yhi, *p_ylo, *p_hhi, *p_hlo;
    __half *p_wpt_hi, *p_wpt_lo, *p_wit_hi, *p_wit_lo, *p_wot_hi, *p_wot_lo;
    cudaGetSymbolAddress((void**)&p_uhi, g_uhi);
    cudaGetSymbolAddress((void**)&p_ulo, g_ulo);
    cudaGetSymbolAddress((void**)&p_zx,  g_zx);
    cudaGetSymbolAddress((void**)&p_yhi, g_yhi);
    cudaGetSymbolAddress((void**)&p_ylo, g_ylo);
    cudaGetSymbolAddress((void**)&p_hhi, g_hhi);
    cudaGetSymbolAddress((void**)&p_hlo, g_hlo);
    cudaGetSymbolAddress((void**)&p_wpt_hi, g_wpt_hi);
    cudaGetSymbolAddress((void**)&p_wpt_lo, g_wpt_lo);
    cudaGetSymbolAddress((void**)&p_wit_hi, g_wit_hi);
    cudaGetSymbolAddress((void**)&p_wit_lo, g_wit_lo);
    cudaGetSymbolAddress((void**)&p_wot_hi, g_wot_hi);
    cudaGetSymbolAddress((void**)&p_wot_lo, g_wot_lo);

    cudaFuncSetAttribute(gemm_h<true,  true >, cudaFuncAttributeMaxDynamicSharedMemorySize, GEMM_SMEM_BYTES);
    cudaFuncSetAttribute(gemm_h<false, false>, cudaFuncAttributeMaxDynamicSharedMemorySize, GEMM_SMEM_BYTES);

    // 0) operand prep: split hidden; transpose+split weights (fp16 hi/lo)
    split4h_kernel<<<(ROWS*DM/4 + 255)/256, 256>>>(hidden, p_hhi, p_hlo, ROWS*DM/4);
    tsplit_kernel<<<dim3(DM/32,  DM/32), dim3(32,8)>>>(W_proj, p_wpt_hi, p_wpt_lo, DM, DM);
    tsplit_kernel<<<dim3(DIPPAD/32, DM/32), dim3(32,8)>>>(W_in,  p_wit_hi, p_wit_lo, DM, DIP);
    tsplit_kernel<<<dim3(DM/32,  DI/32), dim3(32,8)>>>(W_out, p_wot_hi, p_wot_lo, DI, DM);

    // 1) u = hidden @ W_proj + b_proj   (3-pass everywhere: feeds dt path)
    gemm_h<true, true><<<dim3(DM/128, ROWS/128), 512, GEMM_SMEM_BYTES>>>(
        p_hhi, p_hlo, p_wpt_hi, p_wpt_lo, b_proj, nullptr, p_uhi, p_ulo, ROWS, DM, DM, 0);

    // 2) zxbcdt = u @ W_in   (2-pass; 3-pass only on the dt_raw tile n0>=4352)
    gemm_h<false, false><<<dim3(DIPPAD/128, ROWS/128), 512, GEMM_SMEM_BYTES>>>(
        p_uhi, p_ulo, p_wit_hi, p_wit_lo, nullptr, p_zx, nullptr, nullptr, ROWS, DIP, DM, DI + CD);

    // 3) dt = softplus(dt_raw + dt_bias + dte@W_dtmod + b_dtmod); dA = exp(dt*A)
    dt_kernel<<<(ROWS*NH + 255)/256, 256>>>(dte, W_dtmod, b_dtmod, p_zx, dt_bias, A_log);

    // 4) xBC = silu(causal_conv(xBC) + conv_b)
    conv_kernel<<<(ROWS*CD + 255)/256, 256>>>(p_zx, conv_w, conv_b);

    // 5) chunked selective scan
    scanA_kernel<<<dim3(NC, NH, B_SZ), 256>>>(Dvec);
    phaseB_kernel<<<dim3(B_SZ*NH, 8), 256>>>();
    phaseC_kernel<<<dim3(NC, NH, B_SZ), 256>>>();

    // 6) gating + RMS norm (writes split y)
    epilogue_kernel<<<ROWS, 256>>>(norm_w);

    // 7) out = yn @ W_out   (2-pass)
    gemm_h<false, false><<<dim3(DM/128, ROWS/128), 512, GEMM_SMEM_BYTES>>>(
        p_yhi, p_ylo, p_wot_hi, p_wot_lo, nullptr, out, nullptr, nullptr, ROWS, DM, DI, 1 << 30);
}

// round 7
// speedup vs baseline: 1.9781x; 1.0224x over previous
#include <cuda_runtime.h>
#include <cuda_fp16.h>
#include <cuda_bf16.h>
#include <cstdint>

// ---------------- problem constants ----------------
#define B_SZ   2
#define L_SZ   2048
#define DM     1024      // d_model
#define DI     2048      // d_inner
#define DS     128       // d_state
#define DCONV  4
#define NH     32        // nheads
#define HD     64        // headdim
#define DTIME  64
#define CD     (DI + 2*DS)            // 2304 conv dim
#define DIP    (2*DI + 2*DS + NH)     // 4384 in-proj dim
#define DIPPAD 4480                   // 35*128
#define NGEMM2 4352                   // 34*128 = DI+CD (z,xBC cols only)
#define ROWS   (B_SZ*L_SZ)            // 4096
#define NC     16                     // scan chunks
#define CL     (L_SZ/NC)              // 128 chunk len
#define EPSV   1e-5f

// ---------------- scratch (device globals; no allocs allowed) ----------------
__device__ __half g_uhi[ROWS*DM], g_ulo[ROWS*DM];
__device__ float  g_zx[ROWS*DIP];
__device__ float  g_xBCa[ROWS*CD];
__device__ float  g_dt[ROWS*NH];
__device__ float  g_dA[ROWS*NH];
__device__ float  g_cumdec[B_SZ*NH*L_SZ];
__device__ float  g_Sfinal[B_SZ*NH*NC*HD*DS];
__device__ float  g_Hinit [B_SZ*NH*NC*HD*DS];
__device__ float  g_y[ROWS*DI];
__device__ __half g_yhi[ROWS*DI], g_ylo[ROWS*DI];
__device__ __half g_hhi[ROWS*DM], g_hlo[ROWS*DM];
__device__ __half g_wpt_hi[DM*DM], g_wpt_lo[DM*DM];   // W_proj^T  [1024][1024]
__device__ __half g_wit_hi[DIPPAD*DM];                // W_in^T    [4480][1024] (hi only)
__device__ __half g_wot_hi[DM*DI];                    // W_out^T   [1024][2048] (hi only)

// ---------------- mma / ldmatrix helpers ----------------
__device__ __forceinline__ void mma16(float& d0, float& d1, float& d2, float& d3,
                                      uint32_t a0, uint32_t a1, uint32_t a2, uint32_t a3,
                                      uint32_t b0, uint32_t b1)
{
    asm volatile("mma.sync.aligned.m16n8k16.row.col.f32.f16.f16.f32 "
        "{%0,%1,%2,%3},{%4,%5,%6,%7},{%8,%9},{%0,%1,%2,%3};"
        : "+f"(d0), "+f"(d1), "+f"(d2), "+f"(d3)
        : "r"(a0), "r"(a1), "r"(a2), "r"(a3), "r"(b0), "r"(b1));
}
#define LDSM4(r0,r1,r2,r3, addr) \
    asm volatile("ldmatrix.sync.aligned.m8n8.x4.shared.b16 {%0,%1,%2,%3}, [%4];" \
        : "=r"(r0), "=r"(r1), "=r"(r2), "=r"(r3) : "r"(addr))

// smem geometry: rows of 64 halfs padded to 72 (144B stride; 8-row groups bank-disjoint)
#define HSTRIDE 72
#define TBYTES  (128 * HSTRIDE * 2)       // 18432 bytes per tensor per stage
#define STAGEB3 (4 * TBYTES)              // Ahi,Alo,Bhi,Blo = 73728  (3-pass variant)
#define SMEM3P  (2 * STAGEB3)             // 147456
#define STAGEB2 (3 * TBYTES)              // Ahi,Alo,Bhi = 55296      (2-pass variant)
#define SMEM2P  (2 * STAGEB2)             // 110592  -> 2 CTAs/SM

// ============ 3-pass split-FP16 GEMM (GEMM1 only; 4 tensors, 1 CTA/SM) =======
// C = (Ahi+Alo)[M,N] with AhiBhi + AloBhi + AhiBlo; split fp16 output + bias.
__global__ void __launch_bounds__(512, 1) gemm_h3(
    const __half* __restrict__ Ahi, const __half* __restrict__ Alo,
    const __half* __restrict__ Bhi, const __half* __restrict__ Blo,
    const float* __restrict__ bias,
    __half* __restrict__ Hout, __half* __restrict__ Lout,
    int M, int Nreal, int K)
{
    extern __shared__ __align__(16) char smem[];
    const uint32_t sb = (uint32_t)__cvta_generic_to_shared(smem);
    const int tid = threadIdx.x;
    const int wid = tid >> 5;
    const int lane = tid & 31;
    const int wm = wid & 3;           // warp row (4)
    const int wn = wid >> 2;          // warp col (4)
    const int r = lane >> 2;
    const int c = lane & 3;
    const int m0 = blockIdx.y << 7;
    const int n0 = blockIdx.x << 7;
    const int nsteps = K >> 6;

    const int t4   = tid >> 7;
    const int l128 = tid & 127;
    const __half* gsel = (t4 == 0) ? Ahi : (t4 == 1) ? Alo : (t4 == 2) ? Bhi : Blo;
    const int rb = (t4 < 2) ? m0 : n0;

    auto load_stage = [&](int kstep, int s) {
        const int k0 = kstep << 6;
        const __half* gb = gsel + (size_t)rb * K + k0;
        const uint32_t tb = sb + (uint32_t)(s * STAGEB3 + t4 * TBYTES);
        #pragma unroll
        for (int j = 0; j < 8; j++) {
            int q = j * 128 + l128;
            int row = q >> 3, col = q & 7;
            const __half* gp = gb + (size_t)row * K + (col << 3);
            uint32_t sa = tb + (uint32_t)(row * (HSTRIDE * 2) + (col << 4));
            asm volatile("cp.async.cg.shared.global [%0], [%1], 16;" :: "r"(sa), "l"(gp) : "memory");
        }
        asm volatile("cp.async.commit_group;" ::: "memory");
    };

    float acc[2][4][4];
    #pragma unroll
    for (int i = 0; i < 2; i++)
        #pragma unroll
        for (int j = 0; j < 4; j++)
            #pragma unroll
            for (int q = 0; q < 4; q++) acc[i][j][q] = 0.f;

    const int lrow = lane & 15;
    const int lk16 = (lane >> 4) << 4;
    uint32_t arow_off[2], brow_off[2];
    #pragma unroll
    for (int mt = 0; mt < 2; mt++)
        arow_off[mt] = (uint32_t)((wm * 32 + mt * 16 + lrow) * (HSTRIDE * 2)) + (uint32_t)lk16;
    #pragma unroll
    for (int g = 0; g < 2; g++)
        brow_off[g] = (uint32_t)((wn * 32 + g * 16 + lrow) * (HSTRIDE * 2)) + (uint32_t)lk16;

    load_stage(0, 0);

    for (int i = 0; i < nsteps; i++) {
        if (i + 1 < nsteps) {
            load_stage(i + 1, (i + 1) & 1);
            asm volatile("cp.async.wait_group 1;" ::: "memory");
        } else {
            asm volatile("cp.async.wait_group 0;" ::: "memory");
        }
        __syncthreads();

        const int s = i & 1;
        const uint32_t stA_hi = sb + (uint32_t)(s * STAGEB3);
        const uint32_t stA_lo = stA_hi + TBYTES;
        const uint32_t stB_hi = stA_hi + 2 * TBYTES;
        const uint32_t stB_lo = stA_hi + 3 * TBYTES;

        #pragma unroll
        for (int kb = 0; kb < 4; kb++) {
            const uint32_t koff = (uint32_t)(kb << 5);
            uint32_t ah[2][4], al[2][4], bh[4][2], bl[4][2];
            #pragma unroll
            for (int mt = 0; mt < 2; mt++) {
                LDSM4(ah[mt][0], ah[mt][1], ah[mt][2], ah[mt][3], stA_hi + arow_off[mt] + koff);
                LDSM4(al[mt][0], al[mt][1], al[mt][2], al[mt][3], stA_lo + arow_off[mt] + koff);
            }
            #pragma unroll
            for (int g = 0; g < 2; g++) {
                uint32_t r0, r1, r2, r3;
                LDSM4(r0, r1, r2, r3, stB_hi + brow_off[g] + koff);
                bh[2*g][0] = r0; bh[2*g+1][0] = r1; bh[2*g][1] = r2; bh[2*g+1][1] = r3;
                LDSM4(r0, r1, r2, r3, stB_lo + brow_off[g] + koff);
                bl[2*g][0] = r0; bl[2*g+1][0] = r1; bl[2*g][1] = r2; bl[2*g+1][1] = r3;
            }
            #pragma unroll
            for (int mt = 0; mt < 2; mt++)
                #pragma unroll
                for (int nt = 0; nt < 4; nt++) {
                    float* d = acc[mt][nt];
                    mma16(d[0], d[1], d[2], d[3],
                          ah[mt][0], ah[mt][1], ah[mt][2], ah[mt][3], bh[nt][0], bh[nt][1]);
                    mma16(d[0], d[1], d[2], d[3],
                          al[mt][0], al[mt][1], al[mt][2], al[mt][3], bh[nt][0], bh[nt][1]);
                    mma16(d[0], d[1], d[2], d[3],
                          ah[mt][0], ah[mt][1], ah[mt][2], ah[mt][3], bl[nt][0], bl[nt][1]);
                }
        }
        __syncthreads();
    }

    #pragma unroll
    for (int mt = 0; mt < 2; mt++) {
        const int row = m0 + wm * 32 + mt * 16 + r;
        #pragma unroll
        for (int nt = 0; nt < 4; nt++) {
            const int col = n0 + wn * 32 + nt * 8 + 2 * c;
            if (col < Nreal) {
                float v0 = acc[mt][nt][0] + bias[col], v1 = acc[mt][nt][1] + bias[col+1];
                float v2 = acc[mt][nt][2] + bias[col], v3 = acc[mt][nt][3] + bias[col+1];
                __half h0 = __float2half_rn(v0), h1 = __float2half_rn(v1);
                __half h2 = __float2half_rn(v2), h3 = __float2half_rn(v3);
                *(half2*)&Hout[(size_t)row * Nreal + col]       = __halves2half2(h0, h1);
                *(half2*)&Hout[(size_t)(row + 8) * Nreal + col] = __halves2half2(h2, h3);
                *(half2*)&Lout[(size_t)row * Nreal + col] =
                    __halves2half2(__float2half_rn(v0 - __half2float(h0)),
                                   __float2half_rn(v1 - __half2float(h1)));
                *(half2*)&Lout[(size_t)(row + 8) * Nreal + col] =
                    __halves2half2(__float2half_rn(v2 - __half2float(h2)),
                                   __float2half_rn(v3 - __half2float(h3)));
            }
        }
    }
}

// ============ 2-pass split-FP16 GEMM (GEMM2/3; 3 tensors, 2 CTAs/SM) =========
// C[M,Nreal] = (Ahi+Alo)[M,K] @ Bhi^T, fp32 output, no bias.
// 256 threads = 8 warps (2x4), warp tile 64x32, K-step 64, 2-stage.
__global__ void __launch_bounds__(256, 2) gemm_h2(
    const __half* __restrict__ Ahi, const __half* __restrict__ Alo,
    const __half* __restrict__ Bhi,
    float* __restrict__ Cout, int M, int Nreal, int K)
{
    extern __shared__ __align__(16) char smem[];
    const uint32_t sb = (uint32_t)__cvta_generic_to_shared(smem);
    const int tid = threadIdx.x;
    const int wid = tid >> 5;
    const int lane = tid & 31;
    const int wm = wid & 1;           // warp row (2)
    const int wn = wid >> 1;          // warp col (4)
    const int r = lane >> 2;
    const int c = lane & 3;
    const int m0 = blockIdx.y << 7;
    const int n0 = blockIdx.x << 7;
    const int nsteps = K >> 6;

    auto load_stage = [&](int kstep, int s) {
        const int k0 = kstep << 6;
        #pragma unroll
        for (int j = 0; j < 12; j++) {           // 3072 16B-chunks / 256 thr
            const int t = j >> 2;                // tensor id, uniform per j
            const __half* gsel = (t == 0) ? Ahi : (t == 1) ? Alo : Bhi;
            const int rb = (t < 2) ? m0 : n0;
            int rem = ((j & 3) << 8) + tid;      // 0..1023 within tensor
            int row = rem >> 3, col = rem & 7;
            const __half* gp = gsel + (size_t)(rb + row) * K + k0 + (col << 3);
            uint32_t sa = sb + (uint32_t)(s * STAGEB2 + t * TBYTES + row * (HSTRIDE * 2) + (col << 4));
            asm volatile("cp.async.cg.shared.global [%0], [%1], 16;" :: "r"(sa), "l"(gp) : "memory");
        }
        asm volatile("cp.async.commit_group;" ::: "memory");
    };

    float acc[4][4][4];
    #pragma unroll
    for (int i = 0; i < 4; i++)
        #pragma unroll
        for (int j = 0; j < 4; j++)
            #pragma unroll
            for (int q = 0; q < 4; q++) acc[i][j][q] = 0.f;

    const int lrow = lane & 15;
    const int lk16 = (lane >> 4) << 4;
    uint32_t arow_off[4], brow_off[2];
    #pragma unroll
    for (int mt = 0; mt < 4; mt++)
        arow_off[mt] = (uint32_t)((wm * 64 + mt * 16 + lrow) * (HSTRIDE * 2)) + (uint32_t)lk16;
    #pragma unroll
    for (int g = 0; g < 2; g++)
        brow_off[g] = (uint32_t)((wn * 32 + g * 16 + lrow) * (HSTRIDE * 2)) + (uint32_t)lk16;

    load_stage(0, 0);

    for (int i = 0; i < nsteps; i++) {
        if (i + 1 < nsteps) {
            load_stage(i + 1, (i + 1) & 1);
            asm volatile("cp.async.wait_group 1;" ::: "memory");
        } else {
            asm volatile("cp.async.wait_group 0;" ::: "memory");
        }
        __syncthreads();

        const int s = i & 1;
        const uint32_t stA_hi = sb + (uint32_t)(s * STAGEB2);
        const uint32_t stA_lo = stA_hi + TBYTES;
        const uint32_t stB_hi = stA_hi + 2 * TBYTES;

        #pragma unroll
        for (int kb = 0; kb < 4; kb++) {
            const uint32_t koff = (uint32_t)(kb << 5);
            uint32_t ah[4][4], al[4][4], bh[4][2];
            #pragma unroll
            for (int mt = 0; mt < 4; mt++) {
                LDSM4(ah[mt][0], ah[mt][1], ah[mt][2], ah[mt][3], stA_hi + arow_off[mt] + koff);
                LDSM4(al[mt][0], al[mt][1], al[mt][2], al[mt][3], stA_lo + arow_off[mt] + koff);
            }
            #pragma unroll
            for (int g = 0; g < 2; g++) {
                uint32_t r0, r1, r2, r3;
                LDSM4(r0, r1, r2, r3, stB_hi + brow_off[g] + koff);
                bh[2*g][0] = r0; bh[2*g+1][0] = r1; bh[2*g][1] = r2; bh[2*g+1][1] = r3;
            }
            #pragma unroll
            for (int mt = 0; mt < 4; mt++)
                #pragma unroll
                for (int nt = 0; nt < 4; nt++) {
                    float* d = acc[mt][nt];
                    mma16(d[0], d[1], d[2], d[3],
                          ah[mt][0], ah[mt][1], ah[mt][2], ah[mt][3], bh[nt][0], bh[nt][1]);
                    mma16(d[0], d[1], d[2], d[3],
                          al[mt][0], al[mt][1], al[mt][2], al[mt][3], bh[nt][0], bh[nt][1]);
                }
        }
        __syncthreads();
    }

    #pragma unroll
    for (int mt = 0; mt < 4; mt++) {
        const int row = m0 + wm * 64 + mt * 16 + r;
        #pragma unroll
        for (int nt = 0; nt < 4; nt++) {
            const int col = n0 + wn * 32 + nt * 8 + 2 * c;
            if (col < Nreal) {
                *(float2*)&Cout[(size_t)row * Nreal + col] =
                    make_float2(acc[mt][nt][0], acc[mt][nt][1]);
                *(float2*)&Cout[(size_t)(row + 8) * Nreal + col] =
                    make_float2(acc[mt][nt][2], acc[mt][nt][3]);
            }
        }
    }
}

// ---------------- elementwise split: float -> (hi, lo) fp16 pair -------------
__global__ void split4h_kernel(const float* __restrict__ x,
                               __half* __restrict__ hi, __half* __restrict__ lo, int n4)
{
    int i = blockIdx.x * blockDim.x + threadIdx.x;
    if (i >= n4) return;
    float4 v = ((const float4*)x)[i];
    __half h0 = __float2half_rn(v.x), h1 = __float2half_rn(v.y);
    __half h2 = __float2half_rn(v.z), h3 = __float2half_rn(v.w);
    ((half2*)hi)[2*i]   = __halves2half2(h0, h1);
    ((half2*)hi)[2*i+1] = __halves2half2(h2, h3);
    ((half2*)lo)[2*i]   = __halves2half2(__float2half_rn(v.x - __half2float(h0)),
                                         __float2half_rn(v.y - __half2float(h1)));
    ((half2*)lo)[2*i+1] = __halves2half2(__float2half_rn(v.z - __half2float(h2)),
                                         __float2half_rn(v.w - __half2float(h3)));
}

// ---------------- transpose + split: W[K,N] -> Wt_hi(/lo)[Npad,K] fp16 -------
template<bool WLO>
__global__ void tsplit_kernel(const float* __restrict__ W,
                              __half* __restrict__ Thi, __half* __restrict__ Tlo,
                              int K, int N)
{
    __shared__ float t[32][33];
    const int n0 = blockIdx.x * 32, k0 = blockIdx.y * 32;
    const int tx = threadIdx.x, ty = threadIdx.y;   // 32 x 8
    #pragma unroll
    for (int r = 0; r < 4; r++) {
        int k = k0 + ty + r * 8, n = n0 + tx;
        t[ty + r * 8][tx] = (n < N) ? W[(size_t)k * N + n] : 0.f;
    }
    __syncthreads();
    #pragma unroll
    for (int r = 0; r < 4; r++) {
        int n = n0 + ty + r * 8, k = k0 + tx;
        float v = t[tx][ty + r * 8];
        __half h = __float2half_rn(v);
        Thi[(size_t)n * K + k] = h;
        if (WLO) Tlo[(size_t)n * K + k] = __float2half_rn(v - __half2float(h));
    }
}

// ---------------- dt: exact fp32 dt_raw + dtmod + softplus + dA --------------
// block = 8 rows x 32 heads; dt_raw = u . W_in[:, DI+CD+h] computed exactly.
__global__ void __launch_bounds__(256) dt_kernel(
    const float* __restrict__ dte, const float* __restrict__ Wd,
    const float* __restrict__ bd,  const float* __restrict__ W_in,
    const float* __restrict__ dt_bias, const float* __restrict__ A_log)
{
    __shared__ float us[8][1024];
    const int row0 = blockIdx.x * 8;
    const int tid = threadIdx.x;
    for (int idx = tid; idx < 8 * 1024; idx += 256) {
        int r = idx >> 10, j = idx & 1023;
        us[r][j] = __half2float(g_uhi[(size_t)(row0 + r) * DM + j])
                 + __half2float(g_ulo[(size_t)(row0 + r) * DM + j]);
    }
    __syncthreads();
    const int r = tid >> 5, h = tid & 31;
    const int row = row0 + r;
    float s = bd[h];
    #pragma unroll 8
    for (int j = 0; j < DTIME; j++) s = fmaf(dte[(size_t)row * DTIME + j], Wd[j * NH + h], s);
    const float* wcol = W_in + (DI + CD) + h;
    float x0 = 0.f, x1 = 0.f, x2 = 0.f, x3 = 0.f;
    #pragma unroll 4
    for (int j = 0; j < DM; j += 4) {
        x0 = fmaf(us[r][j+0], wcol[(size_t)(j+0) * DIP], x0);
        x1 = fmaf(us[r][j+1], wcol[(size_t)(j+1) * DIP], x1);
        x2 = fmaf(us[r][j+2], wcol[(size_t)(j+2) * DIP], x2);
        x3 = fmaf(us[r][j+3], wcol[(size_t)(j+3) * DIP], x3);
    }
    float x = (x0 + x1) + (x2 + x3) + dt_bias[h] + s;
    float dt = (x > 20.f) ? x : log1pf(expf(x));
    float A  = -expf(A_log[h]);
    const int idx = row * NH + h;
    g_dt[idx] = dt;
    g_dA[idx] = expf(dt * A);
}

// ---------------- causal conv (taps=4) + bias + silu -------------------------
// reads zx over NGEMM2-wide rows (z + xBC layout unchanged in first 4352 cols)
__global__ void conv_kernel(const float* __restrict__ zx,
                            const float* __restrict__ conv_w,
                            const float* __restrict__ conv_b)
{
    int idx = blockIdx.x * blockDim.x + threadIdx.x;   // ROWS*CD
    if (idx >= ROWS * CD) return;
    int c   = idx % CD;
    int row = idx / CD;
    int l   = row & (L_SZ - 1);
    int b   = row / L_SZ;
    float acc = conv_b[c];
    #pragma unroll
    for (int k = 0; k < DCONV; k++) {
        int ll = l - (DCONV - 1) + k;
        if (ll >= 0)
            acc = fmaf(zx[(size_t)(b*L_SZ + ll) * NGEMM2 + DI + c], conv_w[k*CD + c], acc);
    }
    g_xBCa[idx] = acc / (1.f + expf(-acc));   // silu
}

// ---------------- scan phase A: per-chunk local scan from zero state ---------
__global__ void __launch_bounds__(256) scanA_kernel(const float* __restrict__ Dvec)
{
    const int c = blockIdx.x, h = blockIdx.y, b = blockIdx.z;
    const int t = threadIdx.x;
    __shared__ float xs[2][64], Bs[2][128], Cs[2][128], red[2][256];

    const int p = t & 63, g = t >> 6, n0 = g * 32;
    float s[32];
    #pragma unroll
    for (int j = 0; j < 32; j++) s[j] = 0.f;
    float cum = 1.f;
    const float Dh = Dvec[h];
    const int l0 = c * CL;
    const int bh = b * NH + h;

    for (int li = 0; li < CL; li++) {
        const int l = l0 + li, par = li & 1;
        const float* base = g_xBCa + (size_t)(b*L_SZ + l) * CD;
        for (int i = t; i < 320; i += 256) {
            if (i < 64)        xs[par][i]       = base[h*HD + i];
            else if (i < 192)  Bs[par][i - 64]  = base[DI + (i - 64)];
            else               Cs[par][i - 192] = base[DI + DS + (i - 192)];
        }
        float dtv = g_dt[(b*L_SZ + l)*NH + h];
        float dAv = g_dA[(b*L_SZ + l)*NH + h];
        __syncthreads();

        float coef = dtv * xs[par][p];
        float acc = 0.f;
        #pragma unroll
        for (int j = 0; j < 32; j++) {
            s[j] = fmaf(dAv, s[j], coef * Bs[par][n0 + j]);
            acc  = fmaf(s[j], Cs[par][n0 + j], acc);
        }
        red[par][t] = acc;
        cum *= dAv;
        __syncthreads();

        if (t < 64) {
            float y = red[par][t] + red[par][t+64] + red[par][t+128] + red[par][t+192]
                    + Dh * xs[par][t];
            g_y[(size_t)(b*L_SZ + l)*DI + h*HD + t] = y;
        }
        if (t == 0) g_cumdec[bh*L_SZ + l] = cum;
    }

    const size_t sbase = ((size_t)bh * NC + c) * (HD * DS);
    #pragma unroll
    for (int j = 0; j < 32; j++) g_Sfinal[sbase + p*DS + n0 + j] = s[j];
}

// ---------------- scan phase B: sequential chunk-state combine ---------------
__global__ void phaseB_kernel()
{
    const int bh = blockIdx.x;
    const int e0 = blockIdx.y * 1024;
    const int t  = threadIdx.x;
    for (int e = e0 + t; e < e0 + 1024; e += 256) {
        float hv = 0.f;
        for (int c = 0; c < NC; c++) {
            const size_t o = ((size_t)bh * NC + c) * (HD * DS) + e;
            g_Hinit[o] = hv;
            float P = g_cumdec[bh*L_SZ + c*CL + CL - 1];
            hv = fmaf(P, hv, g_Sfinal[o]);
        }
    }
}

// ---------------- scan phase C: rank-correction y += cumdec * C^T h_init -----
__global__ void __launch_bounds__(256) phaseC_kernel()
{
    const int c = blockIdx.x;
    if (c == 0) return;
    const int h = blockIdx.y, b = blockIdx.z;
    const int t = threadIdx.x;
    __shared__ float Hs[64 * 129];
    __shared__ float Cs[2][128], red[2][256];

    const int bh = b * NH + h;
    const size_t hbase = ((size_t)bh * NC + c) * (HD * DS);
    for (int i = t; i < HD * DS; i += 256)
        Hs[(i >> 7) * 129 + (i & 127)] = g_Hinit[hbase + i];

    const int p = t & 63, g = t >> 6, n0 = g * 32;
    const int l0 = c * CL;
    __syncthreads();

    for (int li = 0; li < CL; li++) {
        const int l = l0 + li, par = li & 1;
        const float* base = g_xBCa + (size_t)(b*L_SZ + l) * CD + DI + DS;
        if (t < 128) Cs[par][t] = base[t];
        float cd = g_cumdec[bh*L_SZ + l];
        __syncthreads();

        float acc = 0.f;
        #pragma unroll
        for (int j = 0; j < 32; j++)
            acc = fmaf(Hs[p*129 + n0 + j], Cs[par][n0 + j], acc);
        red[par][t] = acc;
        __syncthreads();

        if (t < 64)
            g_y[(size_t)(b*L_SZ + l)*DI + h*HD + t] +=
                cd * (red[par][t] + red[par][t+64] + red[par][t+128] + red[par][t+192]);
    }
}

// ---------------- gating (silu(z)) + RMS norm -> split fp16 pair -------------
__global__ void __launch_bounds__(256) epilogue_kernel(const float* __restrict__ norm_w)
{
    const int row = blockIdx.x;
    const int t   = threadIdx.x;
    float gv[8];
    float ss = 0.f;
    #pragma unroll
    for (int i = 0; i < 8; i++) {
        int cidx = t + i * 256;
        float yv = g_y[(size_t)row * DI + cidx];
        float zv = g_zx[(size_t)row * NGEMM2 + cidx];
        float sil = zv / (1.f + expf(-zv));
        float v = yv * sil;
        gv[i] = v;
        ss += v * v;
    }
    __shared__ float rs[32];
    #pragma unroll
    for (int o = 16; o; o >>= 1) ss += __shfl_xor_sync(~0u, ss, o);
    if ((t & 31) == 0) rs[t >> 5] = ss;
    __syncthreads();
    if (t < 32) {
        float v = (t < 8) ? rs[t] : 0.f;
        #pragma unroll
        for (int o = 4; o; o >>= 1) v += __shfl_xor_sync(~0u, v, o);
        if (t == 0) rs[0] = v;
    }
    __syncthreads();
    float scale = rsqrtf(rs[0] / (float)DI + EPSV);
    #pragma unroll
    for (int i = 0; i < 8; i++) {
        int cidx = t + i * 256;
        float v = gv[i] * scale * norm_w[cidx];
        __half h = __float2half_rn(v);
        const size_t off = (size_t)row * DI + cidx;
        g_yhi[off] = h;
        g_ylo[off] = __float2half_rn(v - __half2float(h));
    }
}

// ---------------- launch ----------------
extern "C" void kernel_launch(void* const* d_in, const int* in_sizes, int n_in,
                              void* d_out, int out_size)
{
    const float* hidden  = (const float*)d_in[0];
    const float* dte     = (const float*)d_in[1];
    const float* W_proj  = (const float*)d_in[2];
    const float* b_proj  = (const float*)d_in[3];
    const float* W_dtmod = (const float*)d_in[4];
    const float* b_dtmod = (const float*)d_in[5];
    const float* W_in    = (const float*)d_in[6];
    const float* conv_w  = (const float*)d_in[7];
    const float* conv_b  = (const float*)d_in[8];
    const float* dt_bias = (const float*)d_in[9];
    const float* A_log   = (const float*)d_in[10];
    const float* Dvec    = (const float*)d_in[11];
    const float* norm_w  = (const float*)d_in[12];
    const float* W_out   = (const float*)d_in[13];
    float* out = (float*)d_out;

    float *p_zx;
    __half *p_uhi, *p_ulo, *p_yhi, *p_ylo, *p_hhi, *p_hlo;
    __half *p_wpt_hi, *p_wpt_lo, *p_wit_hi, *p_wot_hi;
    cudaGetSymbolAddress((void**)&p_uhi, g_uhi);
    cudaGetSymbolAddress((void**)&p_ulo, g_ulo);
    cudaGetSymbolAddress((void**)&p_zx,  g_zx);
    cudaGetSymbolAddress((void**)&p_yhi, g_yhi);
    cudaGetSymbolAddress((void**)&p_ylo, g_ylo);
    cudaGetSymbolAddress((void**)&p_hhi, g_hhi);
    cudaGetSymbolAddress((void**)&p_hlo, g_hlo);
    cudaGetSymbolAddress((void**)&p_wpt_hi, g_wpt_hi);
    cudaGetSymbolAddress((void**)&p_wpt_lo, g_wpt_lo);
    cudaGetSymbolAddress((void**)&p_wit_hi, g_wit_hi);
    cudaGetSymbolAddress((void**)&p_wot_hi, g_wot_hi);

    cudaFuncSetAttribute(gemm_h3, cudaFuncAttributeMaxDynamicSharedMemorySize, SMEM3P);
    cudaFuncSetAttribute(gemm_h2, cudaFuncAttributeMaxDynamicSharedMemorySize, SMEM2P);

    // 0) operand prep
    split4h_kernel<<<(ROWS*DM/4 + 255)/256, 256>>>(hidden, p_hhi, p_hlo, ROWS*DM/4);
    tsplit_kernel<true ><<<dim3(DM/32,  DM/32), dim3(32,8)>>>(W_proj, p_wpt_hi, p_wpt_lo, DM, DM);
    tsplit_kernel<false><<<dim3(DIPPAD/32, DM/32), dim3(32,8)>>>(W_in,  p_wit_hi, nullptr, DM, DIP);
    tsplit_kernel<false><<<dim3(DM/32,  DI/32), dim3(32,8)>>>(W_out, p_wot_hi, nullptr, DI, DM);

    // 1) u = hidden @ W_proj + b_proj   (3-pass; split fp16 output)
    gemm_h3<<<dim3(DM/128, ROWS/128), 512, SMEM3P>>>(
        p_hhi, p_hlo, p_wpt_hi, p_wpt_lo, b_proj, p_uhi, p_ulo, ROWS, DM, DM);

    // 2) zxbcdt[:, :4352] = u @ W_in   (2-pass, 2 CTAs/SM; dt cols done exactly in dt_kernel)
    gemm_h2<<<dim3(NGEMM2/128, ROWS/128), 256, SMEM2P>>>(
        p_uhi, p_ulo, p_wit_hi, p_zx, ROWS, NGEMM2, DM);

    // 3) dt: exact fp32 dt_raw dot + dtmod + softplus; dA = exp(dt*A)
    dt_kernel<<<ROWS/8, 256>>>(dte, W_dtmod, b_dtmod, W_in, dt_bias, A_log);

    // 4) xBC = silu(causal_conv(xBC) + conv_b)
    conv_kernel<<<(ROWS*CD + 255)/256, 256>>>(p_zx, conv_w, conv_b);

    // 5) chunked selective scan
    scanA_kernel<<<dim3(NC, NH, B_SZ), 256>>>(Dvec);
    phaseB_kernel<<<dim3(B_SZ*NH, 8), 256>>>();
    phaseC_kernel<<<dim3(NC, NH, B_SZ), 256>>>();

    // 6) gating + RMS norm (writes split y)
    epilogue_kernel<<<ROWS, 256>>>(norm_w);

    // 7) out = yn @ W_out   (2-pass, 2 CTAs/SM)
    gemm_h2<<<dim3(DM/128, ROWS/128), 256, SMEM2P>>>(
        p_yhi, p_ylo, p_wot_hi, out, ROWS, DM, DI);
}

// round 8
// speedup vs baseline: 2.2822x; 1.1538x over previous
#include <cuda_runtime.h>
#include <cuda_fp16.h>
#include <cuda_bf16.h>
#include <cstdint>

// ---------------- problem constants ----------------
#define B_SZ   2
#define L_SZ   2048
#define DM     1024      // d_model
#define DI     2048      // d_inner
#define DS     128       // d_state
#define DCONV  4
#define NH     32        // nheads
#define HD     64        // headdim
#define DTIME  64
#define CD     (DI + 2*DS)            // 2304 conv dim
#define DIP    (2*DI + 2*DS + NH)     // 4384 in-proj dim
#define DIPPAD 4480                   // 35*128
#define NGEMM2 4352                   // 34*128 = DI+CD (z,xBC cols only)
#define ROWS   (B_SZ*L_SZ)            // 4096
#define NC     16                     // scan chunks
#define CL     (L_SZ/NC)              // 128 chunk len
#define EPSV   1e-5f

// ---------------- scratch (device globals; no allocs allowed) ----------------
__device__ __half g_uhi[ROWS*DM], g_ulo[ROWS*DM];
__device__ float  g_zx[ROWS*DIP];
__device__ float  g_xBCa[ROWS*CD];
__device__ float  g_dt[ROWS*NH];
__device__ float  g_dA[ROWS*NH];
__device__ float  g_cumdec[B_SZ*NH*L_SZ];
__device__ float  g_Sfinal[B_SZ*NH*NC*HD*DS];
__device__ float  g_Hinit [B_SZ*NH*NC*HD*DS];
__device__ float  g_y[ROWS*DI];
__device__ __half g_yhi[ROWS*DI];
__device__ __half g_hhi[ROWS*DM], g_hlo[ROWS*DM];
__device__ __half g_wpt_hi[DM*DM], g_wpt_lo[DM*DM];   // W_proj^T  [1024][1024]
__device__ __half g_wit_hi[DIPPAD*DM];                // W_in^T    [4480][1024] (hi only)
__device__ __half g_wot_hi[DM*DI];                    // W_out^T   [1024][2048] (hi only)

// ---------------- mma / ldmatrix helpers ----------------
__device__ __forceinline__ void mma16(float& d0, float& d1, float& d2, float& d3,
                                      uint32_t a0, uint32_t a1, uint32_t a2, uint32_t a3,
                                      uint32_t b0, uint32_t b1)
{
    asm volatile("mma.sync.aligned.m16n8k16.row.col.f32.f16.f16.f32 "
        "{%0,%1,%2,%3},{%4,%5,%6,%7},{%8,%9},{%0,%1,%2,%3};"
        : "+f"(d0), "+f"(d1), "+f"(d2), "+f"(d3)
        : "r"(a0), "r"(a1), "r"(a2), "r"(a3), "r"(b0), "r"(b1));
}
#define LDSM4(r0,r1,r2,r3, addr) \
    asm volatile("ldmatrix.sync.aligned.m8n8.x4.shared.b16 {%0,%1,%2,%3}, [%4];" \
        : "=r"(r0), "=r"(r1), "=r"(r2), "=r"(r3) : "r"(addr))

// smem geometry: rows of 64 halfs padded to 72 (144B stride; 8-row groups bank-disjoint)
#define HSTRIDE 72
#define TBYTES  (128 * HSTRIDE * 2)       // 18432 bytes per tensor per stage
#define STAGEB3 (4 * TBYTES)              // Ahi,Alo,Bhi,Blo (3-pass variant)
#define SMEM3P  (2 * STAGEB3)             // 147456
#define STAGEB1 (2 * TBYTES)              // Ahi,Bhi (1-pass variant) = 36864
#define SMEM1P  (2 * STAGEB1)             // 73728 -> 2 CTAs/SM

// ============ 3-pass split-FP16 GEMM (GEMM1 only) ============================
__global__ void __launch_bounds__(512, 1) gemm_h3(
    const __half* __restrict__ Ahi, const __half* __restrict__ Alo,
    const __half* __restrict__ Bhi, const __half* __restrict__ Blo,
    const float* __restrict__ bias,
    __half* __restrict__ Hout, __half* __restrict__ Lout,
    int M, int Nreal, int K)
{
    extern __shared__ __align__(16) char smem[];
    const uint32_t sb = (uint32_t)__cvta_generic_to_shared(smem);
    const int tid = threadIdx.x;
    const int wid = tid >> 5;
    const int lane = tid & 31;
    const int wm = wid & 3;           // warp row (4)
    const int wn = wid >> 2;          // warp col (4)
    const int r = lane >> 2;
    const int c = lane & 3;
    const int m0 = blockIdx.y << 7;
    const int n0 = blockIdx.x << 7;
    const int nsteps = K >> 6;

    const int t4   = tid >> 7;
    const int l128 = tid & 127;
    const __half* gsel = (t4 == 0) ? Ahi : (t4 == 1) ? Alo : (t4 == 2) ? Bhi : Blo;
    const int rb = (t4 < 2) ? m0 : n0;

    auto load_stage = [&](int kstep, int s) {
        const int k0 = kstep << 6;
        const __half* gb = gsel + (size_t)rb * K + k0;
        const uint32_t tb = sb + (uint32_t)(s * STAGEB3 + t4 * TBYTES);
        #pragma unroll
        for (int j = 0; j < 8; j++) {
            int q = j * 128 + l128;
            int row = q >> 3, col = q & 7;
            const __half* gp = gb + (size_t)row * K + (col << 3);
            uint32_t sa = tb + (uint32_t)(row * (HSTRIDE * 2) + (col << 4));
            asm volatile("cp.async.cg.shared.global [%0], [%1], 16;" :: "r"(sa), "l"(gp) : "memory");
        }
        asm volatile("cp.async.commit_group;" ::: "memory");
    };

    float acc[2][4][4];
    #pragma unroll
    for (int i = 0; i < 2; i++)
        #pragma unroll
        for (int j = 0; j < 4; j++)
            #pragma unroll
            for (int q = 0; q < 4; q++) acc[i][j][q] = 0.f;

    const int lrow = lane & 15;
    const int lk16 = (lane >> 4) << 4;
    uint32_t arow_off[2], brow_off[2];
    #pragma unroll
    for (int mt = 0; mt < 2; mt++)
        arow_off[mt] = (uint32_t)((wm * 32 + mt * 16 + lrow) * (HSTRIDE * 2)) + (uint32_t)lk16;
    #pragma unroll
    for (int g = 0; g < 2; g++)
        brow_off[g] = (uint32_t)((wn * 32 + g * 16 + lrow) * (HSTRIDE * 2)) + (uint32_t)lk16;

    load_stage(0, 0);

    for (int i = 0; i < nsteps; i++) {
        if (i + 1 < nsteps) {
            load_stage(i + 1, (i + 1) & 1);
            asm volatile("cp.async.wait_group 1;" ::: "memory");
        } else {
            asm volatile("cp.async.wait_group 0;" ::: "memory");
        }
        __syncthreads();

        const int s = i & 1;
        const uint32_t stA_hi = sb + (uint32_t)(s * STAGEB3);
        const uint32_t stA_lo = stA_hi + TBYTES;
        const uint32_t stB_hi = stA_hi + 2 * TBYTES;
        const uint32_t stB_lo = stA_hi + 3 * TBYTES;

        #pragma unroll
        for (int kb = 0; kb < 4; kb++) {
            const uint32_t koff = (uint32_t)(kb << 5);
            uint32_t ah[2][4], al[2][4], bh[4][2], bl[4][2];
            #pragma unroll
            for (int mt = 0; mt < 2; mt++) {
                LDSM4(ah[mt][0], ah[mt][1], ah[mt][2], ah[mt][3], stA_hi + arow_off[mt] + koff);
                LDSM4(al[mt][0], al[mt][1], al[mt][2], al[mt][3], stA_lo + arow_off[mt] + koff);
            }
            #pragma unroll
            for (int g = 0; g < 2; g++) {
                uint32_t r0, r1, r2, r3;
                LDSM4(r0, r1, r2, r3, stB_hi + brow_off[g] + koff);
                bh[2*g][0] = r0; bh[2*g+1][0] = r1; bh[2*g][1] = r2; bh[2*g+1][1] = r3;
                LDSM4(r0, r1, r2, r3, stB_lo + brow_off[g] + koff);
                bl[2*g][0] = r0; bl[2*g+1][0] = r1; bl[2*g][1] = r2; bl[2*g+1][1] = r3;
            }
            #pragma unroll
            for (int mt = 0; mt < 2; mt++)
                #pragma unroll
                for (int nt = 0; nt < 4; nt++) {
                    float* d = acc[mt][nt];
                    mma16(d[0], d[1], d[2], d[3],
                          ah[mt][0], ah[mt][1], ah[mt][2], ah[mt][3], bh[nt][0], bh[nt][1]);
                    mma16(d[0], d[1], d[2], d[3],
                          al[mt][0], al[mt][1], al[mt][2], al[mt][3], bh[nt][0], bh[nt][1]);
                    mma16(d[0], d[1], d[2], d[3],
                          ah[mt][0], ah[mt][1], ah[mt][2], ah[mt][3], bl[nt][0], bl[nt][1]);
                }
        }
        __syncthreads();
    }

    #pragma unroll
    for (int mt = 0; mt < 2; mt++) {
        const int row = m0 + wm * 32 + mt * 16 + r;
        #pragma unroll
        for (int nt = 0; nt < 4; nt++) {
            const int col = n0 + wn * 32 + nt * 8 + 2 * c;
            if (col < Nreal) {
                float v0 = acc[mt][nt][0] + bias[col], v1 = acc[mt][nt][1] + bias[col+1];
                float v2 = acc[mt][nt][2] + bias[col], v3 = acc[mt][nt][3] + bias[col+1];
                __half h0 = __float2half_rn(v0), h1 = __float2half_rn(v1);
                __half h2 = __float2half_rn(v2), h3 = __float2half_rn(v3);
                *(half2*)&Hout[(size_t)row * Nreal + col]       = __halves2half2(h0, h1);
                *(half2*)&Hout[(size_t)(row + 8) * Nreal + col] = __halves2half2(h2, h3);
                *(half2*)&Lout[(size_t)row * Nreal + col] =
                    __halves2half2(__float2half_rn(v0 - __half2float(h0)),
                                   __float2half_rn(v1 - __half2float(h1)));
                *(half2*)&Lout[(size_t)(row + 8) * Nreal + col] =
                    __halves2half2(__float2half_rn(v2 - __half2float(h2)),
                                   __float2half_rn(v3 - __half2float(h3)));
            }
        }
    }
}

// ============ 1-pass FP16 GEMM (GEMM2/3; 2 tensors, 2 CTAs/SM) ===============
// C[M,Nreal] = Ahi[M,K] @ Bhi^T, fp32 output.
// 256 threads = 8 warps (2x4), warp tile 64x32, K-step 64, 2-stage.
__global__ void __launch_bounds__(256, 2) gemm_h1(
    const __half* __restrict__ Ahi, const __half* __restrict__ Bhi,
    float* __restrict__ Cout, int M, int Nreal, int K)
{
    extern __shared__ __align__(16) char smem[];
    const uint32_t sb = (uint32_t)__cvta_generic_to_shared(smem);
    const int tid = threadIdx.x;
    const int wid = tid >> 5;
    const int lane = tid & 31;
    const int wm = wid & 1;           // warp row (2)
    const int wn = wid >> 1;          // warp col (4)
    const int r = lane >> 2;
    const int c = lane & 3;
    const int m0 = blockIdx.y << 7;
    const int n0 = blockIdx.x << 7;
    const int nsteps = K >> 6;

    auto load_stage = [&](int kstep, int s) {
        const int k0 = kstep << 6;
        #pragma unroll
        for (int j = 0; j < 8; j++) {            // 2048 16B-chunks / 256 thr
            const int t = j >> 2;                // 0 = A, 1 = B (uniform per j)
            const __half* gsel = (t == 0) ? Ahi : Bhi;
            const int rb = (t == 0) ? m0 : n0;
            int rem = ((j & 3) << 8) + tid;      // 0..1023 within tensor
            int row = rem >> 3, col = rem & 7;
            const __half* gp = gsel + (size_t)(rb + row) * K + k0 + (col << 3);
            uint32_t sa = sb + (uint32_t)(s * STAGEB1 + t * TBYTES + row * (HSTRIDE * 2) + (col << 4));
            asm volatile("cp.async.cg.shared.global [%0], [%1], 16;" :: "r"(sa), "l"(gp) : "memory");
        }
        asm volatile("cp.async.commit_group;" ::: "memory");
    };

    float acc[4][4][4];
    #pragma unroll
    for (int i = 0; i < 4; i++)
        #pragma unroll
        for (int j = 0; j < 4; j++)
            #pragma unroll
            for (int q = 0; q < 4; q++) acc[i][j][q] = 0.f;

    const int lrow = lane & 15;
    const int lk16 = (lane >> 4) << 4;
    uint32_t arow_off[4], brow_off[2];
    #pragma unroll
    for (int mt = 0; mt < 4; mt++)
        arow_off[mt] = (uint32_t)((wm * 64 + mt * 16 + lrow) * (HSTRIDE * 2)) + (uint32_t)lk16;
    #pragma unroll
    for (int g = 0; g < 2; g++)
        brow_off[g] = (uint32_t)((wn * 32 + g * 16 + lrow) * (HSTRIDE * 2)) + (uint32_t)lk16;

    load_stage(0, 0);

    for (int i = 0; i < nsteps; i++) {
        if (i + 1 < nsteps) {
            load_stage(i + 1, (i + 1) & 1);
            asm volatile("cp.async.wait_group 1;" ::: "memory");
        } else {
            asm volatile("cp.async.wait_group 0;" ::: "memory");
        }
        __syncthreads();

        const int s = i & 1;
        const uint32_t stA = sb + (uint32_t)(s * STAGEB1);
        const uint32_t stB = stA + TBYTES;

        #pragma unroll
        for (int kb = 0; kb < 4; kb++) {
            const uint32_t koff = (uint32_t)(kb << 5);
            uint32_t ah[4][4], bh[4][2];
            #pragma unroll
            for (int mt = 0; mt < 4; mt++)
                LDSM4(ah[mt][0], ah[mt][1], ah[mt][2], ah[mt][3], stA + arow_off[mt] + koff);
            #pragma unroll
            for (int g = 0; g < 2; g++) {
                uint32_t r0, r1, r2, r3;
                LDSM4(r0, r1, r2, r3, stB + brow_off[g] + koff);
                bh[2*g][0] = r0; bh[2*g+1][0] = r1; bh[2*g][1] = r2; bh[2*g+1][1] = r3;
            }
            #pragma unroll
            for (int mt = 0; mt < 4; mt++)
                #pragma unroll
                for (int nt = 0; nt < 4; nt++) {
                    float* d = acc[mt][nt];
                    mma16(d[0], d[1], d[2], d[3],
                          ah[mt][0], ah[mt][1], ah[mt][2], ah[mt][3], bh[nt][0], bh[nt][1]);
                }
        }
        __syncthreads();
    }

    #pragma unroll
    for (int mt = 0; mt < 4; mt++) {
        const int row = m0 + wm * 64 + mt * 16 + r;
        #pragma unroll
        for (int nt = 0; nt < 4; nt++) {
            const int col = n0 + wn * 32 + nt * 8 + 2 * c;
            if (col < Nreal) {
                *(float2*)&Cout[(size_t)row * Nreal + col] =
                    make_float2(acc[mt][nt][0], acc[mt][nt][1]);
                *(float2*)&Cout[(size_t)(row + 8) * Nreal + col] =
                    make_float2(acc[mt][nt][2], acc[mt][nt][3]);
            }
        }
    }
}

// ---------------- elementwise split: float -> (hi, lo) fp16 pair -------------
__global__ void split4h_kernel(const float* __restrict__ x,
                               __half* __restrict__ hi, __half* __restrict__ lo, int n4)
{
    int i = blockIdx.x * blockDim.x + threadIdx.x;
    if (i >= n4) return;
    float4 v = ((const float4*)x)[i];
    __half h0 = __float2half_rn(v.x), h1 = __float2half_rn(v.y);
    __half h2 = __float2half_rn(v.z), h3 = __float2half_rn(v.w);
    ((half2*)hi)[2*i]   = __halves2half2(h0, h1);
    ((half2*)hi)[2*i+1] = __halves2half2(h2, h3);
    ((half2*)lo)[2*i]   = __halves2half2(__float2half_rn(v.x - __half2float(h0)),
                                         __float2half_rn(v.y - __half2float(h1)));
    ((half2*)lo)[2*i+1] = __halves2half2(__float2half_rn(v.z - __half2float(h2)),
                                         __float2half_rn(v.w - __half2float(h3)));
}

// ---------------- transpose + split: W[K,N] -> Wt_hi(/lo)[Npad,K] fp16 -------
template<bool WLO>
__global__ void tsplit_kernel(const float* __restrict__ W,
                              __half* __restrict__ Thi, __half* __restrict__ Tlo,
                              int K, int N)
{
    __shared__ float t[32][33];
    const int n0 = blockIdx.x * 32, k0 = blockIdx.y * 32;
    const int tx = threadIdx.x, ty = threadIdx.y;   // 32 x 8
    #pragma unroll
    for (int r = 0; r < 4; r++) {
        int k = k0 + ty + r * 8, n = n0 + tx;
        t[ty + r * 8][tx] = (n < N) ? W[(size_t)k * N + n] : 0.f;
    }
    __syncthreads();
    #pragma unroll
    for (int r = 0; r < 4; r++) {
        int n = n0 + ty + r * 8, k = k0 + tx;
        float v = t[tx][ty + r * 8];
        __half h = __float2half_rn(v);
        Thi[(size_t)n * K + k] = h;
        if (WLO) Tlo[(size_t)n * K + k] = __float2half_rn(v - __half2float(h));
    }
}

// ---------------- dt: exact fp32 dt_raw + dtmod + softplus + dA --------------
__global__ void __launch_bounds__(256) dt_kernel(
    const float* __restrict__ dte, const float* __restrict__ Wd,
    const float* __restrict__ bd,  const float* __restrict__ W_in,
    const float* __restrict__ dt_bias, const float* __restrict__ A_log)
{
    __shared__ float us[8][1024];
    const int row0 = blockIdx.x * 8;
    const int tid = threadIdx.x;
    for (int idx = tid; idx < 8 * 1024; idx += 256) {
        int r = idx >> 10, j = idx & 1023;
        us[r][j] = __half2float(g_uhi[(size_t)(row0 + r) * DM + j])
                 + __half2float(g_ulo[(size_t)(row0 + r) * DM + j]);
    }
    __syncthreads();
    const int r = tid >> 5, h = tid & 31;
    const int row = row0 + r;
    float s = bd[h];
    #pragma unroll 8
    for (int j = 0; j < DTIME; j++) s = fmaf(dte[(size_t)row * DTIME + j], Wd[j * NH + h], s);
    const float* wcol = W_in + (DI + CD) + h;
    float x0 = 0.f, x1 = 0.f, x2 = 0.f, x3 = 0.f;
    #pragma unroll 4
    for (int j = 0; j < DM; j += 4) {
        x0 = fmaf(us[r][j+0], wcol[(size_t)(j+0) * DIP], x0);
        x1 = fmaf(us[r][j+1], wcol[(size_t)(j+1) * DIP], x1);
        x2 = fmaf(us[r][j+2], wcol[(size_t)(j+2) * DIP], x2);
        x3 = fmaf(us[r][j+3], wcol[(size_t)(j+3) * DIP], x3);
    }
    float x = (x0 + x1) + (x2 + x3) + dt_bias[h] + s;
    float dt = (x > 20.f) ? x : log1pf(expf(x));
    float A  = -expf(A_log[h]);
    const int idx = row * NH + h;
    g_dt[idx] = dt;
    g_dA[idx] = expf(dt * A);
}

// ---------------- causal conv (taps=4) + bias + silu -------------------------
__global__ void conv_kernel(const float* __restrict__ zx,
                            const float* __restrict__ conv_w,
                            const float* __restrict__ conv_b)
{
    int idx = blockIdx.x * blockDim.x + threadIdx.x;   // ROWS*CD
    if (idx >= ROWS * CD) return;
    int c   = idx % CD;
    int row = idx / CD;
    int l   = row & (L_SZ - 1);
    int b   = row / L_SZ;
    float acc = conv_b[c];
    #pragma unroll
    for (int k = 0; k < DCONV; k++) {
        int ll = l - (DCONV - 1) + k;
        if (ll >= 0)
            acc = fmaf(zx[(size_t)(b*L_SZ + ll) * NGEMM2 + DI + c], conv_w[k*CD + c], acc);
    }
    g_xBCa[idx] = acc / (1.f + expf(-acc));   // silu
}

// ---------------- scan phase A: per-chunk local scan from zero state ---------
__global__ void __launch_bounds__(256) scanA_kernel(const float* __restrict__ Dvec)
{
    const int c = blockIdx.x, h = blockIdx.y, b = blockIdx.z;
    const int t = threadIdx.x;
    __shared__ float xs[2][64], Bs[2][128], Cs[2][128], red[2][256];

    const int p = t & 63, g = t >> 6, n0 = g * 32;
    float s[32];
    #pragma unroll
    for (int j = 0; j < 32; j++) s[j] = 0.f;
    float cum = 1.f;
    const float Dh = Dvec[h];
    const int l0 = c * CL;
    const int bh = b * NH + h;

    for (int li = 0; li < CL; li++) {
        const int l = l0 + li, par = li & 1;
        const float* base = g_xBCa + (size_t)(b*L_SZ + l) * CD;
        for (int i = t; i < 320; i += 256) {
            if (i < 64)        xs[par][i]       = base[h*HD + i];
            else if (i < 192)  Bs[par][i - 64]  = base[DI + (i - 64)];
            else               Cs[par][i - 192] = base[DI + DS + (i - 192)];
        }
        float dtv = g_dt[(b*L_SZ + l)*NH + h];
        float dAv = g_dA[(b*L_SZ + l)*NH + h];
        __syncthreads();

        float coef = dtv * xs[par][p];
        float a0 = 0.f, a1 = 0.f, a2 = 0.f, a3 = 0.f;
        #pragma unroll
        for (int j = 0; j < 32; j += 4) {
            s[j+0] = fmaf(dAv, s[j+0], coef * Bs[par][n0+j+0]);
            s[j+1] = fmaf(dAv, s[j+1], coef * Bs[par][n0+j+1]);
            s[j+2] = fmaf(dAv, s[j+2], coef * Bs[par][n0+j+2]);
            s[j+3] = fmaf(dAv, s[j+3], coef * Bs[par][n0+j+3]);
            a0 = fmaf(s[j+0], Cs[par][n0+j+0], a0);
            a1 = fmaf(s[j+1], Cs[par][n0+j+1], a1);
            a2 = fmaf(s[j+2], Cs[par][n0+j+2], a2);
            a3 = fmaf(s[j+3], Cs[par][n0+j+3], a3);
        }
        red[par][t] = (a0 + a1) + (a2 + a3);
        cum *= dAv;
        __syncthreads();

        if (t < 64) {
            float y = red[par][t] + red[par][t+64] + red[par][t+128] + red[par][t+192]
                    + Dh * xs[par][t];
            g_y[(size_t)(b*L_SZ + l)*DI + h*HD + t] = y;
        }
        if (t == 0) g_cumdec[bh*L_SZ + l] = cum;
    }

    const size_t sbase = ((size_t)bh * NC + c) * (HD * DS);
    #pragma unroll
    for (int j = 0; j < 32; j++) g_Sfinal[sbase + p*DS + n0 + j] = s[j];
}

// ---------------- scan phase B: sequential chunk-state combine ---------------
__global__ void phaseB_kernel()
{
    const int bh = blockIdx.x;
    const int e0 = blockIdx.y * 1024;
    const int t  = threadIdx.x;
    for (int e = e0 + t; e < e0 + 1024; e += 256) {
        float hv = 0.f;
        for (int c = 0; c < NC; c++) {
            const size_t o = ((size_t)bh * NC + c) * (HD * DS) + e;
            g_Hinit[o] = hv;
            float P = g_cumdec[bh*L_SZ + c*CL + CL - 1];
            hv = fmaf(P, hv, g_Sfinal[o]);
        }
    }
}

// ---------------- scan phase C: rank-correction y += cumdec * C^T h_init -----
__global__ void __launch_bounds__(256) phaseC_kernel()
{
    const int c = blockIdx.x;
    if (c == 0) return;
    const int h = blockIdx.y, b = blockIdx.z;
    const int t = threadIdx.x;
    __shared__ float Hs[64 * 129];
    __shared__ float Cs[2][128], red[2][256];

    const int bh = b * NH + h;
    const size_t hbase = ((size_t)bh * NC + c) * (HD * DS);
    for (int i = t; i < HD * DS; i += 256)
        Hs[(i >> 7) * 129 + (i & 127)] = g_Hinit[hbase + i];

    const int p = t & 63, g = t >> 6, n0 = g * 32;
    const int l0 = c * CL;
    __syncthreads();

    for (int li = 0; li < CL; li++) {
        const int l = l0 + li, par = li & 1;
        const float* base = g_xBCa + (size_t)(b*L_SZ + l) * CD + DI + DS;
        if (t < 128) Cs[par][t] = base[t];
        float cd = g_cumdec[bh*L_SZ + l];
        __syncthreads();

        float a0 = 0.f, a1 = 0.f, a2 = 0.f, a3 = 0.f;
        #pragma unroll
        for (int j = 0; j < 32; j += 4) {
            a0 = fmaf(Hs[p*129 + n0+j+0], Cs[par][n0+j+0], a0);
            a1 = fmaf(Hs[p*129 + n0+j+1], Cs[par][n0+j+1], a1);
            a2 = fmaf(Hs[p*129 + n0+j+2], Cs[par][n0+j+2], a2);
            a3 = fmaf(Hs[p*129 + n0+j+3], Cs[par][n0+j+3], a3);
        }
        red[par][t] = (a0 + a1) + (a2 + a3);
        __syncthreads();

        if (t < 64)
            g_y[(size_t)(b*L_SZ + l)*DI + h*HD + t] +=
                cd * (red[par][t] + red[par][t+64] + red[par][t+128] + red[par][t+192]);
    }
}

// ---------------- gating (silu(z)) + RMS norm -> fp16 hi ---------------------
__global__ void __launch_bounds__(256) epilogue_kernel(const float* __restrict__ norm_w)
{
    const int row = blockIdx.x;
    const int t   = threadIdx.x;
    float gv[8];
    float ss = 0.f;
    #pragma unroll
    for (int i = 0; i < 8; i++) {
        int cidx = t + i * 256;
        float yv = g_y[(size_t)row * DI + cidx];
        float zv = g_zx[(size_t)row * NGEMM2 + cidx];
        float sil = zv / (1.f + expf(-zv));
        float v = yv * sil;
        gv[i] = v;
        ss += v * v;
    }
    __shared__ float rs[32];
    #pragma unroll
    for (int o = 16; o; o >>= 1) ss += __shfl_xor_sync(~0u, ss, o);
    if ((t & 31) == 0) rs[t >> 5] = ss;
    __syncthreads();
    if (t < 32) {
        float v = (t < 8) ? rs[t] : 0.f;
        #pragma unroll
        for (int o = 4; o; o >>= 1) v += __shfl_xor_sync(~0u, v, o);
        if (t == 0) rs[0] = v;
    }
    __syncthreads();
    float scale = rsqrtf(rs[0] / (float)DI + EPSV);
    #pragma unroll
    for (int i = 0; i < 8; i++) {
        int cidx = t + i * 256;
        float v = gv[i] * scale * norm_w[cidx];
        g_yhi[(size_t)row * DI + cidx] = __float2half_rn(v);
    }
}

// ---------------- launch ----------------
extern "C" void kernel_launch(void* const* d_in, const int* in_sizes, int n_in,
                              void* d_out, int out_size)
{
    const float* hidden  = (const float*)d_in[0];
    const float* dte     = (const float*)d_in[1];
    const float* W_proj  = (const float*)d_in[2];
    const float* b_proj  = (const float*)d_in[3];
    const float* W_dtmod = (const float*)d_in[4];
    const float* b_dtmod = (const float*)d_in[5];
    const float* W_in    = (const float*)d_in[6];
    const float* conv_w  = (const float*)d_in[7];
    const float* conv_b  = (const float*)d_in[8];
    const float* dt_bias = (const float*)d_in[9];
    const float* A_log   = (const float*)d_in[10];
    const float* Dvec    = (const float*)d_in[11];
    const float* norm_w  = (const float*)d_in[12];
    const float* W_out   = (const float*)d_in[13];
    float* out = (float*)d_out;

    float *p_zx;
    __half *p_uhi, *p_ulo, *p_yhi, *p_hhi, *p_hlo;
    __half *p_wpt_hi, *p_wpt_lo, *p_wit_hi, *p_wot_hi;
    cudaGetSymbolAddress((void**)&p_uhi, g_uhi);
    cudaGetSymbolAddress((void**)&p_ulo, g_ulo);
    cudaGetSymbolAddress((void**)&p_zx,  g_zx);
    cudaGetSymbolAddress((void**)&p_yhi, g_yhi);
    cudaGetSymbolAddress((void**)&p_hhi, g_hhi);
    cudaGetSymbolAddress((void**)&p_hlo, g_hlo);
    cudaGetSymbolAddress((void**)&p_wpt_hi, g_wpt_hi);
    cudaGetSymbolAddress((void**)&p_wpt_lo, g_wpt_lo);
    cudaGetSymbolAddress((void**)&p_wit_hi, g_wit_hi);
    cudaGetSymbolAddress((void**)&p_wot_hi, g_wot_hi);

    cudaFuncSetAttribute(gemm_h3, cudaFuncAttributeMaxDynamicSharedMemorySize, SMEM3P);
    cudaFuncSetAttribute(gemm_h1, cudaFuncAttributeMaxDynamicSharedMemorySize, SMEM1P);

    // 0) operand prep
    split4h_kernel<<<(ROWS*DM/4 + 255)/256, 256>>>(hidden, p_hhi, p_hlo, ROWS*DM/4);
    tsplit_kernel<true ><<<dim3(DM/32,  DM/32), dim3(32,8)>>>(W_proj, p_wpt_hi, p_wpt_lo, DM, DM);
    tsplit_kernel<false><<<dim3(DIPPAD/32, DM/32), dim3(32,8)>>>(W_in,  p_wit_hi, nullptr, DM, DIP);
    tsplit_kernel<false><<<dim3(DM/32,  DI/32), dim3(32,8)>>>(W_out, p_wot_hi, nullptr, DI, DM);

    // 1) u = hidden @ W_proj + b_proj   (3-pass; split fp16 output)
    gemm_h3<<<dim3(DM/128, ROWS/128), 512, SMEM3P>>>(
        p_hhi, p_hlo, p_wpt_hi, p_wpt_lo, b_proj, p_uhi, p_ulo, ROWS, DM, DM);

    // 2) zxbcdt[:, :4352] = u @ W_in   (1-pass; dt cols done exactly in dt_kernel)
    gemm_h1<<<dim3(NGEMM2/128, ROWS/128), 256, SMEM1P>>>(
        p_uhi, p_wit_hi, p_zx, ROWS, NGEMM2, DM);

    // 3) dt: exact fp32 dt_raw dot + dtmod + softplus; dA = exp(dt*A)
    dt_kernel<<<ROWS/8, 256>>>(dte, W_dtmod, b_dtmod, W_in, dt_bias, A_log);

    // 4) xBC = silu(causal_conv(xBC) + conv_b)
    conv_kernel<<<(ROWS*CD + 255)/256, 256>>>(p_zx, conv_w, conv_b);

    // 5) chunked selective scan
    scanA_kernel<<<dim3(NC, NH, B_SZ), 256>>>(Dvec);
    phaseB_kernel<<<dim3(B_SZ*NH, 8), 256>>>();
    phaseC_kernel<<<dim3(NC, NH, B_SZ), 256>>>();

    // 6) gating + RMS norm (writes fp16 hi)
    epilogue_kernel<<<ROWS, 256>>>(norm_w);

    // 7) out = yn @ W_out   (1-pass)
    gemm_h1<<<dim3(DM/128, ROWS/128), 256, SMEM1P>>>(
        p_yhi, p_wot_hi, out, ROWS, DM, DI);
}

// round 9
// speedup vs baseline: 2.4962x; 1.0938x over previous
#include <cuda_runtime.h>
#include <cuda_fp16.h>
#include <cuda_bf16.h>
#include <cstdint>

// ---------------- problem constants ----------------
#define B_SZ   2
#define L_SZ   2048
#define DM     1024      // d_model
#define DI     2048      // d_inner
#define DS     128       // d_state
#define DCONV  4
#define NH     32        // nheads
#define HD     64        // headdim
#define DTIME  64
#define CD     (DI + 2*DS)            // 2304 conv dim
#define DIP    (2*DI + 2*DS + NH)     // 4384 in-proj dim
#define DIPPAD 4480                   // 35*128
#define NGEMM2 4352                   // 34*128 = DI+CD (z,xBC cols only)
#define ROWS   (B_SZ*L_SZ)            // 4096
#define NC     16                     // scan chunks
#define CL     (L_SZ/NC)              // 128 chunk len
#define EPSV   1e-5f

// ---------------- scratch (device globals; no allocs allowed) ----------------
__device__ __half g_uhi[ROWS*DM], g_ulo[ROWS*DM];
__device__ float  g_zx[ROWS*DIP];
__device__ float  g_xBCa[ROWS*CD];
__device__ float  g_dt[ROWS*NH];
__device__ float  g_dA[ROWS*NH];
__device__ float  g_cumdec[B_SZ*NH*L_SZ];
__device__ float  g_Sfinal[B_SZ*NH*NC*HD*DS];
__device__ float  g_Hinit [B_SZ*NH*NC*HD*DS];
__device__ float  g_y[ROWS*DI];
__device__ __half g_yhi[ROWS*DI];
__device__ __half g_hhi[ROWS*DM], g_hlo[ROWS*DM];
__device__ __half g_wpt_hi[DM*DM], g_wpt_lo[DM*DM];   // W_proj^T  [1024][1024]
__device__ __half g_wit_hi[DIPPAD*DM];                // W_in^T    [4480][1024] (hi only)
__device__ __half g_wot_hi[DM*DI];                    // W_out^T   [1024][2048] (hi only)

// ---------------- mma / ldmatrix helpers ----------------
__device__ __forceinline__ void mma16(float& d0, float& d1, float& d2, float& d3,
                                      uint32_t a0, uint32_t a1, uint32_t a2, uint32_t a3,
                                      uint32_t b0, uint32_t b1)
{
    asm volatile("mma.sync.aligned.m16n8k16.row.col.f32.f16.f16.f32 "
        "{%0,%1,%2,%3},{%4,%5,%6,%7},{%8,%9},{%0,%1,%2,%3};"
        : "+f"(d0), "+f"(d1), "+f"(d2), "+f"(d3)
        : "r"(a0), "r"(a1), "r"(a2), "r"(a3), "r"(b0), "r"(b1));
}
#define LDSM4(r0,r1,r2,r3, addr) \
    asm volatile("ldmatrix.sync.aligned.m8n8.x4.shared.b16 {%0,%1,%2,%3}, [%4];" \
        : "=r"(r0), "=r"(r1), "=r"(r2), "=r"(r3) : "r"(addr))
#define CPASYNC4(saddr, gptr) \
    asm volatile("cp.async.ca.shared.global [%0], [%1], 4;" :: "r"(saddr), "l"(gptr) : "memory")
#define CPCOMMIT() asm volatile("cp.async.commit_group;" ::: "memory")

// smem geometry: rows of 64 halfs padded to 72 (144B stride; 8-row groups bank-disjoint)
#define HSTRIDE 72
#define TBYTES  (128 * HSTRIDE * 2)       // 18432 bytes per tensor per stage
#define STAGEB3 (4 * TBYTES)              // Ahi,Alo,Bhi,Blo (3-pass variant)
#define SMEM3P  (2 * STAGEB3)             // 147456
#define STAGEB1 (2 * TBYTES)              // Ahi,Bhi (1-pass variant) = 36864
#define SMEM1P  (2 * STAGEB1)             // 73728 -> 2 CTAs/SM

// ============ 3-pass split-FP16 GEMM (GEMM1 only) ============================
__global__ void __launch_bounds__(512, 1) gemm_h3(
    const __half* __restrict__ Ahi, const __half* __restrict__ Alo,
    const __half* __restrict__ Bhi, const __half* __restrict__ Blo,
    const float* __restrict__ bias,
    __half* __restrict__ Hout, __half* __restrict__ Lout,
    int M, int Nreal, int K)
{
    extern __shared__ __align__(16) char smem[];
    const uint32_t sb = (uint32_t)__cvta_generic_to_shared(smem);
    const int tid = threadIdx.x;
    const int wid = tid >> 5;
    const int lane = tid & 31;
    const int wm = wid & 3;
    const int wn = wid >> 2;
    const int r = lane >> 2;
    const int c = lane & 3;
    const int m0 = blockIdx.y << 7;
    const int n0 = blockIdx.x << 7;
    const int nsteps = K >> 6;

    const int t4   = tid >> 7;
    const int l128 = tid & 127;
    const __half* gsel = (t4 == 0) ? Ahi : (t4 == 1) ? Alo : (t4 == 2) ? Bhi : Blo;
    const int rb = (t4 < 2) ? m0 : n0;

    auto load_stage = [&](int kstep, int s) {
        const int k0 = kstep << 6;
        const __half* gb = gsel + (size_t)rb * K + k0;
        const uint32_t tb = sb + (uint32_t)(s * STAGEB3 + t4 * TBYTES);
        #pragma unroll
        for (int j = 0; j < 8; j++) {
            int q = j * 128 + l128;
            int row = q >> 3, col = q & 7;
            const __half* gp = gb + (size_t)row * K + (col << 3);
            uint32_t sa = tb + (uint32_t)(row * (HSTRIDE * 2) + (col << 4));
            asm volatile("cp.async.cg.shared.global [%0], [%1], 16;" :: "r"(sa), "l"(gp) : "memory");
        }
        CPCOMMIT();
    };

    float acc[2][4][4];
    #pragma unroll
    for (int i = 0; i < 2; i++)
        #pragma unroll
        for (int j = 0; j < 4; j++)
            #pragma unroll
            for (int q = 0; q < 4; q++) acc[i][j][q] = 0.f;

    const int lrow = lane & 15;
    const int lk16 = (lane >> 4) << 4;
    uint32_t arow_off[2], brow_off[2];
    #pragma unroll
    for (int mt = 0; mt < 2; mt++)
        arow_off[mt] = (uint32_t)((wm * 32 + mt * 16 + lrow) * (HSTRIDE * 2)) + (uint32_t)lk16;
    #pragma unroll
    for (int g = 0; g < 2; g++)
        brow_off[g] = (uint32_t)((wn * 32 + g * 16 + lrow) * (HSTRIDE * 2)) + (uint32_t)lk16;

    load_stage(0, 0);

    for (int i = 0; i < nsteps; i++) {
        if (i + 1 < nsteps) {
            load_stage(i + 1, (i + 1) & 1);
            asm volatile("cp.async.wait_group 1;" ::: "memory");
        } else {
            asm volatile("cp.async.wait_group 0;" ::: "memory");
        }
        __syncthreads();

        const int s = i & 1;
        const uint32_t stA_hi = sb + (uint32_t)(s * STAGEB3);
        const uint32_t stA_lo = stA_hi + TBYTES;
        const uint32_t stB_hi = stA_hi + 2 * TBYTES;
        const uint32_t stB_lo = stA_hi + 3 * TBYTES;

        #pragma unroll
        for (int kb = 0; kb < 4; kb++) {
            const uint32_t koff = (uint32_t)(kb << 5);
            uint32_t ah[2][4], al[2][4], bh[4][2], bl[4][2];
            #pragma unroll
            for (int mt = 0; mt < 2; mt++) {
                LDSM4(ah[mt][0], ah[mt][1], ah[mt][2], ah[mt][3], stA_hi + arow_off[mt] + koff);
                LDSM4(al[mt][0], al[mt][1], al[mt][2], al[mt][3], stA_lo + arow_off[mt] + koff);
            }
            #pragma unroll
            for (int g = 0; g < 2; g++) {
                uint32_t r0, r1, r2, r3;
                LDSM4(r0, r1, r2, r3, stB_hi + brow_off[g] + koff);
                bh[2*g][0] = r0; bh[2*g+1][0] = r1; bh[2*g][1] = r2; bh[2*g+1][1] = r3;
                LDSM4(r0, r1, r2, r3, stB_lo + brow_off[g] + koff);
                bl[2*g][0] = r0; bl[2*g+1][0] = r1; bl[2*g][1] = r2; bl[2*g+1][1] = r3;
            }
            #pragma unroll
            for (int mt = 0; mt < 2; mt++)
                #pragma unroll
                for (int nt = 0; nt < 4; nt++) {
                    float* d = acc[mt][nt];
                    mma16(d[0], d[1], d[2], d[3],
                          ah[mt][0], ah[mt][1], ah[mt][2], ah[mt][3], bh[nt][0], bh[nt][1]);
                    mma16(d[0], d[1], d[2], d[3],
                          al[mt][0], al[mt][1], al[mt][2], al[mt][3], bh[nt][0], bh[nt][1]);
                    mma16(d[0], d[1], d[2], d[3],
                          ah[mt][0], ah[mt][1], ah[mt][2], ah[mt][3], bl[nt][0], bl[nt][1]);
                }
        }
        __syncthreads();
    }

    #pragma unroll
    for (int mt = 0; mt < 2; mt++) {
        const int row = m0 + wm * 32 + mt * 16 + r;
        #pragma unroll
        for (int nt = 0; nt < 4; nt++) {
            const int col = n0 + wn * 32 + nt * 8 + 2 * c;
            if (col < Nreal) {
                float v0 = acc[mt][nt][0] + bias[col], v1 = acc[mt][nt][1] + bias[col+1];
                float v2 = acc[mt][nt][2] + bias[col], v3 = acc[mt][nt][3] + bias[col+1];
                __half h0 = __float2half_rn(v0), h1 = __float2half_rn(v1);
                __half h2 = __float2half_rn(v2), h3 = __float2half_rn(v3);
                *(half2*)&Hout[(size_t)row * Nreal + col]       = __halves2half2(h0, h1);
                *(half2*)&Hout[(size_t)(row + 8) * Nreal + col] = __halves2half2(h2, h3);
                *(half2*)&Lout[(size_t)row * Nreal + col] =
                    __halves2half2(__float2half_rn(v0 - __half2float(h0)),
                                   __float2half_rn(v1 - __half2float(h1)));
                *(half2*)&Lout[(size_t)(row + 8) * Nreal + col] =
                    __halves2half2(__float2half_rn(v2 - __half2float(h2)),
                                   __float2half_rn(v3 - __half2float(h3)));
            }
        }
    }
}

// ============ 1-pass FP16 GEMM (GEMM2/3; 2 tensors, 2 CTAs/SM) ===============
__global__ void __launch_bounds__(256, 2) gemm_h1(
    const __half* __restrict__ Ahi, const __half* __restrict__ Bhi,
    float* __restrict__ Cout, int M, int Nreal, int K)
{
    extern __shared__ __align__(16) char smem[];
    const uint32_t sb = (uint32_t)__cvta_generic_to_shared(smem);
    const int tid = threadIdx.x;
    const int wid = tid >> 5;
    const int lane = tid & 31;
    const int wm = wid & 1;
    const int wn = wid >> 1;
    const int r = lane >> 2;
    const int c = lane & 3;
    const int m0 = blockIdx.y << 7;
    const int n0 = blockIdx.x << 7;
    const int nsteps = K >> 6;

    auto load_stage = [&](int kstep, int s) {
        const int k0 = kstep << 6;
        #pragma unroll
        for (int j = 0; j < 8; j++) {
            const int t = j >> 2;
            const __half* gsel = (t == 0) ? Ahi : Bhi;
            const int rb = (t == 0) ? m0 : n0;
            int rem = ((j & 3) << 8) + tid;
            int row = rem >> 3, col = rem & 7;
            const __half* gp = gsel + (size_t)(rb + row) * K + k0 + (col << 3);
            uint32_t sa = sb + (uint32_t)(s * STAGEB1 + t * TBYTES + row * (HSTRIDE * 2) + (col << 4));
            asm volatile("cp.async.cg.shared.global [%0], [%1], 16;" :: "r"(sa), "l"(gp) : "memory");
        }
        CPCOMMIT();
    };

    float acc[4][4][4];
    #pragma unroll
    for (int i = 0; i < 4; i++)
        #pragma unroll
        for (int j = 0; j < 4; j++)
            #pragma unroll
            for (int q = 0; q < 4; q++) acc[i][j][q] = 0.f;

    const int lrow = lane & 15;
    const int lk16 = (lane >> 4) << 4;
    uint32_t arow_off[4], brow_off[2];
    #pragma unroll
    for (int mt = 0; mt < 4; mt++)
        arow_off[mt] = (uint32_t)((wm * 64 + mt * 16 + lrow) * (HSTRIDE * 2)) + (uint32_t)lk16;
    #pragma unroll
    for (int g = 0; g < 2; g++)
        brow_off[g] = (uint32_t)((wn * 32 + g * 16 + lrow) * (HSTRIDE * 2)) + (uint32_t)lk16;

    load_stage(0, 0);

    for (int i = 0; i < nsteps; i++) {
        if (i + 1 < nsteps) {
            load_stage(i + 1, (i + 1) & 1);
            asm volatile("cp.async.wait_group 1;" ::: "memory");
        } else {
            asm volatile("cp.async.wait_group 0;" ::: "memory");
        }
        __syncthreads();

        const int s = i & 1;
        const uint32_t stA = sb + (uint32_t)(s * STAGEB1);
        const uint32_t stB = stA + TBYTES;

        #pragma unroll
        for (int kb = 0; kb < 4; kb++) {
            const uint32_t koff = (uint32_t)(kb << 5);
            uint32_t ah[4][4], bh[4][2];
            #pragma unroll
            for (int mt = 0; mt < 4; mt++)
                LDSM4(ah[mt][0], ah[mt][1], ah[mt][2], ah[mt][3], stA + arow_off[mt] + koff);
            #pragma unroll
            for (int g = 0; g < 2; g++) {
                uint32_t r0, r1, r2, r3;
                LDSM4(r0, r1, r2, r3, stB + brow_off[g] + koff);
                bh[2*g][0] = r0; bh[2*g+1][0] = r1; bh[2*g][1] = r2; bh[2*g+1][1] = r3;
            }
            #pragma unroll
            for (int mt = 0; mt < 4; mt++)
                #pragma unroll
                for (int nt = 0; nt < 4; nt++) {
                    float* d = acc[mt][nt];
                    mma16(d[0], d[1], d[2], d[3],
                          ah[mt][0], ah[mt][1], ah[mt][2], ah[mt][3], bh[nt][0], bh[nt][1]);
                }
        }
        __syncthreads();
    }

    #pragma unroll
    for (int mt = 0; mt < 4; mt++) {
        const int row = m0 + wm * 64 + mt * 16 + r;
        #pragma unroll
        for (int nt = 0; nt < 4; nt++) {
            const int col = n0 + wn * 32 + nt * 8 + 2 * c;
            if (col < Nreal) {
                *(float2*)&Cout[(size_t)row * Nreal + col] =
                    make_float2(acc[mt][nt][0], acc[mt][nt][1]);
                *(float2*)&Cout[(size_t)(row + 8) * Nreal + col] =
                    make_float2(acc[mt][nt][2], acc[mt][nt][3]);
            }
        }
    }
}

// ---------------- elementwise split: float -> (hi, lo) fp16 pair -------------
__global__ void split4h_kernel(const float* __restrict__ x,
                               __half* __restrict__ hi, __half* __restrict__ lo, int n4)
{
    int i = blockIdx.x * blockDim.x + threadIdx.x;
    if (i >= n4) return;
    float4 v = ((const float4*)x)[i];
    __half h0 = __float2half_rn(v.x), h1 = __float2half_rn(v.y);
    __half h2 = __float2half_rn(v.z), h3 = __float2half_rn(v.w);
    ((half2*)hi)[2*i]   = __halves2half2(h0, h1);
    ((half2*)hi)[2*i+1] = __halves2half2(h2, h3);
    ((half2*)lo)[2*i]   = __halves2half2(__float2half_rn(v.x - __half2float(h0)),
                                         __float2half_rn(v.y - __half2float(h1)));
    ((half2*)lo)[2*i+1] = __halves2half2(__float2half_rn(v.z - __half2float(h2)),
                                         __float2half_rn(v.w - __half2float(h3)));
}

// ---------------- transpose + split: W[K,N] -> Wt_hi(/lo)[Npad,K] fp16 -------
template<bool WLO>
__global__ void tsplit_kernel(const float* __restrict__ W,
                              __half* __restrict__ Thi, __half* __restrict__ Tlo,
                              int K, int N)
{
    __shared__ float t[32][33];
    const int n0 = blockIdx.x * 32, k0 = blockIdx.y * 32;
    const int tx = threadIdx.x, ty = threadIdx.y;
    #pragma unroll
    for (int r = 0; r < 4; r++) {
        int k = k0 + ty + r * 8, n = n0 + tx;
        t[ty + r * 8][tx] = (n < N) ? W[(size_t)k * N + n] : 0.f;
    }
    __syncthreads();
    #pragma unroll
    for (int r = 0; r < 4; r++) {
        int n = n0 + ty + r * 8, k = k0 + tx;
        float v = t[tx][ty + r * 8];
        __half h = __float2half_rn(v);
        Thi[(size_t)n * K + k] = h;
        if (WLO) Tlo[(size_t)n * K + k] = __float2half_rn(v - __half2float(h));
    }
}

// ---------------- dt: exact fp32 dt_raw + dtmod + softplus + dA --------------
__global__ void __launch_bounds__(256) dt_kernel(
    const float* __restrict__ dte, const float* __restrict__ Wd,
    const float* __restrict__ bd,  const float* __restrict__ W_in,
    const float* __restrict__ dt_bias, const float* __restrict__ A_log)
{
    __shared__ float us[8][1024];
    const int row0 = blockIdx.x * 8;
    const int tid = threadIdx.x;
    for (int idx = tid; idx < 8 * 1024; idx += 256) {
        int r = idx >> 10, j = idx & 1023;
        us[r][j] = __half2float(g_uhi[(size_t)(row0 + r) * DM + j])
                 + __half2float(g_ulo[(size_t)(row0 + r) * DM + j]);
    }
    __syncthreads();
    const int r = tid >> 5, h = tid & 31;
    const int row = row0 + r;
    float s = bd[h];
    #pragma unroll 8
    for (int j = 0; j < DTIME; j++) s = fmaf(dte[(size_t)row * DTIME + j], Wd[j * NH + h], s);
    const float* wcol = W_in + (DI + CD) + h;
    float x0 = 0.f, x1 = 0.f, x2 = 0.f, x3 = 0.f;
    #pragma unroll 4
    for (int j = 0; j < DM; j += 4) {
        x0 = fmaf(us[r][j+0], wcol[(size_t)(j+0) * DIP], x0);
        x1 = fmaf(us[r][j+1], wcol[(size_t)(j+1) * DIP], x1);
        x2 = fmaf(us[r][j+2], wcol[(size_t)(j+2) * DIP], x2);
        x3 = fmaf(us[r][j+3], wcol[(size_t)(j+3) * DIP], x3);
    }
    float x = (x0 + x1) + (x2 + x3) + dt_bias[h] + s;
    float dt = (x > 20.f) ? x : log1pf(expf(x));
    float A  = -expf(A_log[h]);
    const int idx = row * NH + h;
    g_dt[idx] = dt;
    g_dA[idx] = expf(dt * A);
}

// ---------------- causal conv (taps=4) + bias + silu -------------------------
__global__ void conv_kernel(const float* __restrict__ zx,
                            const float* __restrict__ conv_w,
                            const float* __restrict__ conv_b)
{
    int idx = blockIdx.x * blockDim.x + threadIdx.x;
    if (idx >= ROWS * CD) return;
    int c   = idx % CD;
    int row = idx / CD;
    int l   = row & (L_SZ - 1);
    int b   = row / L_SZ;
    float acc = conv_b[c];
    #pragma unroll
    for (int k = 0; k < DCONV; k++) {
        int ll = l - (DCONV - 1) + k;
        if (ll >= 0)
            acc = fmaf(zx[(size_t)(b*L_SZ + ll) * NGEMM2 + DI + c], conv_w[k*CD + c], acc);
    }
    g_xBCa[idx] = acc / (1.f + expf(-acc));
}

// ---------------- scan phase A: cp.async-pipelined local scan ----------------
// sx layout per step: [0:64) x(head), [64:192) B, [192:320) C
__global__ void __launch_bounds__(256) scanA_kernel(const float* __restrict__ Dvec)
{
    const int c = blockIdx.x, h = blockIdx.y, b = blockIdx.z;
    const int t = threadIdx.x;
    __shared__ float sx[2][320];
    __shared__ float red[2][256];

    const int p = t & 63, g = t >> 6, n0 = g * 32;
    float s[32];
    #pragma unroll
    for (int j = 0; j < 32; j++) s[j] = 0.f;
    float cum = 1.f;
    const float Dh = Dvec[h];
    const int l0 = c * CL;
    const int bh = b * NH + h;

    auto prefetch = [&](int li, int par) {
        const int l = l0 + li;
        const float* base = g_xBCa + (size_t)(b*L_SZ + l) * CD;
        #pragma unroll
        for (int q = 0; q < 2; q++) {
            int i = t + q * 256;
            if (i < 320) {
                const float* src = (i < 64)  ? base + h*HD + i
                                 : (i < 192) ? base + DI + (i - 64)
                                             : base + DI + DS + (i - 192);
                uint32_t sa = (uint32_t)__cvta_generic_to_shared(&sx[par][i]);
                CPASYNC4(sa, src);
            }
        }
        CPCOMMIT();
    };

    prefetch(0, 0);
    float dtv_n = g_dt[(b*L_SZ + l0)*NH + h];
    float dAv_n = g_dA[(b*L_SZ + l0)*NH + h];

    for (int li = 0; li < CL; li++) {
        const int par = li & 1;
        if (li + 1 < CL) {
            prefetch(li + 1, par ^ 1);
            asm volatile("cp.async.wait_group 1;" ::: "memory");
        } else {
            asm volatile("cp.async.wait_group 0;" ::: "memory");
        }
        __syncthreads();

        const float dtv = dtv_n, dAv = dAv_n;
        if (li + 1 < CL) {
            dtv_n = g_dt[(b*L_SZ + l0 + li + 1)*NH + h];
            dAv_n = g_dA[(b*L_SZ + l0 + li + 1)*NH + h];
        }

        const float coef = dtv * sx[par][p];
        const float* Bp = &sx[par][64 + n0];
        const float* Cp = &sx[par][192 + n0];
        float a0 = 0.f, a1 = 0.f, a2 = 0.f, a3 = 0.f;
        #pragma unroll
        for (int j = 0; j < 32; j += 4) {
            s[j+0] = fmaf(dAv, s[j+0], coef * Bp[j+0]);
            s[j+1] = fmaf(dAv, s[j+1], coef * Bp[j+1]);
            s[j+2] = fmaf(dAv, s[j+2], coef * Bp[j+2]);
            s[j+3] = fmaf(dAv, s[j+3], coef * Bp[j+3]);
            a0 = fmaf(s[j+0], Cp[j+0], a0);
            a1 = fmaf(s[j+1], Cp[j+1], a1);
            a2 = fmaf(s[j+2], Cp[j+2], a2);
            a3 = fmaf(s[j+3], Cp[j+3], a3);
        }
        red[par][t] = (a0 + a1) + (a2 + a3);
        cum *= dAv;
        __syncthreads();

        if (t < 64) {
            float y = red[par][t] + red[par][t+64] + red[par][t+128] + red[par][t+192]
                    + Dh * sx[par][t];
            g_y[(size_t)(b*L_SZ + l0 + li)*DI + h*HD + t] = y;
        }
        if (t == 0) g_cumdec[bh*L_SZ + l0 + li] = cum;
    }

    const size_t sbase = ((size_t)bh * NC + c) * (HD * DS);
    #pragma unroll
    for (int j = 0; j < 32; j++) g_Sfinal[sbase + p*DS + n0 + j] = s[j];
}

// ---------------- scan phase B: sequential chunk-state combine ---------------
__global__ void phaseB_kernel()
{
    const int bh = blockIdx.x;
    const int e0 = blockIdx.y * 1024;
    const int t  = threadIdx.x;
    __shared__ float Ps[NC];
    if (t < NC) Ps[t] = g_cumdec[bh*L_SZ + t*CL + CL - 1];
    __syncthreads();
    for (int e = e0 + t; e < e0 + 1024; e += 256) {
        float hv = 0.f;
        for (int c = 0; c < NC; c++) {
            const size_t o = ((size_t)bh * NC + c) * (HD * DS) + e;
            g_Hinit[o] = hv;
            hv = fmaf(Ps[c], hv, g_Sfinal[o]);
        }
    }
}

// ---------------- scan phase C: cp.async-pipelined rank correction -----------
__global__ void __launch_bounds__(256) phaseC_kernel()
{
    const int c = blockIdx.x;
    if (c == 0) return;
    const int h = blockIdx.y, b = blockIdx.z;
    const int t = threadIdx.x;
    __shared__ float Hs[64 * 129];
    __shared__ float Cs[2][128], red[2][256];

    const int bh = b * NH + h;
    const size_t hbase = ((size_t)bh * NC + c) * (HD * DS);
    for (int i = t; i < HD * DS; i += 256)
        Hs[(i >> 7) * 129 + (i & 127)] = g_Hinit[hbase + i];

    const int p = t & 63, g = t >> 6, n0 = g * 32;
    const int l0 = c * CL;

    auto prefetch = [&](int li, int par) {
        if (t < 128) {
            const float* src = g_xBCa + (size_t)(b*L_SZ + l0 + li) * CD + DI + DS + t;
            uint32_t sa = (uint32_t)__cvta_generic_to_shared(&Cs[par][t]);
            CPASYNC4(sa, src);
        }
        CPCOMMIT();
    };

    prefetch(0, 0);
    float cd_n = g_cumdec[bh*L_SZ + l0];
    __syncthreads();   // Hs visible

    for (int li = 0; li < CL; li++) {
        const int par = li & 1;
        if (li + 1 < CL) {
            prefetch(li + 1, par ^ 1);
            asm volatile("cp.async.wait_group 1;" ::: "memory");
        } else {
            asm volatile("cp.async.wait_group 0;" ::: "memory");
        }
        __syncthreads();

        const float cd = cd_n;
        if (li + 1 < CL) cd_n = g_cumdec[bh*L_SZ + l0 + li + 1];

        float a0 = 0.f, a1 = 0.f, a2 = 0.f, a3 = 0.f;
        #pragma unroll
        for (int j = 0; j < 32; j += 4) {
            a0 = fmaf(Hs[p*129 + n0+j+0], Cs[par][n0+j+0], a0);
            a1 = fmaf(Hs[p*129 + n0+j+1], Cs[par][n0+j+1], a1);
            a2 = fmaf(Hs[p*129 + n0+j+2], Cs[par][n0+j+2], a2);
            a3 = fmaf(Hs[p*129 + n0+j+3], Cs[par][n0+j+3], a3);
        }
        red[par][t] = (a0 + a1) + (a2 + a3);
        __syncthreads();

        if (t < 64)
            g_y[(size_t)(b*L_SZ + l0 + li)*DI + h*HD + t] +=
                cd * (red[par][t] + red[par][t+64] + red[par][t+128] + red[par][t+192]);
    }
}

// ---------------- gating (silu(z)) + RMS norm -> fp16 hi ---------------------
__global__ void __launch_bounds__(256) epilogue_kernel(const float* __restrict__ norm_w)
{
    const int row = blockIdx.x;
    const int t   = threadIdx.x;
    float gv[8];
    float ss = 0.f;
    #pragma unroll
    for (int i = 0; i < 8; i++) {
        int cidx = t + i * 256;
        float yv = g_y[(size_t)row * DI + cidx];
        float zv = g_zx[(size_t)row * NGEMM2 + cidx];
        float sil = zv / (1.f + expf(-zv));
        float v = yv * sil;
        gv[i] = v;
        ss += v * v;
    }
    __shared__ float rs[32];
    #pragma unroll
    for (int o = 16; o; o >>= 1) ss += __shfl_xor_sync(~0u, ss, o);
    if ((t & 31) == 0) rs[t >> 5] = ss;
    __syncthreads();
    if (t < 32) {
        float v = (t < 8) ? rs[t] : 0.f;
        #pragma unroll
        for (int o = 4; o; o >>= 1) v += __shfl_xor_sync(~0u, v, o);
        if (t == 0) rs[0] = v;
    }
    __syncthreads();
    float scale = rsqrtf(rs[0] / (float)DI + EPSV);
    #pragma unroll
    for (int i = 0; i < 8; i++) {
        int cidx = t + i * 256;
        float v = gv[i] * scale * norm_w[cidx];
        g_yhi[(size_t)row * DI + cidx] = __float2half_rn(v);
    }
}

// ---------------- launch ----------------
extern "C" void kernel_launch(void* const* d_in, const int* in_sizes, int n_in,
                              void* d_out, int out_size)
{
    const float* hidden  = (const float*)d_in[0];
    const float* dte     = (const float*)d_in[1];
    const float* W_proj  = (const float*)d_in[2];
    const float* b_proj  = (const float*)d_in[3];
    const float* W_dtmod = (const float*)d_in[4];
    const float* b_dtmod = (const float*)d_in[5];
    const float* W_in    = (const float*)d_in[6];
    const float* conv_w  = (const float*)d_in[7];
    const float* conv_b  = (const float*)d_in[8];
    const float* dt_bias = (const float*)d_in[9];
    const float* A_log   = (const float*)d_in[10];
    const float* Dvec    = (const float*)d_in[11];
    const float* norm_w  = (const float*)d_in[12];
    const float* W_out   = (const float*)d_in[13];
    float* out = (float*)d_out;

    float *p_zx;
    __half *p_uhi, *p_ulo, *p_yhi, *p_hhi, *p_hlo;
    __half *p_wpt_hi, *p_wpt_lo, *p_wit_hi, *p_wot_hi;
    cudaGetSymbolAddress((void**)&p_uhi, g_uhi);
    cudaGetSymbolAddress((void**)&p_ulo, g_ulo);
    cudaGetSymbolAddress((void**)&p_zx,  g_zx);
    cudaGetSymbolAddress((void**)&p_yhi, g_yhi);
    cudaGetSymbolAddress((void**)&p_hhi, g_hhi);
    cudaGetSymbolAddress((void**)&p_hlo, g_hlo);
    cudaGetSymbolAddress((void**)&p_wpt_hi, g_wpt_hi);
    cudaGetSymbolAddress((void**)&p_wpt_lo, g_wpt_lo);
    cudaGetSymbolAddress((void**)&p_wit_hi, g_wit_hi);
    cudaGetSymbolAddress((void**)&p_wot_hi, g_wot_hi);

    cudaFuncSetAttribute(gemm_h3, cudaFuncAttributeMaxDynamicSharedMemorySize, SMEM3P);
    cudaFuncSetAttribute(gemm_h1, cudaFuncAttributeMaxDynamicSharedMemorySize, SMEM1P);

    // 0) operand prep
    split4h_kernel<<<(ROWS*DM/4 + 255)/256, 256>>>(hidden, p_hhi, p_hlo, ROWS*DM/4);
    tsplit_kernel<true ><<<dim3(DM/32,  DM/32), dim3(32,8)>>>(W_proj, p_wpt_hi, p_wpt_lo, DM, DM);
    tsplit_kernel<false><<<dim3(DIPPAD/32, DM/32), dim3(32,8)>>>(W_in,  p_wit_hi, nullptr, DM, DIP);
    tsplit_kernel<false><<<dim3(DM/32,  DI/32), dim3(32,8)>>>(W_out, p_wot_hi, nullptr, DI, DM);

    // 1) u = hidden @ W_proj + b_proj   (3-pass; split fp16 output)
    gemm_h3<<<dim3(DM/128, ROWS/128), 512, SMEM3P>>>(
        p_hhi, p_hlo, p_wpt_hi, p_wpt_lo, b_proj, p_uhi, p_ulo, ROWS, DM, DM);

    // 2) zxbcdt[:, :4352] = u @ W_in   (1-pass)
    gemm_h1<<<dim3(NGEMM2/128, ROWS/128), 256, SMEM1P>>>(
        p_uhi, p_wit_hi, p_zx, ROWS, NGEMM2, DM);

    // 3) dt exact
    dt_kernel<<<ROWS/8, 256>>>(dte, W_dtmod, b_dtmod, W_in, dt_bias, A_log);

    // 4) conv + silu
    conv_kernel<<<(ROWS*CD + 255)/256, 256>>>(p_zx, conv_w, conv_b);

    // 5) chunked selective scan (cp.async pipelined)
    scanA_kernel<<<dim3(NC, NH, B_SZ), 256>>>(Dvec);
    phaseB_kernel<<<dim3(B_SZ*NH, 8), 256>>>();
    phaseC_kernel<<<dim3(NC, NH, B_SZ), 256>>>();

    // 6) gating + RMS norm
    epilogue_kernel<<<ROWS, 256>>>(norm_w);

    // 7) out = yn @ W_out   (1-pass)
    gemm_h1<<<dim3(DM/128, ROWS/128), 256, SMEM1P>>>(
        p_yhi, p_wot_hi, out, ROWS, DM, DI);
}

// round 10
// speedup vs baseline: 4.2904x; 1.7188x over previous
#include <cuda_runtime.h>
#include <cuda_fp16.h>
#include <cuda_bf16.h>
#include <cstdint>

// ---------------- problem constants ----------------
#define B_SZ   2
#define L_SZ   2048
#define DM     1024      // d_model
#define DI     2048      // d_inner
#define DS     128       // d_state
#define DCONV  4
#define NH     32        // nheads
#define HD     64        // headdim
#define DTIME  64
#define CD     (DI + 2*DS)            // 2304 conv dim
#define DIP    (2*DI + 2*DS + NH)     // 4384 in-proj dim
#define DIPPAD 4480                   // 35*128
#define NGEMM2 4352                   // 34*128 = DI+CD (z,xBC cols only)
#define ROWS   (B_SZ*L_SZ)            // 4096
#define NC     16                     // scan chunks
#define CL     (L_SZ/NC)              // 128 chunk len
#define EPSV   1e-5f

// ---------------- scratch (device globals; no allocs allowed) ----------------
__device__ __half g_uhi[ROWS*DM], g_ulo[ROWS*DM];
__device__ float  g_zx[ROWS*DIP];
__device__ float  g_xBCa[ROWS*CD];
__device__ float  g_dt[ROWS*NH];
__device__ float  g_dtA[ROWS*NH];
__device__ float  g_cumdec[B_SZ*NH*L_SZ];
__device__ float  g_logcum[B_SZ*NH*L_SZ];
__device__ float  g_Sfinal[B_SZ*NH*NC*HD*DS];
__device__ float  g_Hinit [B_SZ*NH*NC*HD*DS];
__device__ float  g_y[ROWS*DI];
__device__ __half g_yhi[ROWS*DI];
__device__ __half g_hhi[ROWS*DM], g_hlo[ROWS*DM];
__device__ __half g_wpt_hi[DM*DM], g_wpt_lo[DM*DM];   // W_proj^T  [1024][1024]
__device__ __half g_wit_hi[DIPPAD*DM];                // W_in^T    [4480][1024] (hi only)
__device__ __half g_wot_hi[DM*DI];                    // W_out^T   [1024][2048] (hi only)

// ---------------- mma / ldmatrix helpers ----------------
__device__ __forceinline__ void mma16(float& d0, float& d1, float& d2, float& d3,
                                      uint32_t a0, uint32_t a1, uint32_t a2, uint32_t a3,
                                      uint32_t b0, uint32_t b1)
{
    asm volatile("mma.sync.aligned.m16n8k16.row.col.f32.f16.f16.f32 "
        "{%0,%1,%2,%3},{%4,%5,%6,%7},{%8,%9},{%0,%1,%2,%3};"
        : "+f"(d0), "+f"(d1), "+f"(d2), "+f"(d3)
        : "r"(a0), "r"(a1), "r"(a2), "r"(a3), "r"(b0), "r"(b1));
}
#define LDSM4(r0,r1,r2,r3, addr) \
    asm volatile("ldmatrix.sync.aligned.m8n8.x4.shared.b16 {%0,%1,%2,%3}, [%4];" \
        : "=r"(r0), "=r"(r1), "=r"(r2), "=r"(r3) : "r"(addr))

// smem geometry (GEMMs): rows of 64 halfs padded to 72 (144B stride)
#define HSTRIDE 72
#define TBYTES  (128 * HSTRIDE * 2)       // 18432 bytes per tensor per stage
#define STAGEB3 (4 * TBYTES)
#define SMEM3P  (2 * STAGEB3)             // 147456
#define STAGEB1 (2 * TBYTES)
#define SMEM1P  (2 * STAGEB1)             // 73728 -> 2 CTAs/SM

// scan-tile smem geometry: rows of 128 halfs padded to 136 (272B stride; 272%128==16 -> conflict-free ldmatrix)
#define HS2 136

// ============ 3-pass split-FP16 GEMM (GEMM1 only) ============================
__global__ void __launch_bounds__(512, 1) gemm_h3(
    const __half* __restrict__ Ahi, const __half* __restrict__ Alo,
    const __half* __restrict__ Bhi, const __half* __restrict__ Blo,
    const float* __restrict__ bias,
    __half* __restrict__ Hout, __half* __restrict__ Lout,
    int M, int Nreal, int K)
{
    extern __shared__ __align__(16) char smem[];
    const uint32_t sb = (uint32_t)__cvta_generic_to_shared(smem);
    const int tid = threadIdx.x;
    const int wid = tid >> 5;
    const int lane = tid & 31;
    const int wm = wid & 3;
    const int wn = wid >> 2;
    const int r = lane >> 2;
    const int c = lane & 3;
    const int m0 = blockIdx.y << 7;
    const int n0 = blockIdx.x << 7;
    const int nsteps = K >> 6;

    const int t4   = tid >> 7;
    const int l128 = tid & 127;
    const __half* gsel = (t4 == 0) ? Ahi : (t4 == 1) ? Alo : (t4 == 2) ? Bhi : Blo;
    const int rb = (t4 < 2) ? m0 : n0;

    auto load_stage = [&](int kstep, int s) {
        const int k0 = kstep << 6;
        const __half* gb = gsel + (size_t)rb * K + k0;
        const uint32_t tb = sb + (uint32_t)(s * STAGEB3 + t4 * TBYTES);
        #pragma unroll
        for (int j = 0; j < 8; j++) {
            int q = j * 128 + l128;
            int row = q >> 3, col = q & 7;
            const __half* gp = gb + (size_t)row * K + (col << 3);
            uint32_t sa = tb + (uint32_t)(row * (HSTRIDE * 2) + (col << 4));
            asm volatile("cp.async.cg.shared.global [%0], [%1], 16;" :: "r"(sa), "l"(gp) : "memory");
        }
        asm volatile("cp.async.commit_group;" ::: "memory");
    };

    float acc[2][4][4];
    #pragma unroll
    for (int i = 0; i < 2; i++)
        #pragma unroll
        for (int j = 0; j < 4; j++)
            #pragma unroll
            for (int q = 0; q < 4; q++) acc[i][j][q] = 0.f;

    const int lrow = lane & 15;
    const int lk16 = (lane >> 4) << 4;
    uint32_t arow_off[2], brow_off[2];
    #pragma unroll
    for (int mt = 0; mt < 2; mt++)
        arow_off[mt] = (uint32_t)((wm * 32 + mt * 16 + lrow) * (HSTRIDE * 2)) + (uint32_t)lk16;
    #pragma unroll
    for (int g = 0; g < 2; g++)
        brow_off[g] = (uint32_t)((wn * 32 + g * 16 + lrow) * (HSTRIDE * 2)) + (uint32_t)lk16;

    load_stage(0, 0);

    for (int i = 0; i < nsteps; i++) {
        if (i + 1 < nsteps) {
            load_stage(i + 1, (i + 1) & 1);
            asm volatile("cp.async.wait_group 1;" ::: "memory");
        } else {
            asm volatile("cp.async.wait_group 0;" ::: "memory");
        }
        __syncthreads();

        const int s = i & 1;
        const uint32_t stA_hi = sb + (uint32_t)(s * STAGEB3);
        const uint32_t stA_lo = stA_hi + TBYTES;
        const uint32_t stB_hi = stA_hi + 2 * TBYTES;
        const uint32_t stB_lo = stA_hi + 3 * TBYTES;

        #pragma unroll
        for (int kb = 0; kb < 4; kb++) {
            const uint32_t koff = (uint32_t)(kb << 5);
            uint32_t ah[2][4], al[2][4], bh[4][2], bl[4][2];
            #pragma unroll
            for (int mt = 0; mt < 2; mt++) {
                LDSM4(ah[mt][0], ah[mt][1], ah[mt][2], ah[mt][3], stA_hi + arow_off[mt] + koff);
                LDSM4(al[mt][0], al[mt][1], al[mt][2], al[mt][3], stA_lo + arow_off[mt] + koff);
            }
            #pragma unroll
            for (int g = 0; g < 2; g++) {
                uint32_t r0, r1, r2, r3;
                LDSM4(r0, r1, r2, r3, stB_hi + brow_off[g] + koff);
                bh[2*g][0] = r0; bh[2*g+1][0] = r1; bh[2*g][1] = r2; bh[2*g+1][1] = r3;
                LDSM4(r0, r1, r2, r3, stB_lo + brow_off[g] + koff);
                bl[2*g][0] = r0; bl[2*g+1][0] = r1; bl[2*g][1] = r2; bl[2*g+1][1] = r3;
            }
            #pragma unroll
            for (int mt = 0; mt < 2; mt++)
                #pragma unroll
                for (int nt = 0; nt < 4; nt++) {
                    float* d = acc[mt][nt];
                    mma16(d[0], d[1], d[2], d[3],
                          ah[mt][0], ah[mt][1], ah[mt][2], ah[mt][3], bh[nt][0], bh[nt][1]);
                    mma16(d[0], d[1], d[2], d[3],
                          al[mt][0], al[mt][1], al[mt][2], al[mt][3], bh[nt][0], bh[nt][1]);
                    mma16(d[0], d[1], d[2], d[3],
                          ah[mt][0], ah[mt][1], ah[mt][2], ah[mt][3], bl[nt][0], bl[nt][1]);
                }
        }
        __syncthreads();
    }

    #pragma unroll
    for (int mt = 0; mt < 2; mt++) {
        const int row = m0 + wm * 32 + mt * 16 + r;
        #pragma unroll
        for (int nt = 0; nt < 4; nt++) {
            const int col = n0 + wn * 32 + nt * 8 + 2 * c;
            if (col < Nreal) {
                float v0 = acc[mt][nt][0] + bias[col], v1 = acc[mt][nt][1] + bias[col+1];
                float v2 = acc[mt][nt][2] + bias[col], v3 = acc[mt][nt][3] + bias[col+1];
                __half h0 = __float2half_rn(v0), h1 = __float2half_rn(v1);
                __half h2 = __float2half_rn(v2), h3 = __float2half_rn(v3);
                *(half2*)&Hout[(size_t)row * Nreal + col]       = __halves2half2(h0, h1);
                *(half2*)&Hout[(size_t)(row + 8) * Nreal + col] = __halves2half2(h2, h3);
                *(half2*)&Lout[(size_t)row * Nreal + col] =
                    __halves2half2(__float2half_rn(v0 - __half2float(h0)),
                                   __float2half_rn(v1 - __half2float(h1)));
                *(half2*)&Lout[(size_t)(row + 8) * Nreal + col] =
                    __halves2half2(__float2half_rn(v2 - __half2float(h2)),
                                   __float2half_rn(v3 - __half2float(h3)));
            }
        }
    }
}

// ============ 1-pass FP16 GEMM (GEMM2/3; 2 tensors, 2 CTAs/SM) ===============
__global__ void __launch_bounds__(256, 2) gemm_h1(
    const __half* __restrict__ Ahi, const __half* __restrict__ Bhi,
    float* __restrict__ Cout, int M, int Nreal, int K)
{
    extern __shared__ __align__(16) char smem[];
    const uint32_t sb = (uint32_t)__cvta_generic_to_shared(smem);
    const int tid = threadIdx.x;
    const int wid = tid >> 5;
    const int lane = tid & 31;
    const int wm = wid & 1;
    const int wn = wid >> 1;
    const int r = lane >> 2;
    const int c = lane & 3;
    const int m0 = blockIdx.y << 7;
    const int n0 = blockIdx.x << 7;
    const int nsteps = K >> 6;

    auto load_stage = [&](int kstep, int s) {
        const int k0 = kstep << 6;
        #pragma unroll
        for (int j = 0; j < 8; j++) {
            const int t = j >> 2;
            const __half* gsel = (t == 0) ? Ahi : Bhi;
            const int rb = (t == 0) ? m0 : n0;
            int rem = ((j & 3) << 8) + tid;
            int row = rem >> 3, col = rem & 7;
            const __half* gp = gsel + (size_t)(rb + row) * K + k0 + (col << 3);
            uint32_t sa = sb + (uint32_t)(s * STAGEB1 + t * TBYTES + row * (HSTRIDE * 2) + (col << 4));
            asm volatile("cp.async.cg.shared.global [%0], [%1], 16;" :: "r"(sa), "l"(gp) : "memory");
        }
        asm volatile("cp.async.commit_group;" ::: "memory");
    };

    float acc[4][4][4];
    #pragma unroll
    for (int i = 0; i < 4; i++)
        #pragma unroll
        for (int j = 0; j < 4; j++)
            #pragma unroll
            for (int q = 0; q < 4; q++) acc[i][j][q] = 0.f;

    const int lrow = lane & 15;
    const int lk16 = (lane >> 4) << 4;
    uint32_t arow_off[4], brow_off[2];
    #pragma unroll
    for (int mt = 0; mt < 4; mt++)
        arow_off[mt] = (uint32_t)((wm * 64 + mt * 16 + lrow) * (HSTRIDE * 2)) + (uint32_t)lk16;
    #pragma unroll
    for (int g = 0; g < 2; g++)
        brow_off[g] = (uint32_t)((wn * 32 + g * 16 + lrow) * (HSTRIDE * 2)) + (uint32_t)lk16;

    load_stage(0, 0);

    for (int i = 0; i < nsteps; i++) {
        if (i + 1 < nsteps) {
            load_stage(i + 1, (i + 1) & 1);
            asm volatile("cp.async.wait_group 1;" ::: "memory");
        } else {
            asm volatile("cp.async.wait_group 0;" ::: "memory");
        }
        __syncthreads();

        const int s = i & 1;
        const uint32_t stA = sb + (uint32_t)(s * STAGEB1);
        const uint32_t stB = stA + TBYTES;

        #pragma unroll
        for (int kb = 0; kb < 4; kb++) {
            const uint32_t koff = (uint32_t)(kb << 5);
            uint32_t ah[4][4], bh[4][2];
            #pragma unroll
            for (int mt = 0; mt < 4; mt++)
                LDSM4(ah[mt][0], ah[mt][1], ah[mt][2], ah[mt][3], stA + arow_off[mt] + koff);
            #pragma unroll
            for (int g = 0; g < 2; g++) {
                uint32_t r0, r1, r2, r3;
                LDSM4(r0, r1, r2, r3, stB + brow_off[g] + koff);
                bh[2*g][0] = r0; bh[2*g+1][0] = r1; bh[2*g][1] = r2; bh[2*g+1][1] = r3;
            }
            #pragma unroll
            for (int mt = 0; mt < 4; mt++)
                #pragma unroll
                for (int nt = 0; nt < 4; nt++) {
                    float* d = acc[mt][nt];
                    mma16(d[0], d[1], d[2], d[3],
                          ah[mt][0], ah[mt][1], ah[mt][2], ah[mt][3], bh[nt][0], bh[nt][1]);
                }
        }
        __syncthreads();
    }

    #pragma unroll
    for (int mt = 0; mt < 4; mt++) {
        const int row = m0 + wm * 64 + mt * 16 + r;
        #pragma unroll
        for (int nt = 0; nt < 4; nt++) {
            const int col = n0 + wn * 32 + nt * 8 + 2 * c;
            if (col < Nreal) {
                *(float2*)&Cout[(size_t)row * Nreal + col] =
                    make_float2(acc[mt][nt][0], acc[mt][nt][1]);
                *(float2*)&Cout[(size_t)(row + 8) * Nreal + col] =
                    make_float2(acc[mt][nt][2], acc[mt][nt][3]);
            }
        }
    }
}

// ---------------- elementwise split: float -> (hi, lo) fp16 pair -------------
__global__ void split4h_kernel(const float* __restrict__ x,
                               __half* __restrict__ hi, __half* __restrict__ lo, int n4)
{
    int i = blockIdx.x * blockDim.x + threadIdx.x;
    if (i >= n4) return;
    float4 v = ((const float4*)x)[i];
    __half h0 = __float2half_rn(v.x), h1 = __float2half_rn(v.y);
    __half h2 = __float2half_rn(v.z), h3 = __float2half_rn(v.w);
    ((half2*)hi)[2*i]   = __halves2half2(h0, h1);
    ((half2*)hi)[2*i+1] = __halves2half2(h2, h3);
    ((half2*)lo)[2*i]   = __halves2half2(__float2half_rn(v.x - __half2float(h0)),
                                         __float2half_rn(v.y - __half2float(h1)));
    ((half2*)lo)[2*i+1] = __halves2half2(__float2half_rn(v.z - __half2float(h2)),
                                         __float2half_rn(v.w - __half2float(h3)));
}

// ---------------- transpose + split: W[K,N] -> Wt_hi(/lo)[Npad,K] fp16 -------
template<bool WLO>
__global__ void tsplit_kernel(const float* __restrict__ W,
                              __half* __restrict__ Thi, __half* __restrict__ Tlo,
                              int K, int N)
{
    __shared__ float t[32][33];
    const int n0 = blockIdx.x * 32, k0 = blockIdx.y * 32;
    const int tx = threadIdx.x, ty = threadIdx.y;
    #pragma unroll
    for (int r = 0; r < 4; r++) {
        int k = k0 + ty + r * 8, n = n0 + tx;
        t[ty + r * 8][tx] = (n < N) ? W[(size_t)k * N + n] : 0.f;
    }
    __syncthreads();
    #pragma unroll
    for (int r = 0; r < 4; r++) {
        int n = n0 + ty + r * 8, k = k0 + tx;
        float v = t[tx][ty + r * 8];
        __half h = __float2half_rn(v);
        Thi[(size_t)n * K + k] = h;
        if (WLO) Tlo[(size_t)n * K + k] = __float2half_rn(v - __half2float(h));
    }
}

// ---------------- dt: exact fp32 dt_raw + dtmod + softplus; stores dt, dt*A --
__global__ void __launch_bounds__(256) dt_kernel(
    const float* __restrict__ dte, const float* __restrict__ Wd,
    const float* __restrict__ bd,  const float* __restrict__ W_in,
    const float* __restrict__ dt_bias, const float* __restrict__ A_log)
{
    __shared__ float us[8][1024];
    const int row0 = blockIdx.x * 8;
    const int tid = threadIdx.x;
    for (int idx = tid; idx < 8 * 1024; idx += 256) {
        int r = idx >> 10, j = idx & 1023;
        us[r][j] = __half2float(g_uhi[(size_t)(row0 + r) * DM + j])
                 + __half2float(g_ulo[(size_t)(row0 + r) * DM + j]);
    }
    __syncthreads();
    const int r = tid >> 5, h = tid & 31;
    const int row = row0 + r;
    float s = bd[h];
    #pragma unroll 8
    for (int j = 0; j < DTIME; j++) s = fmaf(dte[(size_t)row * DTIME + j], Wd[j * NH + h], s);
    const float* wcol = W_in + (DI + CD) + h;
    float x0 = 0.f, x1 = 0.f, x2 = 0.f, x3 = 0.f;
    #pragma unroll 4
    for (int j = 0; j < DM; j += 4) {
        x0 = fmaf(us[r][j+0], wcol[(size_t)(j+0) * DIP], x0);
        x1 = fmaf(us[r][j+1], wcol[(size_t)(j+1) * DIP], x1);
        x2 = fmaf(us[r][j+2], wcol[(size_t)(j+2) * DIP], x2);
        x3 = fmaf(us[r][j+3], wcol[(size_t)(j+3) * DIP], x3);
    }
    float x = (x0 + x1) + (x2 + x3) + dt_bias[h] + s;
    float dt = (x > 20.f) ? x : log1pf(expf(x));
    float A  = -expf(A_log[h]);
    const int idx = row * NH + h;
    g_dt[idx]  = dt;
    g_dtA[idx] = dt * A;
}

// ---------------- causal conv (taps=4) + bias + silu -------------------------
__global__ void conv_kernel(const float* __restrict__ zx,
                            const float* __restrict__ conv_w,
                            const float* __restrict__ conv_b)
{
    int idx = blockIdx.x * blockDim.x + threadIdx.x;
    if (idx >= ROWS * CD) return;
    int c   = idx % CD;
    int row = idx / CD;
    int l   = row & (L_SZ - 1);
    int b   = row / L_SZ;
    float acc = conv_b[c];
    #pragma unroll
    for (int k = 0; k < DCONV; k++) {
        int ll = l - (DCONV - 1) + k;
        if (ll >= 0)
            acc = fmaf(zx[(size_t)(b*L_SZ + ll) * NGEMM2 + DI + c], conv_w[k*CD + c], acc);
    }
    g_xBCa[idx] = acc / (1.f + expf(-acc));
}

// ================= chunk_state: logcum/cumdec + Sfinal = Xw^T @ B ===========
// one CTA per (c,h,b). Sf[p,n] = sum_j dt_j*exp(lc_last - lc_j)*x_j[p]*B_j[n]
#define CS_SXTW 0
#define CS_SBT  (64*HS2*2)                 // 17408
#define CS_LCS  (CS_SBT + 128*HS2*2)       // 52224
#define CS_DTV  (CS_LCS + 512)
#define CS_WQ   (CS_DTV + 512)
#define CS_SMEM (CS_WQ + 512)              // 53760
__global__ void __launch_bounds__(256, 2) chunk_state_kernel()
{
    extern __shared__ __align__(16) char sm[];
    __half* sXTw = (__half*)(sm + CS_SXTW);
    __half* sBT  = (__half*)(sm + CS_SBT);
    float*  lcs  = (float*)(sm + CS_LCS);
    float*  dtv  = (float*)(sm + CS_DTV);
    float*  wq   = (float*)(sm + CS_WQ);
    const uint32_t sb = (uint32_t)__cvta_generic_to_shared(sm);

    const int c = blockIdx.x, h = blockIdx.y, b = blockIdx.z;
    const int t = threadIdx.x;
    const int l0 = c * CL;
    const int bh = b * NH + h;

    // stage B transposed: sBT[n][j] = B_j[n]
    for (int idx = t; idx < CL * DS; idx += 256) {
        int j = idx >> 7, n = idx & 127;
        float v = g_xBCa[(size_t)(b*L_SZ + l0 + j) * CD + DI + n];
        sBT[n * HS2 + j] = __float2half_rn(v);
    }
    if (t < CL) {
        dtv[t] = g_dt [(b*L_SZ + l0 + t) * NH + h];
        lcs[t] = g_dtA[(b*L_SZ + l0 + t) * NH + h];
    }
    __syncthreads();
    // inclusive prefix sum of lcs
    for (int off = 1; off < CL; off <<= 1) {
        float cur = 0.f, v = 0.f;
        if (t < CL) { cur = lcs[t]; if (t >= off) v = lcs[t - off]; }
        __syncthreads();
        if (t < CL) lcs[t] = cur + v;
        __syncthreads();
    }
    if (t < CL) {
        float lc = lcs[t];
        g_logcum[bh*L_SZ + l0 + t] = lc;
        g_cumdec[bh*L_SZ + l0 + t] = __expf(lc);
    }
    __syncthreads();
    const float lcL = lcs[CL - 1];
    if (t < CL) wq[t] = dtv[t] * __expf(lcL - lcs[t]);
    __syncthreads();
    // stage weighted X transposed: sXTw[p][j] = x_j[p]*wq[j]
    for (int idx = t; idx < CL * HD; idx += 256) {
        int j = idx >> 6, p = idx & 63;
        float v = g_xBCa[(size_t)(b*L_SZ + l0 + j) * CD + h*HD + p];
        sXTw[p * HS2 + j] = __float2half_rn(v * wq[j]);
    }
    __syncthreads();

    // GEMM: M=64 p (2 warps x32), N=128 n (4 warps x32), K=128 j
    const int wid = t >> 5, lane = t & 31;
    const int wm = wid & 1, wn = wid >> 1;
    const int r = lane >> 2, cc = lane & 3;
    const int lrow = lane & 15, lk16 = (lane >> 4) << 4;
    uint32_t aoff[2], boff[2];
    #pragma unroll
    for (int mt = 0; mt < 2; mt++)
        aoff[mt] = sb + CS_SXTW + (uint32_t)((wm*32 + mt*16 + lrow) * (HS2*2)) + (uint32_t)lk16;
    #pragma unroll
    for (int g = 0; g < 2; g++)
        boff[g] = sb + CS_SBT + (uint32_t)((wn*32 + g*16 + lrow) * (HS2*2)) + (uint32_t)lk16;

    float acc[2][4][4];
    #pragma unroll
    for (int i = 0; i < 2; i++)
        #pragma unroll
        for (int j = 0; j < 4; j++)
            #pragma unroll
            for (int q = 0; q < 4; q++) acc[i][j][q] = 0.f;

    #pragma unroll
    for (int kb = 0; kb < 8; kb++) {
        const uint32_t koff = (uint32_t)(kb << 5);
        uint32_t ah[2][4], bhf[4][2];
        #pragma unroll
        for (int mt = 0; mt < 2; mt++)
            LDSM4(ah[mt][0], ah[mt][1], ah[mt][2], ah[mt][3], aoff[mt] + koff);
        #pragma unroll
        for (int g = 0; g < 2; g++) {
            uint32_t r0, r1, r2, r3;
            LDSM4(r0, r1, r2, r3, boff[g] + koff);
            bhf[2*g][0] = r0; bhf[2*g+1][0] = r1; bhf[2*g][1] = r2; bhf[2*g+1][1] = r3;
        }
        #pragma unroll
        for (int mt = 0; mt < 2; mt++)
            #pragma unroll
            for (int nt = 0; nt < 4; nt++) {
                float* d = acc[mt][nt];
                mma16(d[0], d[1], d[2], d[3],
                      ah[mt][0], ah[mt][1], ah[mt][2], ah[mt][3], bhf[nt][0], bhf[nt][1]);
            }
    }
    const size_t sbase = ((size_t)bh * NC + c) * (HD * DS);
    #pragma unroll
    for (int mt = 0; mt < 2; mt++) {
        const int p0 = wm*32 + mt*16 + r;
        #pragma unroll
        for (int nt = 0; nt < 4; nt++) {
            const int n0 = wn*32 + nt*8 + 2*cc;
            *(float2*)&g_Sfinal[sbase + (size_t)p0 * DS + n0] =
                make_float2(acc[mt][nt][0], acc[mt][nt][1]);
            *(float2*)&g_Sfinal[sbase + (size_t)(p0+8) * DS + n0] =
                make_float2(acc[mt][nt][2], acc[mt][nt][3]);
        }
    }
}

// ---------------- phase B: sequential chunk-state combine --------------------
__global__ void phaseB_kernel()
{
    const int bh = blockIdx.x;
    const int e0 = blockIdx.y * 1024;
    const int t  = threadIdx.x;
    __shared__ float Ps[NC];
    if (t < NC) Ps[t] = g_cumdec[bh*L_SZ + t*CL + CL - 1];
    __syncthreads();
    for (int e = e0 + t; e < e0 + 1024; e += 256) {
        float hv = 0.f;
        for (int c = 0; c < NC; c++) {
            const size_t o = ((size_t)bh * NC + c) * (HD * DS) + e;
            g_Hinit[o] = hv;
            hv = fmaf(Ps[c], hv, g_Sfinal[o]);
        }
    }
}

// ================ chunk_out: Y = (CB^T o M o dt) @ X + cum*(C@H^T) + D*x =====
// one CTA per (c,h,b).
#define CO_SC   0
#define CO_SB   (128*HS2*2)                 // 34816
#define CO_SXT  (2*128*HS2*2)               // 69632
#define CO_SH   (CO_SXT + 64*HS2*2)         // 87040
#define CO_LC   (CO_SH + 64*HS2*2)          // 104448
#define CO_DT   (CO_LC + 512)
#define CO_SMEM (CO_DT + 512)               // 105472
__global__ void __launch_bounds__(256, 2) chunk_out_kernel(const float* __restrict__ Dvec)
{
    extern __shared__ __align__(16) char sm[];
    __half* sC  = (__half*)(sm + CO_SC);
    __half* sB  = (__half*)(sm + CO_SB);    // becomes sW after G
    __half* sXT = (__half*)(sm + CO_SXT);
    __half* sH  = (__half*)(sm + CO_SH);
    float*  lc  = (float*)(sm + CO_LC);
    float*  dtw = (float*)(sm + CO_DT);
    const uint32_t sb = (uint32_t)__cvta_generic_to_shared(sm);

    const int c = blockIdx.x, h = blockIdx.y, b = blockIdx.z;
    const int t = threadIdx.x;
    const int l0 = c * CL;
    const int bh = b * NH + h;
    const bool do_corr = (c != 0);

    // stage
    for (int idx = t; idx < CL * DS; idx += 256) {
        int l = idx >> 7, n = idx & 127;
        const float* base = g_xBCa + (size_t)(b*L_SZ + l0 + l) * CD;
        sC[l * HS2 + n] = __float2half_rn(base[DI + DS + n]);
        sB[l * HS2 + n] = __float2half_rn(base[DI + n]);
    }
    for (int idx = t; idx < CL * HD; idx += 256) {
        int l = idx >> 6, p = idx & 63;
        float v = g_xBCa[(size_t)(b*L_SZ + l0 + l) * CD + h*HD + p];
        sXT[p * HS2 + l] = __float2half_rn(v);
    }
    const size_t hbase = ((size_t)bh * NC + c) * (HD * DS);
    for (int idx = t; idx < HD * DS; idx += 256) {
        int p = idx >> 7, n = idx & 127;
        float v = do_corr ? g_Hinit[hbase + (size_t)p * DS + n] : 0.f;
        sH[p * HS2 + n] = __float2half_rn(v);
    }
    if (t < CL) {
        lc[t]  = g_logcum[bh*L_SZ + l0 + t];
        dtw[t] = g_dt[(b*L_SZ + l0 + t) * NH + h];
    }
    __syncthreads();

    const int wid = t >> 5, lane = t & 31;
    const int wm = wid & 3;        // l: 4 warps x 32
    const int wn = wid >> 2;       // j/p: 2 warps
    const int r = lane >> 2, cc = lane & 3;
    const int lrow = lane & 15, lk16 = (lane >> 4) << 4;

    uint32_t aoffC[2], aoffW[2], boffB[4], boffX[2], boffH[2];
    #pragma unroll
    for (int mt = 0; mt < 2; mt++) {
        uint32_t ro = (uint32_t)((wm*32 + mt*16 + lrow) * (HS2*2)) + (uint32_t)lk16;
        aoffC[mt] = sb + CO_SC + ro;
        aoffW[mt] = sb + CO_SB + ro;
    }
    #pragma unroll
    for (int g = 0; g < 4; g++)
        boffB[g] = sb + CO_SB + (uint32_t)((wn*64 + g*16 + lrow) * (HS2*2)) + (uint32_t)lk16;
    #pragma unroll
    for (int g = 0; g < 2; g++) {
        uint32_t ro = (uint32_t)((wn*32 + g*16 + lrow) * (HS2*2)) + (uint32_t)lk16;
        boffX[g] = sb + CO_SXT + ro;
        boffH[g] = sb + CO_SH + ro;
    }

    // ---- G = C @ B^T : M=128 l, N=128 j (warp: 32 x 64), K=128 n
    float G[2][8][4];
    #pragma unroll
    for (int i = 0; i < 2; i++)
        #pragma unroll
        for (int j = 0; j < 8; j++)
            #pragma unroll
            for (int q = 0; q < 4; q++) G[i][j][q] = 0.f;
    #pragma unroll
    for (int kb = 0; kb < 8; kb++) {
        const uint32_t koff = (uint32_t)(kb << 5);
        uint32_t ah[2][4], bhf[8][2];
        #pragma unroll
        for (int mt = 0; mt < 2; mt++)
            LDSM4(ah[mt][0], ah[mt][1], ah[mt][2], ah[mt][3], aoffC[mt] + koff);
        #pragma unroll
        for (int g = 0; g < 4; g++) {
            uint32_t r0, r1, r2, r3;
            LDSM4(r0, r1, r2, r3, boffB[g] + koff);
            bhf[2*g][0] = r0; bhf[2*g+1][0] = r1; bhf[2*g][1] = r2; bhf[2*g+1][1] = r3;
        }
        #pragma unroll
        for (int mt = 0; mt < 2; mt++)
            #pragma unroll
            for (int nt = 0; nt < 8; nt++) {
                float* d = G[mt][nt];
                mma16(d[0], d[1], d[2], d[3],
                      ah[mt][0], ah[mt][1], ah[mt][2], ah[mt][3], bhf[nt][0], bhf[nt][1]);
            }
    }
    __syncthreads();   // all B reads done; sB can be overwritten with W

    // ---- W[l][j] = G * dt_j * exp(lc_l - lc_j), causal mask
    __half* sW = sB;
    #pragma unroll
    for (int mt = 0; mt < 2; mt++) {
        const int lr0 = wm*32 + mt*16 + r;
        const int lr1 = lr0 + 8;
        const float lc0 = lc[lr0], lc1 = lc[lr1];
        #pragma unroll
        for (int nt = 0; nt < 8; nt++) {
            const int j0 = wn*64 + nt*8 + 2*cc;
            const int j1 = j0 + 1;
            const float dj0 = dtw[j0], dj1 = dtw[j1];
            const float lj0 = lc[j0], lj1 = lc[j1];
            float w00 = (j0 <= lr0) ? G[mt][nt][0] * dj0 * __expf(lc0 - lj0) : 0.f;
            float w01 = (j1 <= lr0) ? G[mt][nt][1] * dj1 * __expf(lc0 - lj1) : 0.f;
            float w10 = (j0 <= lr1) ? G[mt][nt][2] * dj0 * __expf(lc1 - lj0) : 0.f;
            float w11 = (j1 <= lr1) ? G[mt][nt][3] * dj1 * __expf(lc1 - lj1) : 0.f;
            *(half2*)&sW[lr0 * HS2 + j0] = __halves2half2(__float2half_rn(w00), __float2half_rn(w01));
            *(half2*)&sW[lr1 * HS2 + j0] = __halves2half2(__float2half_rn(w10), __float2half_rn(w11));
        }
    }
    __syncthreads();

    // ---- Y = W @ X^T : M=128 l, N=64 p (warp 32 x 32), K=128 j
    //      R = C @ H^T : same shape, K=128 n
    float Y[2][4][4], R[2][4][4];
    #pragma unroll
    for (int i = 0; i < 2; i++)
        #pragma unroll
        for (int j = 0; j < 4; j++)
            #pragma unroll
            for (int q = 0; q < 4; q++) { Y[i][j][q] = 0.f; R[i][j][q] = 0.f; }
    #pragma unroll
    for (int kb = 0; kb < 8; kb++) {
        const uint32_t koff = (uint32_t)(kb << 5);
        uint32_t ah[2][4], bhf[4][2];
        #pragma unroll
        for (int mt = 0; mt < 2; mt++)
            LDSM4(ah[mt][0], ah[mt][1], ah[mt][2], ah[mt][3], aoffW[mt] + koff);
        #pragma unroll
        for (int g = 0; g < 2; g++) {
            uint32_t r0, r1, r2, r3;
            LDSM4(r0, r1, r2, r3, boffX[g] + koff);
            bhf[2*g][0] = r0; bhf[2*g+1][0] = r1; bhf[2*g][1] = r2; bhf[2*g+1][1] = r3;
        }
        #pragma unroll
        for (int mt = 0; mt < 2; mt++)
            #pragma unroll
            for (int nt = 0; nt < 4; nt++) {
                float* d = Y[mt][nt];
                mma16(d[0], d[1], d[2], d[3],
                      ah[mt][0], ah[mt][1], ah[mt][2], ah[mt][3], bhf[nt][0], bhf[nt][1]);
            }
    }
    if (do_corr) {
        #pragma unroll
        for (int kb = 0; kb < 8; kb++) {
            const uint32_t koff = (uint32_t)(kb << 5);
            uint32_t ah[2][4], bhf[4][2];
            #pragma unroll
            for (int mt = 0; mt < 2; mt++)
                LDSM4(ah[mt][0], ah[mt][1], ah[mt][2], ah[mt][3], aoffC[mt] + koff);
            #pragma unroll
            for (int g = 0; g < 2; g++) {
                uint32_t r0, r1, r2, r3;
                LDSM4(r0, r1, r2, r3, boffH[g] + koff);
                bhf[2*g][0] = r0; bhf[2*g+1][0] = r1; bhf[2*g][1] = r2; bhf[2*g+1][1] = r3;
            }
            #pragma unroll
            for (int mt = 0; mt < 2; mt++)
                #pragma unroll
                for (int nt = 0; nt < 4; nt++) {
                    float* d = R[mt][nt];
                    mma16(d[0], d[1], d[2], d[3],
                          ah[mt][0], ah[mt][1], ah[mt][2], ah[mt][3], bhf[nt][0], bhf[nt][1]);
                }
        }
    }

    // ---- epilogue: y = Y + exp(lc_l)*R + D*x
    const float Dh = Dvec[h];
    #pragma unroll
    for (int mt = 0; mt < 2; mt++) {
        #pragma unroll
        for (int half = 0; half < 2; half++) {
            const int lrw = wm*32 + mt*16 + r + half*8;
            const float cum = __expf(lc[lrw]);
            const size_t grow = (size_t)(b*L_SZ + l0 + lrw);
            #pragma unroll
            for (int nt = 0; nt < 4; nt++) {
                const int p0 = wn*32 + nt*8 + 2*cc;
                float2 xv = *(const float2*)&g_xBCa[grow * CD + h*HD + p0];
                float y0 = Y[mt][nt][2*half+0] + cum * R[mt][nt][2*half+0] + Dh * xv.x;
                float y1 = Y[mt][nt][2*half+1] + cum * R[mt][nt][2*half+1] + Dh * xv.y;
                *(float2*)&g_y[grow * DI + h*HD + p0] = make_float2(y0, y1);
            }
        }
    }
}

// ---------------- gating (silu(z)) + RMS norm -> fp16 hi ---------------------
__global__ void __launch_bounds__(256) epilogue_kernel(const float* __restrict__ norm_w)
{
    const int row = blockIdx.x;
    const int t   = threadIdx.x;
    float gv[8];
    float ss = 0.f;
    #pragma unroll
    for (int i = 0; i < 8; i++) {
        int cidx = t + i * 256;
        float yv = g_y[(size_t)row * DI + cidx];
        float zv = g_zx[(size_t)row * NGEMM2 + cidx];
        float sil = zv / (1.f + expf(-zv));
        float v = yv * sil;
        gv[i] = v;
        ss += v * v;
    }
    __shared__ float rs[32];
    #pragma unroll
    for (int o = 16; o; o >>= 1) ss += __shfl_xor_sync(~0u, ss, o);
    if ((t & 31) == 0) rs[t >> 5] = ss;
    __syncthreads();
    if (t < 32) {
        float v = (t < 8) ? rs[t] : 0.f;
        #pragma unroll
        for (int o = 4; o; o >>= 1) v += __shfl_xor_sync(~0u, v, o);
        if (t == 0) rs[0] = v;
    }
    __syncthreads();
    float scale = rsqrtf(rs[0] / (float)DI + EPSV);
    #pragma unroll
    for (int i = 0; i < 8; i++) {
        int cidx = t + i * 256;
        float v = gv[i] * scale * norm_w[cidx];
        g_yhi[(size_t)row * DI + cidx] = __float2half_rn(v);
    }
}

// ---------------- launch ----------------
extern "C" void kernel_launch(void* const* d_in, const int* in_sizes, int n_in,
                              void* d_out, int out_size)
{
    const float* hidden  = (const float*)d_in[0];
    const float* dte     = (const float*)d_in[1];
    const float* W_proj  = (const float*)d_in[2];
    const float* b_proj  = (const float*)d_in[3];
    const float* W_dtmod = (const float*)d_in[4];
    const float* b_dtmod = (const float*)d_in[5];
    const float* W_in    = (const float*)d_in[6];
    const float* conv_w  = (const float*)d_in[7];
    const float* conv_b  = (const float*)d_in[8];
    const float* dt_bias = (const float*)d_in[9];
    const float* A_log   = (const float*)d_in[10];
    const float* Dvec    = (const float*)d_in[11];
    const float* norm_w  = (const float*)d_in[12];
    const float* W_out   = (const float*)d_in[13];
    float* out = (float*)d_out;

    float *p_zx;
    __half *p_uhi, *p_ulo, *p_yhi, *p_hhi, *p_hlo;
    __half *p_wpt_hi, *p_wpt_lo, *p_wit_hi, *p_wot_hi;
    cudaGetSymbolAddress((void**)&p_uhi, g_uhi);
    cudaGetSymbolAddress((void**)&p_ulo, g_ulo);
    cudaGetSymbolAddress((void**)&p_zx,  g_zx);
    cudaGetSymbolAddress((void**)&p_yhi, g_yhi);
    cudaGetSymbolAddress((void**)&p_hhi, g_hhi);
    cudaGetSymbolAddress((void**)&p_hlo, g_hlo);
    cudaGetSymbolAddress((void**)&p_wpt_hi, g_wpt_hi);
    cudaGetSymbolAddress((void**)&p_wpt_lo, g_wpt_lo);
    cudaGetSymbolAddress((void**)&p_wit_hi, g_wit_hi);
    cudaGetSymbolAddress((void**)&p_wot_hi, g_wot_hi);

    cudaFuncSetAttribute(gemm_h3, cudaFuncAttributeMaxDynamicSharedMemorySize, SMEM3P);
    cudaFuncSetAttribute(gemm_h1, cudaFuncAttributeMaxDynamicSharedMemorySize, SMEM1P);
    cudaFuncSetAttribute(chunk_state_kernel, cudaFuncAttributeMaxDynamicSharedMemorySize, CS_SMEM);
    cudaFuncSetAttribute(chunk_out_kernel,   cudaFuncAttributeMaxDynamicSharedMemorySize, CO_SMEM);

    // 0) operand prep
    split4h_kernel<<<(ROWS*DM/4 + 255)/256, 256>>>(hidden, p_hhi, p_hlo, ROWS*DM/4);
    tsplit_kernel<true ><<<dim3(DM/32,  DM/32), dim3(32,8)>>>(W_proj, p_wpt_hi, p_wpt_lo, DM, DM);
    tsplit_kernel<false><<<dim3(DIPPAD/32, DM/32), dim3(32,8)>>>(W_in,  p_wit_hi, nullptr, DM, DIP);
    tsplit_kernel<false><<<dim3(DM/32,  DI/32), dim3(32,8)>>>(W_out, p_wot_hi, nullptr, DI, DM);

    // 1) u = hidden @ W_proj + b_proj   (3-pass; split fp16 output)
    gemm_h3<<<dim3(DM/128, ROWS/128), 512, SMEM3P>>>(
        p_hhi, p_hlo, p_wpt_hi, p_wpt_lo, b_proj, p_uhi, p_ulo, ROWS, DM, DM);

    // 2) zxbcdt[:, :4352] = u @ W_in   (1-pass)
    gemm_h1<<<dim3(NGEMM2/128, ROWS/128), 256, SMEM1P>>>(
        p_uhi, p_wit_hi, p_zx, ROWS, NGEMM2, DM);

    // 3) dt exact (stores dt and dt*A)
    dt_kernel<<<ROWS/8, 256>>>(dte, W_dtmod, b_dtmod, W_in, dt_bias, A_log);

    // 4) conv + silu
    conv_kernel<<<(ROWS*CD + 255)/256, 256>>>(p_zx, conv_w, conv_b);

    // 5) chunked scan in matmul form (tensor-core)
    chunk_state_kernel<<<dim3(NC, NH, B_SZ), 256, CS_SMEM>>>();
    phaseB_kernel<<<dim3(B_SZ*NH, 8), 256>>>();
    chunk_out_kernel<<<dim3(NC, NH, B_SZ), 256, CO_SMEM>>>(Dvec);

    // 6) gating + RMS norm
    epilogue_kernel<<<ROWS, 256>>>(norm_w);

    // 7) out = yn @ W_out   (1-pass)
    gemm_h1<<<dim3(DM/128, ROWS/128), 256, SMEM1P>>>(
        p_yhi, p_wot_hi, out, ROWS, DM, DI);
}

// round 11
// speedup vs baseline: 4.4971x; 1.0482x over previous
#include <cuda_runtime.h>
#include <cuda_fp16.h>
#include <cuda_bf16.h>
#include <cstdint>

// ---------------- problem constants ----------------
#define B_SZ   2
#define L_SZ   2048
#define DM     1024      // d_model
#define DI     2048      // d_inner
#define DS     128       // d_state
#define DCONV  4
#define NH     32        // nheads
#define HD     64        // headdim
#define DTIME  64
#define CD     (DI + 2*DS)            // 2304 conv dim
#define DIP    (2*DI + 2*DS + NH)     // 4384 in-proj dim
#define DIPPAD 4480                   // 35*128
#define NGEMM2 4352                   // 34*128 = DI+CD (z,xBC cols only)
#define ROWS   (B_SZ*L_SZ)            // 4096
#define NC     16                     // scan chunks
#define CL     (L_SZ/NC)              // 128 chunk len
#define EPSV   1e-5f

// ---------------- scratch (device globals; no allocs allowed) ----------------
__device__ __half g_uhi[ROWS*DM], g_ulo[ROWS*DM];
__device__ __half g_zxh[ROWS*NGEMM2];      // GEMM2 output (z + xBC pre-conv), fp16
__device__ __half g_xBCh[ROWS*CD];         // conv+silu output, fp16
__device__ float  g_dt[ROWS*NH];
__device__ float  g_dtA[ROWS*NH];
__device__ float  g_cumdec[B_SZ*NH*L_SZ];
__device__ float  g_logcum[B_SZ*NH*L_SZ];
__device__ float  g_Sfinal[B_SZ*NH*NC*HD*DS];
__device__ float  g_Hinit [B_SZ*NH*NC*HD*DS];
__device__ float  g_y[ROWS*DI];
__device__ __half g_yhi[ROWS*DI];
__device__ __half g_hhi[ROWS*DM], g_hlo[ROWS*DM];
__device__ __half g_wpt_hi[DM*DM], g_wpt_lo[DM*DM];   // W_proj^T  [1024][1024]
__device__ __half g_wit_hi[DIPPAD*DM];                // W_in^T    [4480][1024] (hi only)
__device__ __half g_wot_hi[DM*DI];                    // W_out^T   [1024][2048] (hi only)

// ---------------- mma / ldmatrix helpers ----------------
__device__ __forceinline__ void mma16(float& d0, float& d1, float& d2, float& d3,
                                      uint32_t a0, uint32_t a1, uint32_t a2, uint32_t a3,
                                      uint32_t b0, uint32_t b1)
{
    asm volatile("mma.sync.aligned.m16n8k16.row.col.f32.f16.f16.f32 "
        "{%0,%1,%2,%3},{%4,%5,%6,%7},{%8,%9},{%0,%1,%2,%3};"
        : "+f"(d0), "+f"(d1), "+f"(d2), "+f"(d3)
        : "r"(a0), "r"(a1), "r"(a2), "r"(a3), "r"(b0), "r"(b1));
}
#define LDSM4(r0,r1,r2,r3, addr) \
    asm volatile("ldmatrix.sync.aligned.m8n8.x4.shared.b16 {%0,%1,%2,%3}, [%4];" \
        : "=r"(r0), "=r"(r1), "=r"(r2), "=r"(r3) : "r"(addr))

// smem geometry (GEMMs): rows of 64 halfs padded to 72 (144B stride)
#define HSTRIDE 72
#define TBYTES  (128 * HSTRIDE * 2)       // 18432 bytes per tensor per stage
#define STAGEB3 (4 * TBYTES)
#define SMEM3P  (2 * STAGEB3)             // 147456
#define STAGEB1 (2 * TBYTES)
#define SMEM1P  (2 * STAGEB1)             // 73728 -> 2 CTAs/SM

// scan-tile smem geometry: rows of 128 halfs padded to 136
#define HS2 136

// ============ 3-pass split-FP16 GEMM (GEMM1 only) ============================
__global__ void __launch_bounds__(512, 1) gemm_h3(
    const __half* __restrict__ Ahi, const __half* __restrict__ Alo,
    const __half* __restrict__ Bhi, const __half* __restrict__ Blo,
    const float* __restrict__ bias,
    __half* __restrict__ Hout, __half* __restrict__ Lout,
    int M, int Nreal, int K)
{
    extern __shared__ __align__(16) char smem[];
    const uint32_t sb = (uint32_t)__cvta_generic_to_shared(smem);
    const int tid = threadIdx.x;
    const int wid = tid >> 5;
    const int lane = tid & 31;
    const int wm = wid & 3;
    const int wn = wid >> 2;
    const int r = lane >> 2;
    const int c = lane & 3;
    const int m0 = blockIdx.y << 7;
    const int n0 = blockIdx.x << 7;
    const int nsteps = K >> 6;

    const int t4   = tid >> 7;
    const int l128 = tid & 127;
    const __half* gsel = (t4 == 0) ? Ahi : (t4 == 1) ? Alo : (t4 == 2) ? Bhi : Blo;
    const int rb = (t4 < 2) ? m0 : n0;

    auto load_stage = [&](int kstep, int s) {
        const int k0 = kstep << 6;
        const __half* gb = gsel + (size_t)rb * K + k0;
        const uint32_t tb = sb + (uint32_t)(s * STAGEB3 + t4 * TBYTES);
        #pragma unroll
        for (int j = 0; j < 8; j++) {
            int q = j * 128 + l128;
            int row = q >> 3, col = q & 7;
            const __half* gp = gb + (size_t)row * K + (col << 3);
            uint32_t sa = tb + (uint32_t)(row * (HSTRIDE * 2) + (col << 4));
            asm volatile("cp.async.cg.shared.global [%0], [%1], 16;" :: "r"(sa), "l"(gp) : "memory");
        }
        asm volatile("cp.async.commit_group;" ::: "memory");
    };

    float acc[2][4][4];
    #pragma unroll
    for (int i = 0; i < 2; i++)
        #pragma unroll
        for (int j = 0; j < 4; j++)
            #pragma unroll
            for (int q = 0; q < 4; q++) acc[i][j][q] = 0.f;

    const int lrow = lane & 15;
    const int lk16 = (lane >> 4) << 4;
    uint32_t arow_off[2], brow_off[2];
    #pragma unroll
    for (int mt = 0; mt < 2; mt++)
        arow_off[mt] = (uint32_t)((wm * 32 + mt * 16 + lrow) * (HSTRIDE * 2)) + (uint32_t)lk16;
    #pragma unroll
    for (int g = 0; g < 2; g++)
        brow_off[g] = (uint32_t)((wn * 32 + g * 16 + lrow) * (HSTRIDE * 2)) + (uint32_t)lk16;

    load_stage(0, 0);

    for (int i = 0; i < nsteps; i++) {
        if (i + 1 < nsteps) {
            load_stage(i + 1, (i + 1) & 1);
            asm volatile("cp.async.wait_group 1;" ::: "memory");
        } else {
            asm volatile("cp.async.wait_group 0;" ::: "memory");
        }
        __syncthreads();

        const int s = i & 1;
        const uint32_t stA_hi = sb + (uint32_t)(s * STAGEB3);
        const uint32_t stA_lo = stA_hi + TBYTES;
        const uint32_t stB_hi = stA_hi + 2 * TBYTES;
        const uint32_t stB_lo = stA_hi + 3 * TBYTES;

        #pragma unroll
        for (int kb = 0; kb < 4; kb++) {
            const uint32_t koff = (uint32_t)(kb << 5);
            uint32_t ah[2][4], al[2][4], bh[4][2], bl[4][2];
            #pragma unroll
            for (int mt = 0; mt < 2; mt++) {
                LDSM4(ah[mt][0], ah[mt][1], ah[mt][2], ah[mt][3], stA_hi + arow_off[mt] + koff);
                LDSM4(al[mt][0], al[mt][1], al[mt][2], al[mt][3], stA_lo + arow_off[mt] + koff);
            }
            #pragma unroll
            for (int g = 0; g < 2; g++) {
                uint32_t r0, r1, r2, r3;
                LDSM4(r0, r1, r2, r3, stB_hi + brow_off[g] + koff);
                bh[2*g][0] = r0; bh[2*g+1][0] = r1; bh[2*g][1] = r2; bh[2*g+1][1] = r3;
                LDSM4(r0, r1, r2, r3, stB_lo + brow_off[g] + koff);
                bl[2*g][0] = r0; bl[2*g+1][0] = r1; bl[2*g][1] = r2; bl[2*g+1][1] = r3;
            }
            #pragma unroll
            for (int mt = 0; mt < 2; mt++)
                #pragma unroll
                for (int nt = 0; nt < 4; nt++) {
                    float* d = acc[mt][nt];
                    mma16(d[0], d[1], d[2], d[3],
                          ah[mt][0], ah[mt][1], ah[mt][2], ah[mt][3], bh[nt][0], bh[nt][1]);
                    mma16(d[0], d[1], d[2], d[3],
                          al[mt][0], al[mt][1], al[mt][2], al[mt][3], bh[nt][0], bh[nt][1]);
                    mma16(d[0], d[1], d[2], d[3],
                          ah[mt][0], ah[mt][1], ah[mt][2], ah[mt][3], bl[nt][0], bl[nt][1]);
                }
        }
        __syncthreads();
    }

    #pragma unroll
    for (int mt = 0; mt < 2; mt++) {
        const int row = m0 + wm * 32 + mt * 16 + r;
        #pragma unroll
        for (int nt = 0; nt < 4; nt++) {
            const int col = n0 + wn * 32 + nt * 8 + 2 * c;
            if (col < Nreal) {
                float v0 = acc[mt][nt][0] + bias[col], v1 = acc[mt][nt][1] + bias[col+1];
                float v2 = acc[mt][nt][2] + bias[col], v3 = acc[mt][nt][3] + bias[col+1];
                __half h0 = __float2half_rn(v0), h1 = __float2half_rn(v1);
                __half h2 = __float2half_rn(v2), h3 = __float2half_rn(v3);
                *(half2*)&Hout[(size_t)row * Nreal + col]       = __halves2half2(h0, h1);
                *(half2*)&Hout[(size_t)(row + 8) * Nreal + col] = __halves2half2(h2, h3);
                *(half2*)&Lout[(size_t)row * Nreal + col] =
                    __halves2half2(__float2half_rn(v0 - __half2float(h0)),
                                   __float2half_rn(v1 - __half2float(h1)));
                *(half2*)&Lout[(size_t)(row + 8) * Nreal + col] =
                    __halves2half2(__float2half_rn(v2 - __half2float(h2)),
                                   __float2half_rn(v3 - __half2float(h3)));
            }
        }
    }
}

// ============ 1-pass FP16 GEMM (GEMM2/3; 2 tensors, 2 CTAs/SM) ===============
// HOUT: write fp16 output (GEMM2); else fp32 (GEMM3 -> out).
template<bool HOUT>
__global__ void __launch_bounds__(256, 2) gemm_h1(
    const __half* __restrict__ Ahi, const __half* __restrict__ Bhi,
    float* __restrict__ Cout, __half* __restrict__ HoutP,
    int M, int Nreal, int K)
{
    extern __shared__ __align__(16) char smem[];
    const uint32_t sb = (uint32_t)__cvta_generic_to_shared(smem);
    const int tid = threadIdx.x;
    const int wid = tid >> 5;
    const int lane = tid & 31;
    const int wm = wid & 1;
    const int wn = wid >> 1;
    const int r = lane >> 2;
    const int c = lane & 3;
    const int m0 = blockIdx.y << 7;
    const int n0 = blockIdx.x << 7;
    const int nsteps = K >> 6;

    auto load_stage = [&](int kstep, int s) {
        const int k0 = kstep << 6;
        #pragma unroll
        for (int j = 0; j < 8; j++) {
            const int t = j >> 2;
            const __half* gsel = (t == 0) ? Ahi : Bhi;
            const int rb = (t == 0) ? m0 : n0;
            int rem = ((j & 3) << 8) + tid;
            int row = rem >> 3, col = rem & 7;
            const __half* gp = gsel + (size_t)(rb + row) * K + k0 + (col << 3);
            uint32_t sa = sb + (uint32_t)(s * STAGEB1 + t * TBYTES + row * (HSTRIDE * 2) + (col << 4));
            asm volatile("cp.async.cg.shared.global [%0], [%1], 16;" :: "r"(sa), "l"(gp) : "memory");
        }
        asm volatile("cp.async.commit_group;" ::: "memory");
    };

    float acc[4][4][4];
    #pragma unroll
    for (int i = 0; i < 4; i++)
        #pragma unroll
        for (int j = 0; j < 4; j++)
            #pragma unroll
            for (int q = 0; q < 4; q++) acc[i][j][q] = 0.f;

    const int lrow = lane & 15;
    const int lk16 = (lane >> 4) << 4;
    uint32_t arow_off[4], brow_off[2];
    #pragma unroll
    for (int mt = 0; mt < 4; mt++)
        arow_off[mt] = (uint32_t)((wm * 64 + mt * 16 + lrow) * (HSTRIDE * 2)) + (uint32_t)lk16;
    #pragma unroll
    for (int g = 0; g < 2; g++)
        brow_off[g] = (uint32_t)((wn * 32 + g * 16 + lrow) * (HSTRIDE * 2)) + (uint32_t)lk16;

    load_stage(0, 0);

    for (int i = 0; i < nsteps; i++) {
        if (i + 1 < nsteps) {
            load_stage(i + 1, (i + 1) & 1);
            asm volatile("cp.async.wait_group 1;" ::: "memory");
        } else {
            asm volatile("cp.async.wait_group 0;" ::: "memory");
        }
        __syncthreads();

        const int s = i & 1;
        const uint32_t stA = sb + (uint32_t)(s * STAGEB1);
        const uint32_t stB = stA + TBYTES;

        #pragma unroll
        for (int kb = 0; kb < 4; kb++) {
            const uint32_t koff = (uint32_t)(kb << 5);
            uint32_t ah[4][4], bh[4][2];
            #pragma unroll
            for (int mt = 0; mt < 4; mt++)
                LDSM4(ah[mt][0], ah[mt][1], ah[mt][2], ah[mt][3], stA + arow_off[mt] + koff);
            #pragma unroll
            for (int g = 0; g < 2; g++) {
                uint32_t r0, r1, r2, r3;
                LDSM4(r0, r1, r2, r3, stB + brow_off[g] + koff);
                bh[2*g][0] = r0; bh[2*g+1][0] = r1; bh[2*g][1] = r2; bh[2*g+1][1] = r3;
            }
            #pragma unroll
            for (int mt = 0; mt < 4; mt++)
                #pragma unroll
                for (int nt = 0; nt < 4; nt++) {
                    float* d = acc[mt][nt];
                    mma16(d[0], d[1], d[2], d[3],
                          ah[mt][0], ah[mt][1], ah[mt][2], ah[mt][3], bh[nt][0], bh[nt][1]);
                }
        }
        __syncthreads();
    }

    #pragma unroll
    for (int mt = 0; mt < 4; mt++) {
        const int row = m0 + wm * 64 + mt * 16 + r;
        #pragma unroll
        for (int nt = 0; nt < 4; nt++) {
            const int col = n0 + wn * 32 + nt * 8 + 2 * c;
            if (col < Nreal) {
                if (HOUT) {
                    *(half2*)&HoutP[(size_t)row * Nreal + col] =
                        __halves2half2(__float2half_rn(acc[mt][nt][0]), __float2half_rn(acc[mt][nt][1]));
                    *(half2*)&HoutP[(size_t)(row + 8) * Nreal + col] =
                        __halves2half2(__float2half_rn(acc[mt][nt][2]), __float2half_rn(acc[mt][nt][3]));
                } else {
                    *(float2*)&Cout[(size_t)row * Nreal + col] =
                        make_float2(acc[mt][nt][0], acc[mt][nt][1]);
                    *(float2*)&Cout[(size_t)(row + 8) * Nreal + col] =
                        make_float2(acc[mt][nt][2], acc[mt][nt][3]);
                }
            }
        }
    }
}

// ---------------- elementwise split: float -> (hi, lo) fp16 pair -------------
__global__ void split4h_kernel(const float* __restrict__ x,
                               __half* __restrict__ hi, __half* __restrict__ lo, int n4)
{
    int i = blockIdx.x * blockDim.x + threadIdx.x;
    if (i >= n4) return;
    float4 v = ((const float4*)x)[i];
    __half h0 = __float2half_rn(v.x), h1 = __float2half_rn(v.y);
    __half h2 = __float2half_rn(v.z), h3 = __float2half_rn(v.w);
    ((half2*)hi)[2*i]   = __halves2half2(h0, h1);
    ((half2*)hi)[2*i+1] = __halves2half2(h2, h3);
    ((half2*)lo)[2*i]   = __halves2half2(__float2half_rn(v.x - __half2float(h0)),
                                         __float2half_rn(v.y - __half2float(h1)));
    ((half2*)lo)[2*i+1] = __halves2half2(__float2half_rn(v.z - __half2float(h2)),
                                         __float2half_rn(v.w - __half2float(h3)));
}

// ---------------- transpose + split: W[K,N] -> Wt_hi(/lo)[Npad,K] fp16 -------
template<bool WLO>
__global__ void tsplit_kernel(const float* __restrict__ W,
                              __half* __restrict__ Thi, __half* __restrict__ Tlo,
                              int K, int N)
{
    __shared__ float t[32][33];
    const int n0 = blockIdx.x * 32, k0 = blockIdx.y * 32;
    const int tx = threadIdx.x, ty = threadIdx.y;
    #pragma unroll
    for (int r = 0; r < 4; r++) {
        int k = k0 + ty + r * 8, n = n0 + tx;
        t[ty + r * 8][tx] = (n < N) ? W[(size_t)k * N + n] : 0.f;
    }
    __syncthreads();
    #pragma unroll
    for (int r = 0; r < 4; r++) {
        int n = n0 + ty + r * 8, k = k0 + tx;
        float v = t[tx][ty + r * 8];
        __half h = __float2half_rn(v);
        Thi[(size_t)n * K + k] = h;
        if (WLO) Tlo[(size_t)n * K + k] = __float2half_rn(v - __half2float(h));
    }
}

// ---------------- dt: exact fp32 dt_raw + dtmod + softplus; stores dt, dt*A --
__global__ void __launch_bounds__(256) dt_kernel(
    const float* __restrict__ dte, const float* __restrict__ Wd,
    const float* __restrict__ bd,  const float* __restrict__ W_in,
    const float* __restrict__ dt_bias, const float* __restrict__ A_log)
{
    __shared__ float us[8][1024];
    const int row0 = blockIdx.x * 8;
    const int tid = threadIdx.x;
    for (int idx = tid; idx < 8 * 1024; idx += 256) {
        int r = idx >> 10, j = idx & 1023;
        us[r][j] = __half2float(g_uhi[(size_t)(row0 + r) * DM + j])
                 + __half2float(g_ulo[(size_t)(row0 + r) * DM + j]);
    }
    __syncthreads();
    const int r = tid >> 5, h = tid & 31;
    const int row = row0 + r;
    float s = bd[h];
    #pragma unroll 8
    for (int j = 0; j < DTIME; j++) s = fmaf(dte[(size_t)row * DTIME + j], Wd[j * NH + h], s);
    const float* wcol = W_in + (DI + CD) + h;
    float x0 = 0.f, x1 = 0.f, x2 = 0.f, x3 = 0.f;
    #pragma unroll 4
    for (int j = 0; j < DM; j += 4) {
        x0 = fmaf(us[r][j+0], wcol[(size_t)(j+0) * DIP], x0);
        x1 = fmaf(us[r][j+1], wcol[(size_t)(j+1) * DIP], x1);
        x2 = fmaf(us[r][j+2], wcol[(size_t)(j+2) * DIP], x2);
        x3 = fmaf(us[r][j+3], wcol[(size_t)(j+3) * DIP], x3);
    }
    float x = (x0 + x1) + (x2 + x3) + dt_bias[h] + s;
    float dt = (x > 20.f) ? x : log1pf(expf(x));
    float A  = -expf(A_log[h]);
    const int idx = row * NH + h;
    g_dt[idx]  = dt;
    g_dtA[idx] = dt * A;
}

// ---------------- causal conv (taps=4) + bias + silu; fp16 in/out ------------
__global__ void conv_kernel(const float* __restrict__ conv_w,
                            const float* __restrict__ conv_b)
{
    int idx = blockIdx.x * blockDim.x + threadIdx.x;
    if (idx >= ROWS * CD) return;
    int c   = idx % CD;
    int row = idx / CD;
    int l   = row & (L_SZ - 1);
    int b   = row / L_SZ;
    float acc = conv_b[c];
    #pragma unroll
    for (int k = 0; k < DCONV; k++) {
        int ll = l - (DCONV - 1) + k;
        if (ll >= 0)
            acc = fmaf(__half2float(g_zxh[(size_t)(b*L_SZ + ll) * NGEMM2 + DI + c]),
                       conv_w[k*CD + c], acc);
    }
    g_xBCh[idx] = __float2half_rn(acc / (1.f + expf(-acc)));
}

// ================= chunk_state: logcum/cumdec + Sfinal = Xw^T @ B ===========
#define CS_SXTW 0
#define CS_SBT  (64*HS2*2)                 // 17408
#define CS_LCS  (CS_SBT + 128*HS2*2)       // 52224
#define CS_DTV  (CS_LCS + 512)
#define CS_WQ   (CS_DTV + 512)
#define CS_SMEM (CS_WQ + 512)              // 53760
__global__ void __launch_bounds__(256, 2) chunk_state_kernel()
{
    extern __shared__ __align__(16) char sm[];
    __half* sXTw = (__half*)(sm + CS_SXTW);
    __half* sBT  = (__half*)(sm + CS_SBT);
    float*  lcs  = (float*)(sm + CS_LCS);
    float*  dtv  = (float*)(sm + CS_DTV);
    float*  wq   = (float*)(sm + CS_WQ);
    const uint32_t sb = (uint32_t)__cvta_generic_to_shared(sm);

    const int c = blockIdx.x, h = blockIdx.y, b = blockIdx.z;
    const int t = threadIdx.x;
    const int l0 = c * CL;
    const int bh = b * NH + h;

    // stage B transposed: sBT[n][j] = B_j[n]  (fp16 direct)
    for (int idx = t; idx < CL * DS; idx += 256) {
        int j = idx >> 7, n = idx & 127;
        sBT[n * HS2 + j] = g_xBCh[(size_t)(b*L_SZ + l0 + j) * CD + DI + n];
    }
    if (t < CL) {
        dtv[t] = g_dt [(b*L_SZ + l0 + t) * NH + h];
        lcs[t] = g_dtA[(b*L_SZ + l0 + t) * NH + h];
    }
    __syncthreads();
    for (int off = 1; off < CL; off <<= 1) {
        float cur = 0.f, v = 0.f;
        if (t < CL) { cur = lcs[t]; if (t >= off) v = lcs[t - off]; }
        __syncthreads();
        if (t < CL) lcs[t] = cur + v;
        __syncthreads();
    }
    if (t < CL) {
        float lc = lcs[t];
        g_logcum[bh*L_SZ + l0 + t] = lc;
        g_cumdec[bh*L_SZ + l0 + t] = __expf(lc);
    }
    __syncthreads();
    const float lcL = lcs[CL - 1];
    if (t < CL) wq[t] = dtv[t] * __expf(lcL - lcs[t]);
    __syncthreads();
    for (int idx = t; idx < CL * HD; idx += 256) {
        int j = idx >> 6, p = idx & 63;
        float v = __half2float(g_xBCh[(size_t)(b*L_SZ + l0 + j) * CD + h*HD + p]);
        sXTw[p * HS2 + j] = __float2half_rn(v * wq[j]);
    }
    __syncthreads();

    const int wid = t >> 5, lane = t & 31;
    const int wm = wid & 1, wn = wid >> 1;
    const int r = lane >> 2, cc = lane & 3;
    const int lrow = lane & 15, lk16 = (lane >> 4) << 4;
    uint32_t aoff[2], boff[2];
    #pragma unroll
    for (int mt = 0; mt < 2; mt++)
        aoff[mt] = sb + CS_SXTW + (uint32_t)((wm*32 + mt*16 + lrow) * (HS2*2)) + (uint32_t)lk16;
    #pragma unroll
    for (int g = 0; g < 2; g++)
        boff[g] = sb + CS_SBT + (uint32_t)((wn*32 + g*16 + lrow) * (HS2*2)) + (uint32_t)lk16;

    float acc[2][4][4];
    #pragma unroll
    for (int i = 0; i < 2; i++)
        #pragma unroll
        for (int j = 0; j < 4; j++)
            #pragma unroll
            for (int q = 0; q < 4; q++) acc[i][j][q] = 0.f;

    #pragma unroll
    for (int kb = 0; kb < 8; kb++) {
        const uint32_t koff = (uint32_t)(kb << 5);
        uint32_t ah[2][4], bhf[4][2];
        #pragma unroll
        for (int mt = 0; mt < 2; mt++)
            LDSM4(ah[mt][0], ah[mt][1], ah[mt][2], ah[mt][3], aoff[mt] + koff);
        #pragma unroll
        for (int g = 0; g < 2; g++) {
            uint32_t r0, r1, r2, r3;
            LDSM4(r0, r1, r2, r3, boff[g] + koff);
            bhf[2*g][0] = r0; bhf[2*g+1][0] = r1; bhf[2*g][1] = r2; bhf[2*g+1][1] = r3;
        }
        #pragma unroll
        for (int mt = 0; mt < 2; mt++)
            #pragma unroll
            for (int nt = 0; nt < 4; nt++) {
                float* d = acc[mt][nt];
                mma16(d[0], d[1], d[2], d[3],
                      ah[mt][0], ah[mt][1], ah[mt][2], ah[mt][3], bhf[nt][0], bhf[nt][1]);
            }
    }
    const size_t sbase = ((size_t)bh * NC + c) * (HD * DS);
    #pragma unroll
    for (int mt = 0; mt < 2; mt++) {
        const int p0 = wm*32 + mt*16 + r;
        #pragma unroll
        for (int nt = 0; nt < 4; nt++) {
            const int n0 = wn*32 + nt*8 + 2*cc;
            *(float2*)&g_Sfinal[sbase + (size_t)p0 * DS + n0] =
                make_float2(acc[mt][nt][0], acc[mt][nt][1]);
            *(float2*)&g_Sfinal[sbase + (size_t)(p0+8) * DS + n0] =
                make_float2(acc[mt][nt][2], acc[mt][nt][3]);
        }
    }
}

// ---------------- phase B: sequential chunk-state combine --------------------
__global__ void phaseB_kernel()
{
    const int bh = blockIdx.x;
    const int e0 = blockIdx.y * 1024;
    const int t  = threadIdx.x;
    __shared__ float Ps[NC];
    if (t < NC) Ps[t] = g_cumdec[bh*L_SZ + t*CL + CL - 1];
    __syncthreads();
    for (int e = e0 + t; e < e0 + 1024; e += 256) {
        float hv = 0.f;
        for (int c = 0; c < NC; c++) {
            const size_t o = ((size_t)bh * NC + c) * (HD * DS) + e;
            g_Hinit[o] = hv;
            hv = fmaf(Ps[c], hv, g_Sfinal[o]);
        }
    }
}

// ================ chunk_out: Y = (CB^T o M o dt) @ X + cum*(C@H^T) + D*x =====
#define CO_SC   0
#define CO_SB   (128*HS2*2)                 // 34816
#define CO_SXT  (2*128*HS2*2)               // 69632
#define CO_SH   (CO_SXT + 64*HS2*2)         // 87040
#define CO_LC   (CO_SH + 64*HS2*2)          // 104448
#define CO_DT   (CO_LC + 512)
#define CO_SMEM (CO_DT + 512)               // 105472
__global__ void __launch_bounds__(256, 2) chunk_out_kernel(const float* __restrict__ Dvec)
{
    extern __shared__ __align__(16) char sm[];
    __half* sC  = (__half*)(sm + CO_SC);
    __half* sB  = (__half*)(sm + CO_SB);    // becomes sW after G
    __half* sXT = (__half*)(sm + CO_SXT);
    __half* sH  = (__half*)(sm + CO_SH);
    float*  lc  = (float*)(sm + CO_LC);
    float*  dtw = (float*)(sm + CO_DT);
    const uint32_t sb = (uint32_t)__cvta_generic_to_shared(sm);

    const int c = blockIdx.x, h = blockIdx.y, b = blockIdx.z;
    const int t = threadIdx.x;
    const int l0 = c * CL;
    const int bh = b * NH + h;
    const bool do_corr = (c != 0);

    // stage C and B rows with 16B vector copies (fp16 source)
    for (int idx = t; idx < CL * 16; idx += 256) {
        int l = idx >> 4, q = idx & 15;
        const __half* base = g_xBCh + (size_t)(b*L_SZ + l0 + l) * CD;
        *(uint4*)&sC[l * HS2 + q * 8] = *(const uint4*)&base[DI + DS + q * 8];
        *(uint4*)&sB[l * HS2 + q * 8] = *(const uint4*)&base[DI + q * 8];
    }
    for (int idx = t; idx < CL * HD; idx += 256) {
        int l = idx >> 6, p = idx & 63;
        sXT[p * HS2 + l] = g_xBCh[(size_t)(b*L_SZ + l0 + l) * CD + h*HD + p];
    }
    const size_t hbase = ((size_t)bh * NC + c) * (HD * DS);
    for (int idx = t; idx < HD * DS; idx += 256) {
        int p = idx >> 7, n = idx & 127;
        float v = do_corr ? g_Hinit[hbase + (size_t)p * DS + n] : 0.f;
        sH[p * HS2 + n] = __float2half_rn(v);
    }
    if (t < CL) {
        lc[t]  = g_logcum[bh*L_SZ + l0 + t];
        dtw[t] = g_dt[(b*L_SZ + l0 + t) * NH + h];
    }
    __syncthreads();

    const int wid = t >> 5, lane = t & 31;
    const int wm = wid & 3;
    const int wn = wid >> 2;
    const int r = lane >> 2, cc = lane & 3;
    const int lrow = lane & 15, lk16 = (lane >> 4) << 4;

    uint32_t aoffC[2], aoffW[2], boffB[4], boffX[2], boffH[2];
    #pragma unroll
    for (int mt = 0; mt < 2; mt++) {
        uint32_t ro = (uint32_t)((wm*32 + mt*16 + lrow) * (HS2*2)) + (uint32_t)lk16;
        aoffC[mt] = sb + CO_SC + ro;
        aoffW[mt] = sb + CO_SB + ro;
    }
    #pragma unroll
    for (int g = 0; g < 4; g++)
        boffB[g] = sb + CO_SB + (uint32_t)((wn*64 + g*16 + lrow) * (HS2*2)) + (uint32_t)lk16;
    #pragma unroll
    for (int g = 0; g < 2; g++) {
        uint32_t ro = (uint32_t)((wn*32 + g*16 + lrow) * (HS2*2)) + (uint32_t)lk16;
        boffX[g] = sb + CO_SXT + ro;
        boffH[g] = sb + CO_SH + ro;
    }

    // ---- G = C @ B^T
    float G[2][8][4];
    #pragma unroll
    for (int i = 0; i < 2; i++)
        #pragma unroll
        for (int j = 0; j < 8; j++)
            #pragma unroll
            for (int q = 0; q < 4; q++) G[i][j][q] = 0.f;
    #pragma unroll
    for (int kb = 0; kb < 8; kb++) {
        const uint32_t koff = (uint32_t)(kb << 5);
        uint32_t ah[2][4], bhf[8][2];
        #pragma unroll
        for (int mt = 0; mt < 2; mt++)
            LDSM4(ah[mt][0], ah[mt][1], ah[mt][2], ah[mt][3], aoffC[mt] + koff);
        #pragma unroll
        for (int g = 0; g < 4; g++) {
            uint32_t r0, r1, r2, r3;
            LDSM4(r0, r1, r2, r3, boffB[g] + koff);
            bhf[2*g][0] = r0; bhf[2*g+1][0] = r1; bhf[2*g][1] = r2; bhf[2*g+1][1] = r3;
        }
        #pragma unroll
        for (int mt = 0; mt < 2; mt++)
            #pragma unroll
            for (int nt = 0; nt < 8; nt++) {
                float* d = G[mt][nt];
                mma16(d[0], d[1], d[2], d[3],
                      ah[mt][0], ah[mt][1], ah[mt][2], ah[mt][3], bhf[nt][0], bhf[nt][1]);
            }
    }
    __syncthreads();

    // ---- W[l][j] = G * dt_j * exp(lc_l - lc_j), causal
    __half* sW = sB;
    #pragma unroll
    for (int mt = 0; mt < 2; mt++) {
        const int lr0 = wm*32 + mt*16 + r;
        const int lr1 = lr0 + 8;
        const float lc0 = lc[lr0], lc1 = lc[lr1];
        #pragma unroll
        for (int nt = 0; nt < 8; nt++) {
            const int j0 = wn*64 + nt*8 + 2*cc;
            const int j1 = j0 + 1;
            const float dj0 = dtw[j0], dj1 = dtw[j1];
            const float lj0 = lc[j0], lj1 = lc[j1];
            float w00 = (j0 <= lr0) ? G[mt][nt][0] * dj0 * __expf(lc0 - lj0) : 0.f;
            float w01 = (j1 <= lr0) ? G[mt][nt][1] * dj1 * __expf(lc0 - lj1) : 0.f;
            float w10 = (j0 <= lr1) ? G[mt][nt][2] * dj0 * __expf(lc1 - lj0) : 0.f;
            float w11 = (j1 <= lr1) ? G[mt][nt][3] * dj1 * __expf(lc1 - lj1) : 0.f;
            *(half2*)&sW[lr0 * HS2 + j0] = __halves2half2(__float2half_rn(w00), __float2half_rn(w01));
            *(half2*)&sW[lr1 * HS2 + j0] = __halves2half2(__float2half_rn(w10), __float2half_rn(w11));
        }
    }
    __syncthreads();

    // ---- Y = W @ X^T ; R = C @ H^T
    float Y[2][4][4], R[2][4][4];
    #pragma unroll
    for (int i = 0; i < 2; i++)
        #pragma unroll
        for (int j = 0; j < 4; j++)
            #pragma unroll
            for (int q = 0; q < 4; q++) { Y[i][j][q] = 0.f; R[i][j][q] = 0.f; }
    #pragma unroll
    for (int kb = 0; kb < 8; kb++) {
        const uint32_t koff = (uint32_t)(kb << 5);
        uint32_t ah[2][4], bhf[4][2];
        #pragma unroll
        for (int mt = 0; mt < 2; mt++)
            LDSM4(ah[mt][0], ah[mt][1], ah[mt][2], ah[mt][3], aoffW[mt] + koff);
        #pragma unroll
        for (int g = 0; g < 2; g++) {
            uint32_t r0, r1, r2, r3;
            LDSM4(r0, r1, r2, r3, boffX[g] + koff);
            bhf[2*g][0] = r0; bhf[2*g+1][0] = r1; bhf[2*g][1] = r2; bhf[2*g+1][1] = r3;
        }
        #pragma unroll
        for (int mt = 0; mt < 2; mt++)
            #pragma unroll
            for (int nt = 0; nt < 4; nt++) {
                float* d = Y[mt][nt];
                mma16(d[0], d[1], d[2], d[3],
                      ah[mt][0], ah[mt][1], ah[mt][2], ah[mt][3], bhf[nt][0], bhf[nt][1]);
            }
    }
    if (do_corr) {
        #pragma unroll
        for (int kb = 0; kb < 8; kb++) {
            const uint32_t koff = (uint32_t)(kb << 5);
            uint32_t ah[2][4], bhf[4][2];
            #pragma unroll
            for (int mt = 0; mt < 2; mt++)
                LDSM4(ah[mt][0], ah[mt][1], ah[mt][2], ah[mt][3], aoffC[mt] + koff);
            #pragma unroll
            for (int g = 0; g < 2; g++) {
                uint32_t r0, r1, r2, r3;
                LDSM4(r0, r1, r2, r3, boffH[g] + koff);
                bhf[2*g][0] = r0; bhf[2*g+1][0] = r1; bhf[2*g][1] = r2; bhf[2*g+1][1] = r3;
            }
            #pragma unroll
            for (int mt = 0; mt < 2; mt++)
                #pragma unroll
                for (int nt = 0; nt < 4; nt++) {
                    float* d = R[mt][nt];
                    mma16(d[0], d[1], d[2], d[3],
                          ah[mt][0], ah[mt][1], ah[mt][2], ah[mt][3], bhf[nt][0], bhf[nt][1]);
                }
        }
    }

    // ---- epilogue: y = Y + exp(lc_l)*R + D*x
    const float Dh = Dvec[h];
    #pragma unroll
    for (int mt = 0; mt < 2; mt++) {
        #pragma unroll
        for (int half = 0; half < 2; half++) {
            const int lrw = wm*32 + mt*16 + r + half*8;
            const float cum = __expf(lc[lrw]);
            const size_t grow = (size_t)(b*L_SZ + l0 + lrw);
            #pragma unroll
            for (int nt = 0; nt < 4; nt++) {
                const int p0 = wn*32 + nt*8 + 2*cc;
                half2 xh = *(const half2*)&g_xBCh[grow * CD + h*HD + p0];
                float2 xv = __half22float2(xh);
                float y0 = Y[mt][nt][2*half+0] + cum * R[mt][nt][2*half+0] + Dh * xv.x;
                float y1 = Y[mt][nt][2*half+1] + cum * R[mt][nt][2*half+1] + Dh * xv.y;
                *(float2*)&g_y[grow * DI + h*HD + p0] = make_float2(y0, y1);
            }
        }
    }
}

// ---------------- gating (silu(z)) + RMS norm -> fp16 hi ---------------------
__global__ void __launch_bounds__(256) epilogue_kernel(const float* __restrict__ norm_w)
{
    const int row = blockIdx.x;
    const int t   = threadIdx.x;
    float gv[8];
    float ss = 0.f;
    #pragma unroll
    for (int i = 0; i < 8; i++) {
        int cidx = t + i * 256;
        float yv = g_y[(size_t)row * DI + cidx];
        float zv = __half2float(g_zxh[(size_t)row * NGEMM2 + cidx]);
        float sil = zv / (1.f + expf(-zv));
        float v = yv * sil;
        gv[i] = v;
        ss += v * v;
    }
    __shared__ float rs[32];
    #pragma unroll
    for (int o = 16; o; o >>= 1) ss += __shfl_xor_sync(~0u, ss, o);
    if ((t & 31) == 0) rs[t >> 5] = ss;
    __syncthreads();
    if (t < 32) {
        float v = (t < 8) ? rs[t] : 0.f;
        #pragma unroll
        for (int o = 4; o; o >>= 1) v += __shfl_xor_sync(~0u, v, o);
        if (t == 0) rs[0] = v;
    }
    __syncthreads();
    float scale = rsqrtf(rs[0] / (float)DI + EPSV);
    #pragma unroll
    for (int i = 0; i < 8; i++) {
        int cidx = t + i * 256;
        float v = gv[i] * scale * norm_w[cidx];
        g_yhi[(size_t)row * DI + cidx] = __float2half_rn(v);
    }
}

// ---------------- launch ----------------
extern "C" void kernel_launch(void* const* d_in, const int* in_sizes, int n_in,
                              void* d_out, int out_size)
{
    const float* hidden  = (const float*)d_in[0];
    const float* dte     = (const float*)d_in[1];
    const float* W_proj  = (const float*)d_in[2];
    const float* b_proj  = (const float*)d_in[3];
    const float* W_dtmod = (const float*)d_in[4];
    const float* b_dtmod = (const float*)d_in[5];
    const float* W_in    = (const float*)d_in[6];
    const float* conv_w  = (const float*)d_in[7];
    const float* conv_b  = (const float*)d_in[8];
    const float* dt_bias = (const float*)d_in[9];
    const float* A_log   = (const float*)d_in[10];
    const float* Dvec    = (const float*)d_in[11];
    const float* norm_w  = (const float*)d_in[12];
    const float* W_out   = (const float*)d_in[13];
    float* out = (float*)d_out;

    __half *p_uhi, *p_ulo, *p_yhi, *p_hhi, *p_hlo, *p_zxh;
    __half *p_wpt_hi, *p_wpt_lo, *p_wit_hi, *p_wot_hi;
    cudaGetSymbolAddress((void**)&p_uhi, g_uhi);
    cudaGetSymbolAddress((void**)&p_ulo, g_ulo);
    cudaGetSymbolAddress((void**)&p_zxh, g_zxh);
    cudaGetSymbolAddress((void**)&p_yhi, g_yhi);
    cudaGetSymbolAddress((void**)&p_hhi, g_hhi);
    cudaGetSymbolAddress((void**)&p_hlo, g_hlo);
    cudaGetSymbolAddress((void**)&p_wpt_hi, g_wpt_hi);
    cudaGetSymbolAddress((void**)&p_wpt_lo, g_wpt_lo);
    cudaGetSymbolAddress((void**)&p_wit_hi, g_wit_hi);
    cudaGetSymbolAddress((void**)&p_wot_hi, g_wot_hi);

    cudaFuncSetAttribute(gemm_h3, cudaFuncAttributeMaxDynamicSharedMemorySize, SMEM3P);
    cudaFuncSetAttribute(gemm_h1<true >, cudaFuncAttributeMaxDynamicSharedMemorySize, SMEM1P);
    cudaFuncSetAttribute(gemm_h1<false>, cudaFuncAttributeMaxDynamicSharedMemorySize, SMEM1P);
    cudaFuncSetAttribute(chunk_state_kernel, cudaFuncAttributeMaxDynamicSharedMemorySize, CS_SMEM);
    cudaFuncSetAttribute(chunk_out_kernel,   cudaFuncAttributeMaxDynamicSharedMemorySize, CO_SMEM);

    // 0) operand prep
    split4h_kernel<<<(ROWS*DM/4 + 255)/256, 256>>>(hidden, p_hhi, p_hlo, ROWS*DM/4);
    tsplit_kernel<true ><<<dim3(DM/32,  DM/32), dim3(32,8)>>>(W_proj, p_wpt_hi, p_wpt_lo, DM, DM);
    tsplit_kernel<false><<<dim3(DIPPAD/32, DM/32), dim3(32,8)>>>(W_in,  p_wit_hi, nullptr, DM, DIP);
    tsplit_kernel<false><<<dim3(DM/32,  DI/32), dim3(32,8)>>>(W_out, p_wot_hi, nullptr, DI, DM);

    // 1) u = hidden @ W_proj + b_proj   (3-pass; split fp16 output)
    gemm_h3<<<dim3(DM/128, ROWS/128), 512, SMEM3P>>>(
        p_hhi, p_hlo, p_wpt_hi, p_wpt_lo, b_proj, p_uhi, p_ulo, ROWS, DM, DM);

    // 2) zxbcdt[:, :4352] = u @ W_in   (1-pass, fp16 output)
    gemm_h1<true><<<dim3(NGEMM2/128, ROWS/128), 256, SMEM1P>>>(
        p_uhi, p_wit_hi, nullptr, p_zxh, ROWS, NGEMM2, DM);

    // 3) dt exact (stores dt and dt*A)
    dt_kernel<<<ROWS/8, 256>>>(dte, W_dtmod, b_dtmod, W_in, dt_bias, A_log);

    // 4) conv + silu (fp16 in/out)
    conv_kernel<<<(ROWS*CD + 255)/256, 256>>>(conv_w, conv_b);

    // 5) chunked scan in matmul form (tensor-core)
    chunk_state_kernel<<<dim3(NC, NH, B_SZ), 256, CS_SMEM>>>();
    phaseB_kernel<<<dim3(B_SZ*NH, 8), 256>>>();
    chunk_out_kernel<<<dim3(NC, NH, B_SZ), 256, CO_SMEM>>>(Dvec);

    // 6) gating + RMS norm
    epilogue_kernel<<<ROWS, 256>>>(norm_w);

    // 7) out = yn @ W_out   (1-pass, fp32 output)
    gemm_h1<false><<<dim3(DM/128, ROWS/128), 256, SMEM1P>>>(
        p_yhi, p_wot_hi, out, nullptr, ROWS, DM, DI);
}